// round 2
// baseline (speedup 1.0000x reference)
#include <cuda_runtime.h>

#define NB 2
#define NS 1024
#define FIN 768
#define NE 768
#define NH 12
#define NBH (NB * NH)
#define NDH 64
#define NFH 64
#define NSPLIT 8
#define OSPL (NS / NSPLIT)   // 128 tokens per split
#define MIN_POS 1e-6f
#define EPSV 1e-20f

// ---------------- scratch (device globals; no allocation) ----------------
__device__ __align__(16) float g_Wn[NFH * NDH];                 // normalized W [f][d]
__device__ __align__(16) float g_xe[NB * NS * NE];              // clipped embed output
__device__ __align__(16) float g_h[NBH * NS * NFH];             // h   [bh][s][f]
__device__ __align__(16) float g_hri[NBH * NS * NDH];           // rec*inp [bh][s][d]
__device__ __align__(16) float g_G1p[NBH * NSPLIT * 64 * 64];   // partial h^T*hri
__device__ __align__(16) float g_csp[NBH * NSPLIT * 64];        // partial colsum(h)
__device__ __align__(16) float g_c2p[NBH * NSPLIT * 64];        // partial c2
__device__ __align__(16) float g_cfp[NBH * NSPLIT * 64];        // partial cfin
__device__ __align__(16) float g_aiA[NBH * 64];                 // arec_inv iter0
__device__ __align__(16) float g_aiB[NBH * 64];                 // arec_inv iter1
__device__ __align__(16) float g_aiC[NBH * 64];                 // arec_inv iter2
__device__ __align__(16) float g_w01[NBH * NS];                 // u0*u1 per token
__device__ __align__(16) float g_cfin[NB * NE];                 // final mixed row per batch
__device__ __align__(16) float g_yrow[NB * FIN];                // final projected row per batch

// ---------------- helpers ----------------
__device__ __forceinline__ float red16(float v) {
    v += __shfl_xor_sync(0xffffffffu, v, 8);
    v += __shfl_xor_sync(0xffffffffu, v, 4);
    v += __shfl_xor_sync(0xffffffffu, v, 2);
    v += __shfl_xor_sync(0xffffffffu, v, 1);
    return v;
}
__device__ __forceinline__ float red32(float v) {
    v += __shfl_xor_sync(0xffffffffu, v, 16);
    return red16(v);
}

// ---------------- K1: normalize nnmf_w rows ----------------
__global__ void wnorm_kernel(const float* __restrict__ nnmf_w) {
    int f = threadIdx.x;  // 0..63
    float s = 0.f;
#pragma unroll
    for (int d = 0; d < NDH; ++d) s += nnmf_w[f * NDH + d];
    s = fmaxf(s, EPSV);
    float inv = 1.f / s;
#pragma unroll
    for (int d = 0; d < NDH; ++d) g_Wn[f * NDH + d] = nnmf_w[f * NDH + d] * inv;
}

// ---------------- K2: embed GEMM + clip ----------------
// 64x64 tile, BK=16, 64 threads, 8x8 microtile. grid (12, 32) = 384 blocks.
__global__ void __launch_bounds__(64) embed_gemm_kernel(const float* __restrict__ X,
                                                        const float* __restrict__ Wm,
                                                        const float* __restrict__ bias) {
    __shared__ __align__(16) float As[16][68];
    __shared__ __align__(16) float Bs[16][68];
    int tid = threadIdx.x;
    int bm = blockIdx.y * 64, bn = blockIdx.x * 64;
    int tx = tid & 7, ty = tid >> 3;
    float acc[8][8] = {};

    const float* xr = X + (size_t)(bm + tid) * FIN;
    const float* wr = Wm + (size_t)(bn + tid) * FIN;

    for (int k0 = 0; k0 < FIN; k0 += 16) {
        float4 a0 = *(const float4*)&xr[k0 + 0];
        float4 a1 = *(const float4*)&xr[k0 + 4];
        float4 a2 = *(const float4*)&xr[k0 + 8];
        float4 a3 = *(const float4*)&xr[k0 + 12];
        float4 b0 = *(const float4*)&wr[k0 + 0];
        float4 b1 = *(const float4*)&wr[k0 + 4];
        float4 b2 = *(const float4*)&wr[k0 + 8];
        float4 b3 = *(const float4*)&wr[k0 + 12];
        As[0][tid] = a0.x; As[1][tid] = a0.y; As[2][tid] = a0.z; As[3][tid] = a0.w;
        As[4][tid] = a1.x; As[5][tid] = a1.y; As[6][tid] = a1.z; As[7][tid] = a1.w;
        As[8][tid] = a2.x; As[9][tid] = a2.y; As[10][tid] = a2.z; As[11][tid] = a2.w;
        As[12][tid] = a3.x; As[13][tid] = a3.y; As[14][tid] = a3.z; As[15][tid] = a3.w;
        Bs[0][tid] = b0.x; Bs[1][tid] = b0.y; Bs[2][tid] = b0.z; Bs[3][tid] = b0.w;
        Bs[4][tid] = b1.x; Bs[5][tid] = b1.y; Bs[6][tid] = b1.z; Bs[7][tid] = b1.w;
        Bs[8][tid] = b2.x; Bs[9][tid] = b2.y; Bs[10][tid] = b2.z; Bs[11][tid] = b2.w;
        Bs[12][tid] = b3.x; Bs[13][tid] = b3.y; Bs[14][tid] = b3.z; Bs[15][tid] = b3.w;
        __syncthreads();
#pragma unroll
        for (int kk = 0; kk < 16; kk++) {
            float4 ra0 = *(const float4*)&As[kk][ty * 8];
            float4 ra1 = *(const float4*)&As[kk][ty * 8 + 4];
            float4 rb0 = *(const float4*)&Bs[kk][tx * 8];
            float4 rb1 = *(const float4*)&Bs[kk][tx * 8 + 4];
            float a[8] = {ra0.x, ra0.y, ra0.z, ra0.w, ra1.x, ra1.y, ra1.z, ra1.w};
            float b_[8] = {rb0.x, rb0.y, rb0.z, rb0.w, rb1.x, rb1.y, rb1.z, rb1.w};
#pragma unroll
            for (int i = 0; i < 8; i++)
#pragma unroll
                for (int j = 0; j < 8; j++) acc[i][j] += a[i] * b_[j];
        }
        __syncthreads();
    }
#pragma unroll
    for (int i = 0; i < 8; i++) {
        int m = bm + ty * 8 + i;
        float* orow = g_xe + (size_t)m * NE + bn + tx * 8;
#pragma unroll
        for (int j = 0; j < 8; j++)
            orow[j] = fmaxf(acc[i][j] + bias[bn + tx * 8 + j], MIN_POS);
    }
}

// ---------------- K3: fused NNMF iterations ----------------
__global__ void __launch_bounds__(256) nnmf_kernel() {
    __shared__ __align__(16) float sW[NFH * NDH];
    __shared__ __align__(16) float s_h[32][64];
    __shared__ __align__(16) float s_ratio[32][64];

    int head = blockIdx.y;
    int tile = blockIdx.x;
    int tid = threadIdx.x;
    int d4 = tid & 15;
    int tg = tid >> 4;
    int t0 = tg * 2, t1 = tg * 2 + 1;
    int tokbase = tile * 32;

    for (int i = tid; i < NFH * NDH; i += 256) sW[i] = g_Wn[i];

    float inp0[4], inp1[4];
    {
        const float4 x0 = *(const float4*)&g_xe[(size_t)(tokbase + t0) * NE + head * 64 + d4 * 4];
        const float4 x1 = *(const float4*)&g_xe[(size_t)(tokbase + t1) * NE + head * 64 + d4 * 4];
        float s0 = red16(x0.x + x0.y + x0.z + x0.w);
        float s1 = red16(x1.x + x1.y + x1.z + x1.w);
        float i0 = 1.f / fmaxf(s0, EPSV), i1 = 1.f / fmaxf(s1, EPSV);
        inp0[0] = x0.x * i0; inp0[1] = x0.y * i0; inp0[2] = x0.z * i0; inp0[3] = x0.w * i0;
        inp1[0] = x1.x * i1; inp1[1] = x1.y * i1; inp1[2] = x1.z * i1; inp1[3] = x1.w * i1;
    }
    float hr0[4], hr1[4];
    const float hinit = 1.f / 64.f;
#pragma unroll
    for (int i = 0; i < 4; i++) { hr0[i] = hinit; hr1[i] = hinit; }
    *(float4*)&s_h[t0][d4 * 4] = make_float4(hinit, hinit, hinit, hinit);
    *(float4*)&s_h[t1][d4 * 4] = make_float4(hinit, hinit, hinit, hinit);
    __syncthreads();

    float rn0[4], rn1[4];

    for (int it = 0; it < 3; ++it) {
        float a0[4] = {}, a1[4] = {};
#pragma unroll 16
        for (int ff = 0; ff < 64; ++ff) {
            float4 w = *(const float4*)&sW[ff * 64 + d4 * 4];
            float h0 = s_h[t0][ff], h1 = s_h[t1][ff];
            a0[0] += h0 * w.x; a0[1] += h0 * w.y; a0[2] += h0 * w.z; a0[3] += h0 * w.w;
            a1[0] += h1 * w.x; a1[1] += h1 * w.y; a1[2] += h1 * w.z; a1[3] += h1 * w.w;
        }
#pragma unroll
        for (int i = 0; i < 4; i++) { a0[i] = fmaxf(a0[i], MIN_POS); a1[i] = fmaxf(a1[i], MIN_POS); }
        float p0 = red16(a0[0] + a0[1] + a0[2] + a0[3]);
        float p1 = red16(a1[0] + a1[1] + a1[2] + a1[3]);
        float iv0 = 1.f / fmaxf(p0, EPSV), iv1 = 1.f / fmaxf(p1, EPSV);
        float q0[4], q1[4];
#pragma unroll
        for (int i = 0; i < 4; i++) {
            rn0[i] = a0[i] * iv0; rn1[i] = a1[i] * iv1;
            q0[i] = inp0[i] / rn0[i]; q1[i] = inp1[i] / rn1[i];
        }
        *(float4*)&s_ratio[t0][d4 * 4] = make_float4(q0[0], q0[1], q0[2], q0[3]);
        *(float4*)&s_ratio[t1][d4 * 4] = make_float4(q1[0], q1[1], q1[2], q1[3]);
        __syncthreads();

        float b0[4] = {}, b1[4] = {};
#pragma unroll
        for (int jj = 0; jj < 16; ++jj) {
            int j = (jj + d4) & 15;
            float4 r0v = *(const float4*)&s_ratio[t0][j * 4];
            float4 r1v = *(const float4*)&s_ratio[t1][j * 4];
#pragma unroll
            for (int i = 0; i < 4; i++) {
                float4 w = *(const float4*)&sW[(d4 * 4 + i) * 64 + j * 4];
                b0[i] += w.x * r0v.x + w.y * r0v.y + w.z * r0v.z + w.w * r0v.w;
                b1[i] += w.x * r1v.x + w.y * r1v.y + w.z * r1v.z + w.w * r1v.w;
            }
        }
        float hn0[4], hn1[4];
#pragma unroll
        for (int i = 0; i < 4; i++) {
            hn0[i] = fmaxf(hr0[i] * b0[i], MIN_POS);
            hn1[i] = fmaxf(hr1[i] * b1[i], MIN_POS);
        }
        float hs0 = red16(hn0[0] + hn0[1] + hn0[2] + hn0[3]);
        float hs1 = red16(hn1[0] + hn1[1] + hn1[2] + hn1[3]);
        float ih0 = 1.f / fmaxf(hs0, EPSV), ih1 = 1.f / fmaxf(hs1, EPSV);
#pragma unroll
        for (int i = 0; i < 4; i++) { hr0[i] = hn0[i] * ih0; hr1[i] = hn1[i] * ih1; }
        *(float4*)&s_h[t0][d4 * 4] = make_float4(hr0[0], hr0[1], hr0[2], hr0[3]);
        *(float4*)&s_h[t1][d4 * 4] = make_float4(hr1[0], hr1[1], hr1[2], hr1[3]);
        __syncthreads();
    }

    float hs0 = red16(hr0[0] + hr0[1] + hr0[2] + hr0[3]);
    float hs1 = red16(hr1[0] + hr1[1] + hr1[2] + hr1[3]);
    float ih0 = 1.f / fmaxf(hs0, EPSV), ih1 = 1.f / fmaxf(hs1, EPSV);

    int token0 = tokbase + t0, token1 = tokbase + t1;
    int b0i = token0 >> 10, s0i = token0 & 1023;
    int b1i = token1 >> 10, s1i = token1 & 1023;
    size_t base0 = ((size_t)((b0i * NH + head) * NS + s0i)) * 64 + d4 * 4;
    size_t base1 = ((size_t)((b1i * NH + head) * NS + s1i)) * 64 + d4 * 4;
    *(float4*)&g_h[base0] = make_float4(hr0[0] * ih0, hr0[1] * ih0, hr0[2] * ih0, hr0[3] * ih0);
    *(float4*)&g_h[base1] = make_float4(hr1[0] * ih1, hr1[1] * ih1, hr1[2] * ih1, hr1[3] * ih1);
    *(float4*)&g_hri[base0] = make_float4(rn0[0] * inp0[0], rn0[1] * inp0[1], rn0[2] * inp0[2], rn0[3] * inp0[3]);
    *(float4*)&g_hri[base1] = make_float4(rn1[0] * inp1[0], rn1[1] * inp1[1], rn1[2] * inp1[2], rn1[3] * inp1[3]);
}

// ---------------- K4a: G1 = h^T * hri partials + colsum(h) partials ----------------
// grid (NSPLIT, NBH), 256 threads.
__global__ void __launch_bounds__(256) g1_kernel() {
    __shared__ __align__(16) float s_h[16][68];
    __shared__ __align__(16) float s_r[16][68];
    int split = blockIdx.x, bh = blockIdx.y;
    int tid = threadIdx.x;
    int f4 = tid & 15, d4 = tid >> 4;
    int lo = tid >> 4, lq = tid & 15;
    const float* hb = g_h + ((size_t)bh * NS + split * OSPL) * 64;
    const float* rb = g_hri + ((size_t)bh * NS + split * OSPL) * 64;

    float acc[4][4] = {};
    float cs[4] = {};
    for (int c = 0; c < OSPL / 16; ++c) {
        *(float4*)&s_h[lo][lq * 4] = *(const float4*)&hb[(c * 16 + lo) * 64 + lq * 4];
        *(float4*)&s_r[lo][lq * 4] = *(const float4*)&rb[(c * 16 + lo) * 64 + lq * 4];
        __syncthreads();
#pragma unroll
        for (int o = 0; o < 16; ++o) {
            float4 hv = *(const float4*)&s_h[o][f4 * 4];
            float4 rv = *(const float4*)&s_r[o][d4 * 4];
            float hvv[4] = {hv.x, hv.y, hv.z, hv.w};
            float rvv[4] = {rv.x, rv.y, rv.z, rv.w};
#pragma unroll
            for (int i = 0; i < 4; i++)
#pragma unroll
                for (int j = 0; j < 4; j++) acc[i][j] += hvv[i] * rvv[j];
            if (d4 == 0) {
#pragma unroll
                for (int i = 0; i < 4; i++) cs[i] += hvv[i];
            }
        }
        __syncthreads();
    }
    float* gp = g_G1p + ((size_t)(bh * NSPLIT + split)) * 4096;
#pragma unroll
    for (int i = 0; i < 4; i++)
#pragma unroll
        for (int j = 0; j < 4; j++) gp[(f4 * 4 + i) * 64 + d4 * 4 + j] = acc[i][j];
    if (d4 == 0) {
#pragma unroll
        for (int i = 0; i < 4; i++) g_csp[(bh * NSPLIT + split) * 64 + f4 * 4 + i] = cs[i];
    }
}

// ---------------- K4b: iterations 0+1 in closed form ----------------
// grid NBH, 256 threads.
__global__ void __launch_bounds__(256) alpha01_kernel() {
    __shared__ float sW[4096];
    __shared__ float sG[4096];
    __shared__ float s_c0[64], s_ai0[64], s_c1[64];
    int bh = blockIdx.x, tid = threadIdx.x;

    for (int i = tid; i < 4096; i += 256) sW[i] = g_Wn[i];
    const float* gp = g_G1p + (size_t)bh * NSPLIT * 4096;
    for (int i = tid; i < 4096; i += 256) {
        float s = 0.f;
#pragma unroll
        for (int p = 0; p < NSPLIT; ++p) s += gp[p * 4096 + i];
        sG[i] = s;
    }
    if (tid < 64) {
        float s = 0.f;
#pragma unroll
        for (int p = 0; p < NSPLIT; ++p) s += g_csp[(bh * NSPLIT + p) * 64 + tid];
        s_c0[tid] = s;
    }
    __syncthreads();
    if (tid < 64) {
        int d = tid;
        float r = 0.f;
#pragma unroll 8
        for (int f = 0; f < 64; ++f) r += s_c0[f] * sW[f * 64 + d];
        float ai = 1.f / (r + EPSV);
        s_ai0[d] = ai;
        g_aiA[bh * 64 + d] = ai;
    }
    __syncthreads();
    if (tid < 64) {
        int f = tid;
        float c1 = 0.f;
#pragma unroll 8
        for (int dd = 0; dd < 64; ++dd) {
            int d = (dd + f) & 63;
            c1 += sG[f * 64 + d] * s_ai0[d];
        }
        s_c1[f] = c1;
    }
    __syncthreads();
    if (tid < 64) {
        int d = tid;
        float r = 0.f;
#pragma unroll 8
        for (int f = 0; f < 64; ++f) r += s_c1[f] * sW[f * 64 + d];
        g_aiB[bh * 64 + d] = 1.f / (r + EPSV);
    }
}

// ---------------- K4c: pass2 — w = u0*u1, partial c2 ----------------
// grid (NSPLIT, NBH), 256 threads.
__global__ void __launch_bounds__(256) pass2_kernel() {
    __shared__ float s_ai0[64], s_ai1[64];
    __shared__ float s_w[OSPL];
    __shared__ float s_p[4][64];
    int split = blockIdx.x, bh = blockIdx.y;
    int tid = threadIdx.x;
    if (tid < 64) s_ai0[tid] = g_aiA[bh * 64 + tid];
    else if (tid < 128) s_ai1[tid - 64] = g_aiB[bh * 64 + tid - 64];
    __syncthreads();

    const float* rb = g_hri + ((size_t)bh * NS + split * OSPL) * 64;
    const float* hb = g_h + ((size_t)bh * NS + split * OSPL) * 64;

    // u0,u1 per token: 2 threads per token, each half of the dot
    {
        int o = tid >> 1, half = tid & 1;
        const float4* r4 = (const float4*)(rb + (size_t)o * 64 + half * 32);
        float u0 = 0.f, u1 = 0.f;
#pragma unroll
        for (int q = 0; q < 8; ++q) {
            float4 v = r4[q];
            int base = half * 32 + q * 4;
            u0 += v.x * s_ai0[base] + v.y * s_ai0[base + 1] + v.z * s_ai0[base + 2] + v.w * s_ai0[base + 3];
            u1 += v.x * s_ai1[base] + v.y * s_ai1[base + 1] + v.z * s_ai1[base + 2] + v.w * s_ai1[base + 3];
        }
        u0 += __shfl_xor_sync(0xffffffffu, u0, 1);
        u1 += __shfl_xor_sync(0xffffffffu, u1, 1);
        if (half == 0) {
            float w = u0 * u1;
            s_w[o] = w;
            g_w01[bh * NS + split * OSPL + o] = w;
        }
    }
    __syncthreads();
    // partial c2[f] = sum_o h[o,f] * w[o]
    {
        int f = tid & 63, g = tid >> 6;
        float p = 0.f;
#pragma unroll 8
        for (int oo = 0; oo < 32; ++oo) {
            int o = g * 32 + oo;
            p += hb[(size_t)o * 64 + f] * s_w[o];
        }
        s_p[g][f] = p;
    }
    __syncthreads();
    if (tid < 64)
        g_c2p[(bh * NSPLIT + split) * 64 + tid] =
            s_p[0][tid] + s_p[1][tid] + s_p[2][tid] + s_p[3][tid];
}

// ---------------- K4d: ai2 ----------------
__global__ void __launch_bounds__(256) alpha2_kernel() {
    __shared__ float sW[4096];
    __shared__ float s_c2[64];
    int bh = blockIdx.x, tid = threadIdx.x;
    for (int i = tid; i < 4096; i += 256) sW[i] = g_Wn[i];
    if (tid < 64) {
        float s = 0.f;
#pragma unroll
        for (int p = 0; p < NSPLIT; ++p) s += g_c2p[(bh * NSPLIT + p) * 64 + tid];
        s_c2[tid] = s;
    }
    __syncthreads();
    if (tid < 64) {
        int d = tid;
        float r = 0.f;
#pragma unroll 8
        for (int f = 0; f < 64; ++f) r += s_c2[f] * sW[f * 64 + d];
        g_aiC[bh * 64 + d] = 1.f / (r + EPSV);
    }
}

// ---------------- K4e: pass3 — a_final = w*u2, partial cfin ----------------
__global__ void __launch_bounds__(256) pass3_kernel() {
    __shared__ float s_ai2[64];
    __shared__ float s_a[OSPL];
    __shared__ float s_p[4][64];
    int split = blockIdx.x, bh = blockIdx.y;
    int tid = threadIdx.x;
    if (tid < 64) s_ai2[tid] = g_aiC[bh * 64 + tid];
    __syncthreads();

    const float* rb = g_hri + ((size_t)bh * NS + split * OSPL) * 64;
    const float* hb = g_h + ((size_t)bh * NS + split * OSPL) * 64;

    {
        int o = tid >> 1, half = tid & 1;
        const float4* r4 = (const float4*)(rb + (size_t)o * 64 + half * 32);
        float u2 = 0.f;
#pragma unroll
        for (int q = 0; q < 8; ++q) {
            float4 v = r4[q];
            int base = half * 32 + q * 4;
            u2 += v.x * s_ai2[base] + v.y * s_ai2[base + 1] + v.z * s_ai2[base + 2] + v.w * s_ai2[base + 3];
        }
        u2 += __shfl_xor_sync(0xffffffffu, u2, 1);
        if (half == 0) s_a[o] = g_w01[bh * NS + split * OSPL + o] * u2;
    }
    __syncthreads();
    {
        int f = tid & 63, g = tid >> 6;
        float p = 0.f;
#pragma unroll 8
        for (int oo = 0; oo < 32; ++oo) {
            int o = g * 32 + oo;
            p += hb[(size_t)o * 64 + f] * s_a[o];
        }
        s_p[g][f] = p;
    }
    __syncthreads();
    if (tid < 64)
        g_cfp[(bh * NSPLIT + split) * 64 + tid] =
            s_p[0][tid] + s_p[1][tid] + s_p[2][tid] + s_p[3][tid];
}

// ---------------- K4f: reduce cfin partials ----------------
__global__ void __launch_bounds__(64) cfin_kernel() {
    int bh = blockIdx.x, f = threadIdx.x;
    float s = 0.f;
#pragma unroll
    for (int p = 0; p < NSPLIT; ++p) s += g_cfp[(bh * NSPLIT + p) * 64 + f];
    int b = bh / NH, head = bh % NH;
    g_cfin[b * NE + head * 64 + f] = s;
}

// ---------------- K5: out projection of the 2 unique rows ----------------
__global__ void __launch_bounds__(256) outrow_kernel(const float* __restrict__ out_w,
                                                     const float* __restrict__ out_b) {
    int b = blockIdx.y;
    int warp = threadIdx.x >> 5, lane = threadIdx.x & 31;
    int j = blockIdx.x * 8 + warp;
    const float* c = g_cfin + b * NE;
    const float* wrow = out_w + (size_t)j * NE;
    float acc = 0.f;
    for (int e = lane; e < NE; e += 32) acc += c[e] * wrow[e];
    acc = red32(acc);
    if (lane == 0) g_yrow[b * FIN + j] = acc + out_b[j];
}

// ---------------- K6: broadcast rows to all positions ----------------
__global__ void __launch_bounds__(256) bcast_kernel(float* __restrict__ out) {
    int idx = blockIdx.x * 256 + threadIdx.x;
    const int per_row = FIN / 4;
    int j4 = idx % per_row;
    int bs = idx / per_row;
    int b = bs >> 10;
    float4 v = ((const float4*)(g_yrow + b * FIN))[j4];
    ((float4*)out)[idx] = v;
}

// ---------------- launch ----------------
extern "C" void kernel_launch(void* const* d_in, const int* in_sizes, int n_in,
                              void* d_out, int out_size) {
    const float* x       = (const float*)d_in[0];
    const float* embed_w = (const float*)d_in[1];
    const float* embed_b = (const float*)d_in[2];
    const float* nnmf_w  = (const float*)d_in[3];
    const float* out_w   = (const float*)d_in[4];
    const float* out_b   = (const float*)d_in[5];
    float* out = (float*)d_out;

    wnorm_kernel<<<1, 64>>>(nnmf_w);
    embed_gemm_kernel<<<dim3(NE / 64, (NB * NS) / 64), 64>>>(x, embed_w, embed_b);
    nnmf_kernel<<<dim3((NB * NS) / 32, NH), 256>>>();
    g1_kernel<<<dim3(NSPLIT, NBH), 256>>>();
    alpha01_kernel<<<NBH, 256>>>();
    pass2_kernel<<<dim3(NSPLIT, NBH), 256>>>();
    alpha2_kernel<<<NBH, 256>>>();
    pass3_kernel<<<dim3(NSPLIT, NBH), 256>>>();
    cfin_kernel<<<NBH, 64>>>();
    outrow_kernel<<<dim3(NE / 8, NB), 256>>>(out_w, out_b);
    bcast_kernel<<<(NB * NS * (FIN / 4)) / 256, 256>>>(out);
}

// round 3
// speedup vs baseline: 1.1035x; 1.1035x over previous
#include <cuda_runtime.h>

#define NB 2
#define NS 1024
#define FIN 768
#define NE 768
#define NH 12
#define NBH (NB * NH)
#define NDH 64
#define NFH 64
#define NSPLIT 16
#define OSPL (NS / NSPLIT)   // 64 tokens per split
#define MIN_POS 1e-6f
#define EPSV 1e-20f

// ---------------- scratch (device globals; no allocation) ----------------
__device__ __align__(16) float g_Wn[NFH * NDH];                 // normalized W [f][d]
__device__ __align__(16) float g_xe[NB * NS * NE];              // clipped embed output
__device__ __align__(16) float g_h[NBH * NS * NFH];             // h   [bh][s][f]
__device__ __align__(16) float g_hri[NBH * NS * NDH];           // rec*inp [bh][s][d]
__device__ __align__(16) float g_G1p[NBH * NSPLIT * 64 * 64];   // partial h^T*hri
__device__ __align__(16) float g_Mp[NBH * NSPLIT * 64 * 64];    // partial h^T*(w01*hri)
__device__ __align__(16) float g_csp[NBH * NSPLIT * 64];        // partial colsum(h)
__device__ __align__(16) float g_c2p[NBH * NSPLIT * 64];        // partial c2
__device__ __align__(16) float g_aiA[NBH * 64];                 // arec_inv iter0
__device__ __align__(16) float g_aiB[NBH * 64];                 // arec_inv iter1
__device__ __align__(16) float g_cfin[NB * NE];                 // final mixed row per batch
__device__ __align__(16) float g_yrow[NB * FIN];                // final projected row per batch

// ---------------- helpers ----------------
__device__ __forceinline__ float red16(float v) {
    v += __shfl_xor_sync(0xffffffffu, v, 8);
    v += __shfl_xor_sync(0xffffffffu, v, 4);
    v += __shfl_xor_sync(0xffffffffu, v, 2);
    v += __shfl_xor_sync(0xffffffffu, v, 1);
    return v;
}
__device__ __forceinline__ float red32(float v) {
    v += __shfl_xor_sync(0xffffffffu, v, 16);
    return red16(v);
}

// ---------------- K1: normalize nnmf_w rows ----------------
__global__ void wnorm_kernel(const float* __restrict__ nnmf_w) {
    int f = threadIdx.x;  // 0..63
    float s = 0.f;
#pragma unroll
    for (int d = 0; d < NDH; ++d) s += nnmf_w[f * NDH + d];
    s = fmaxf(s, EPSV);
    float inv = 1.f / s;
#pragma unroll
    for (int d = 0; d < NDH; ++d) g_Wn[f * NDH + d] = nnmf_w[f * NDH + d] * inv;
}

// ---------------- K2: embed GEMM + clip ----------------
// BM=128, BN=64, BK=16, 256 threads, 8x4 microtile. grid (12, 16) = 192 blocks.
__global__ void __launch_bounds__(256) embed_gemm_kernel(const float* __restrict__ X,
                                                         const float* __restrict__ Wm,
                                                         const float* __restrict__ bias) {
    __shared__ __align__(16) float As[16][132];
    __shared__ __align__(16) float Bs[16][68];
    int tid = threadIdx.x;
    int bm = blockIdx.y * 128, bn = blockIdx.x * 64;
    int tx = tid & 15, ty = tid >> 4;   // compute coords: rows ty*8.., cols tx*4..
    float acc[8][4] = {};

    for (int k0 = 0; k0 < FIN; k0 += 16) {
        // load A tile: 128 rows x 16 k = 512 float4; 2 per thread
#pragma unroll
        for (int r = 0; r < 2; ++r) {
            int p = tid + r * 256;
            int m = p >> 2, q = p & 3;
            float4 v = *(const float4*)&X[(size_t)(bm + m) * FIN + k0 + q * 4];
            As[q * 4 + 0][m] = v.x; As[q * 4 + 1][m] = v.y;
            As[q * 4 + 2][m] = v.z; As[q * 4 + 3][m] = v.w;
        }
        // load B tile: 64 rows x 16 k = 256 float4; 1 per thread
        {
            int m = tid >> 2, q = tid & 3;
            float4 v = *(const float4*)&Wm[(size_t)(bn + m) * FIN + k0 + q * 4];
            Bs[q * 4 + 0][m] = v.x; Bs[q * 4 + 1][m] = v.y;
            Bs[q * 4 + 2][m] = v.z; Bs[q * 4 + 3][m] = v.w;
        }
        __syncthreads();
#pragma unroll
        for (int kk = 0; kk < 16; kk++) {
            float4 ra0 = *(const float4*)&As[kk][ty * 8];
            float4 ra1 = *(const float4*)&As[kk][ty * 8 + 4];
            float4 rb = *(const float4*)&Bs[kk][tx * 4];
            float a[8] = {ra0.x, ra0.y, ra0.z, ra0.w, ra1.x, ra1.y, ra1.z, ra1.w};
            float b_[4] = {rb.x, rb.y, rb.z, rb.w};
#pragma unroll
            for (int i = 0; i < 8; i++)
#pragma unroll
                for (int j = 0; j < 4; j++) acc[i][j] += a[i] * b_[j];
        }
        __syncthreads();
    }
    float4 bv = *(const float4*)&bias[bn + tx * 4];
#pragma unroll
    for (int i = 0; i < 8; i++) {
        int m = bm + ty * 8 + i;
        float4 o;
        o.x = fmaxf(acc[i][0] + bv.x, MIN_POS);
        o.y = fmaxf(acc[i][1] + bv.y, MIN_POS);
        o.z = fmaxf(acc[i][2] + bv.z, MIN_POS);
        o.w = fmaxf(acc[i][3] + bv.w, MIN_POS);
        *(float4*)&g_xe[(size_t)m * NE + bn + tx * 4] = o;
    }
}

// ---------------- K3: fused NNMF iterations (unchanged; correct+fast enough) ----------------
__global__ void __launch_bounds__(256) nnmf_kernel() {
    __shared__ __align__(16) float sW[NFH * NDH];
    __shared__ __align__(16) float s_h[32][64];
    __shared__ __align__(16) float s_ratio[32][64];

    int head = blockIdx.y;
    int tile = blockIdx.x;
    int tid = threadIdx.x;
    int d4 = tid & 15;
    int tg = tid >> 4;
    int t0 = tg * 2, t1 = tg * 2 + 1;
    int tokbase = tile * 32;

    for (int i = tid; i < NFH * NDH; i += 256) sW[i] = g_Wn[i];

    float inp0[4], inp1[4];
    {
        const float4 x0 = *(const float4*)&g_xe[(size_t)(tokbase + t0) * NE + head * 64 + d4 * 4];
        const float4 x1 = *(const float4*)&g_xe[(size_t)(tokbase + t1) * NE + head * 64 + d4 * 4];
        float s0 = red16(x0.x + x0.y + x0.z + x0.w);
        float s1 = red16(x1.x + x1.y + x1.z + x1.w);
        float i0 = 1.f / fmaxf(s0, EPSV), i1 = 1.f / fmaxf(s1, EPSV);
        inp0[0] = x0.x * i0; inp0[1] = x0.y * i0; inp0[2] = x0.z * i0; inp0[3] = x0.w * i0;
        inp1[0] = x1.x * i1; inp1[1] = x1.y * i1; inp1[2] = x1.z * i1; inp1[3] = x1.w * i1;
    }
    float hr0[4], hr1[4];
    const float hinit = 1.f / 64.f;
#pragma unroll
    for (int i = 0; i < 4; i++) { hr0[i] = hinit; hr1[i] = hinit; }
    *(float4*)&s_h[t0][d4 * 4] = make_float4(hinit, hinit, hinit, hinit);
    *(float4*)&s_h[t1][d4 * 4] = make_float4(hinit, hinit, hinit, hinit);
    __syncthreads();

    float rn0[4], rn1[4];

    for (int it = 0; it < 3; ++it) {
        float a0[4] = {}, a1[4] = {};
#pragma unroll 16
        for (int ff = 0; ff < 64; ++ff) {
            float4 w = *(const float4*)&sW[ff * 64 + d4 * 4];
            float h0 = s_h[t0][ff], h1 = s_h[t1][ff];
            a0[0] += h0 * w.x; a0[1] += h0 * w.y; a0[2] += h0 * w.z; a0[3] += h0 * w.w;
            a1[0] += h1 * w.x; a1[1] += h1 * w.y; a1[2] += h1 * w.z; a1[3] += h1 * w.w;
        }
#pragma unroll
        for (int i = 0; i < 4; i++) { a0[i] = fmaxf(a0[i], MIN_POS); a1[i] = fmaxf(a1[i], MIN_POS); }
        float p0 = red16(a0[0] + a0[1] + a0[2] + a0[3]);
        float p1 = red16(a1[0] + a1[1] + a1[2] + a1[3]);
        float iv0 = 1.f / fmaxf(p0, EPSV), iv1 = 1.f / fmaxf(p1, EPSV);
        float q0[4], q1[4];
#pragma unroll
        for (int i = 0; i < 4; i++) {
            rn0[i] = a0[i] * iv0; rn1[i] = a1[i] * iv1;
            q0[i] = inp0[i] / rn0[i]; q1[i] = inp1[i] / rn1[i];
        }
        *(float4*)&s_ratio[t0][d4 * 4] = make_float4(q0[0], q0[1], q0[2], q0[3]);
        *(float4*)&s_ratio[t1][d4 * 4] = make_float4(q1[0], q1[1], q1[2], q1[3]);
        __syncthreads();

        float b0[4] = {}, b1[4] = {};
#pragma unroll
        for (int jj = 0; jj < 16; ++jj) {
            int j = (jj + d4) & 15;
            float4 r0v = *(const float4*)&s_ratio[t0][j * 4];
            float4 r1v = *(const float4*)&s_ratio[t1][j * 4];
#pragma unroll
            for (int i = 0; i < 4; i++) {
                float4 w = *(const float4*)&sW[(d4 * 4 + i) * 64 + j * 4];
                b0[i] += w.x * r0v.x + w.y * r0v.y + w.z * r0v.z + w.w * r0v.w;
                b1[i] += w.x * r1v.x + w.y * r1v.y + w.z * r1v.z + w.w * r1v.w;
            }
        }
        float hn0[4], hn1[4];
#pragma unroll
        for (int i = 0; i < 4; i++) {
            hn0[i] = fmaxf(hr0[i] * b0[i], MIN_POS);
            hn1[i] = fmaxf(hr1[i] * b1[i], MIN_POS);
        }
        float hs0 = red16(hn0[0] + hn0[1] + hn0[2] + hn0[3]);
        float hs1 = red16(hn1[0] + hn1[1] + hn1[2] + hn1[3]);
        float ih0 = 1.f / fmaxf(hs0, EPSV), ih1 = 1.f / fmaxf(hs1, EPSV);
#pragma unroll
        for (int i = 0; i < 4; i++) { hr0[i] = hn0[i] * ih0; hr1[i] = hn1[i] * ih1; }
        *(float4*)&s_h[t0][d4 * 4] = make_float4(hr0[0], hr0[1], hr0[2], hr0[3]);
        *(float4*)&s_h[t1][d4 * 4] = make_float4(hr1[0], hr1[1], hr1[2], hr1[3]);
        __syncthreads();
    }

    float hs0 = red16(hr0[0] + hr0[1] + hr0[2] + hr0[3]);
    float hs1 = red16(hr1[0] + hr1[1] + hr1[2] + hr1[3]);
    float ih0 = 1.f / fmaxf(hs0, EPSV), ih1 = 1.f / fmaxf(hs1, EPSV);

    int token0 = tokbase + t0, token1 = tokbase + t1;
    int b0i = token0 >> 10, s0i = token0 & 1023;
    int b1i = token1 >> 10, s1i = token1 & 1023;
    size_t base0 = ((size_t)((b0i * NH + head) * NS + s0i)) * 64 + d4 * 4;
    size_t base1 = ((size_t)((b1i * NH + head) * NS + s1i)) * 64 + d4 * 4;
    *(float4*)&g_h[base0] = make_float4(hr0[0] * ih0, hr0[1] * ih0, hr0[2] * ih0, hr0[3] * ih0);
    *(float4*)&g_h[base1] = make_float4(hr1[0] * ih1, hr1[1] * ih1, hr1[2] * ih1, hr1[3] * ih1);
    *(float4*)&g_hri[base0] = make_float4(rn0[0] * inp0[0], rn0[1] * inp0[1], rn0[2] * inp0[2], rn0[3] * inp0[3]);
    *(float4*)&g_hri[base1] = make_float4(rn1[0] * inp1[0], rn1[1] * inp1[1], rn1[2] * inp1[2], rn1[3] * inp1[3]);
}

// ---------------- K4a: G1 = h^T * hri partials + colsum(h) partials ----------------
// grid (NSPLIT, NBH) = (16, 24) = 384 blocks, 256 threads.
__global__ void __launch_bounds__(256) g1_kernel() {
    __shared__ __align__(16) float s_h[16][68];
    __shared__ __align__(16) float s_r[16][68];
    int split = blockIdx.x, bh = blockIdx.y;
    int tid = threadIdx.x;
    int f4 = tid & 15, d4 = tid >> 4;
    int lo = tid >> 4, lq = tid & 15;
    const float* hb = g_h + ((size_t)bh * NS + split * OSPL) * 64;
    const float* rb = g_hri + ((size_t)bh * NS + split * OSPL) * 64;

    float acc[4][4] = {};
    float cs[4] = {};
    for (int c = 0; c < OSPL / 16; ++c) {
        *(float4*)&s_h[lo][lq * 4] = *(const float4*)&hb[(c * 16 + lo) * 64 + lq * 4];
        *(float4*)&s_r[lo][lq * 4] = *(const float4*)&rb[(c * 16 + lo) * 64 + lq * 4];
        __syncthreads();
#pragma unroll
        for (int o = 0; o < 16; ++o) {
            float4 hv = *(const float4*)&s_h[o][f4 * 4];
            float4 rv = *(const float4*)&s_r[o][d4 * 4];
            float hvv[4] = {hv.x, hv.y, hv.z, hv.w};
            float rvv[4] = {rv.x, rv.y, rv.z, rv.w};
#pragma unroll
            for (int i = 0; i < 4; i++)
#pragma unroll
                for (int j = 0; j < 4; j++) acc[i][j] += hvv[i] * rvv[j];
            if (d4 == 0) {
#pragma unroll
                for (int i = 0; i < 4; i++) cs[i] += hvv[i];
            }
        }
        __syncthreads();
    }
    float* gp = g_G1p + ((size_t)(bh * NSPLIT + split)) * 4096;
#pragma unroll
    for (int i = 0; i < 4; i++)
#pragma unroll
        for (int j = 0; j < 4; j++) gp[(f4 * 4 + i) * 64 + d4 * 4 + j] = acc[i][j];
    if (d4 == 0) {
#pragma unroll
        for (int i = 0; i < 4; i++) g_csp[(bh * NSPLIT + split) * 64 + f4 * 4 + i] = cs[i];
    }
}

// ---------------- K4b: iterations 0+1 in closed form ----------------
__global__ void __launch_bounds__(256) alpha01_kernel() {
    __shared__ float sW[4096];
    __shared__ float sG[4096];
    __shared__ float s_c0[64], s_ai0[64], s_c1[64];
    int bh = blockIdx.x, tid = threadIdx.x;

    for (int i = tid; i < 4096; i += 256) sW[i] = g_Wn[i];
    const float* gp = g_G1p + (size_t)bh * NSPLIT * 4096;
    for (int i = tid; i < 4096; i += 256) {
        float s = 0.f;
#pragma unroll
        for (int p = 0; p < NSPLIT; ++p) s += gp[p * 4096 + i];
        sG[i] = s;
    }
    if (tid < 64) {
        float s = 0.f;
#pragma unroll
        for (int p = 0; p < NSPLIT; ++p) s += g_csp[(bh * NSPLIT + p) * 64 + tid];
        s_c0[tid] = s;
    }
    __syncthreads();
    if (tid < 64) {
        int d = tid;
        float r = 0.f;
#pragma unroll 8
        for (int f = 0; f < 64; ++f) r += s_c0[f] * sW[f * 64 + d];
        float ai = 1.f / (r + EPSV);
        s_ai0[d] = ai;
        g_aiA[bh * 64 + d] = ai;
    }
    __syncthreads();
    if (tid < 64) {
        int f = tid;
        float c1 = 0.f;
#pragma unroll 8
        for (int dd = 0; dd < 64; ++dd) {
            int d = (dd + f) & 63;
            c1 += sG[f * 64 + d] * s_ai0[d];
        }
        s_c1[f] = c1;
    }
    __syncthreads();
    if (tid < 64) {
        int d = tid;
        float r = 0.f;
#pragma unroll 8
        for (int f = 0; f < 64; ++f) r += s_c1[f] * sW[f * 64 + d];
        g_aiB[bh * 64 + d] = 1.f / (r + EPSV);
    }
}

// ---------------- K4c: pass2 — w01 per token, partial c2, partial M = h^T (w01*hri) ----------------
// grid (NSPLIT, NBH), 256 threads.
__global__ void __launch_bounds__(256) pass2_kernel() {
    __shared__ __align__(16) float s_h[16][68];
    __shared__ __align__(16) float s_r[16][68];
    __shared__ float s_ai0[64], s_ai1[64];
    __shared__ float s_w[16];
    int split = blockIdx.x, bh = blockIdx.y;
    int tid = threadIdx.x;
    int f4 = tid & 15, d4 = tid >> 4;
    int lo = tid >> 4, lq = tid & 15;
    if (tid < 64) s_ai0[tid] = g_aiA[bh * 64 + tid];
    else if (tid < 128) s_ai1[tid - 64] = g_aiB[bh * 64 + tid - 64];

    const float* hb = g_h + ((size_t)bh * NS + split * OSPL) * 64;
    const float* rb = g_hri + ((size_t)bh * NS + split * OSPL) * 64;

    float accM[4][4] = {};
    float cs[4] = {};
    for (int c = 0; c < OSPL / 16; ++c) {
        *(float4*)&s_h[lo][lq * 4] = *(const float4*)&hb[(c * 16 + lo) * 64 + lq * 4];
        *(float4*)&s_r[lo][lq * 4] = *(const float4*)&rb[(c * 16 + lo) * 64 + lq * 4];
        __syncthreads();
        // w01 for these 16 tokens: token tt = tid>>4, 16 threads each (d slice lq*4)
        {
            int tt = tid >> 4;
            float4 v = *(const float4*)&s_r[tt][lq * 4];
            int base = lq * 4;
            float u0 = v.x * s_ai0[base] + v.y * s_ai0[base + 1] + v.z * s_ai0[base + 2] + v.w * s_ai0[base + 3];
            float u1 = v.x * s_ai1[base] + v.y * s_ai1[base + 1] + v.z * s_ai1[base + 2] + v.w * s_ai1[base + 3];
            u0 = red16(u0);
            u1 = red16(u1);
            if (lq == 0) s_w[tt] = u0 * u1;
        }
        __syncthreads();
#pragma unroll
        for (int o = 0; o < 16; ++o) {
            float wo = s_w[o];
            float4 hv = *(const float4*)&s_h[o][f4 * 4];
            float4 rv = *(const float4*)&s_r[o][d4 * 4];
            float hw[4] = {hv.x * wo, hv.y * wo, hv.z * wo, hv.w * wo};
            float rvv[4] = {rv.x, rv.y, rv.z, rv.w};
#pragma unroll
            for (int i = 0; i < 4; i++)
#pragma unroll
                for (int j = 0; j < 4; j++) accM[i][j] += hw[i] * rvv[j];
            if (d4 == 0) {
#pragma unroll
                for (int i = 0; i < 4; i++) cs[i] += hw[i];
            }
        }
        __syncthreads();
    }
    float* mp = g_Mp + ((size_t)(bh * NSPLIT + split)) * 4096;
#pragma unroll
    for (int i = 0; i < 4; i++)
#pragma unroll
        for (int j = 0; j < 4; j++) mp[(f4 * 4 + i) * 64 + d4 * 4 + j] = accM[i][j];
    if (d4 == 0) {
#pragma unroll
        for (int i = 0; i < 4; i++) g_c2p[(bh * NSPLIT + split) * 64 + f4 * 4 + i] = cs[i];
    }
}

// ---------------- K4d: ai2 + cfin = (ΣM)·ai2 ----------------
__global__ void __launch_bounds__(256) alpha2cfin_kernel() {
    __shared__ float sW[4096];
    __shared__ float s_c2[64];
    __shared__ float s_ai2[64];
    __shared__ float s_p[4][64];
    int bh = blockIdx.x, tid = threadIdx.x;
    for (int i = tid; i < 4096; i += 256) sW[i] = g_Wn[i];
    if (tid < 64) {
        float s = 0.f;
#pragma unroll
        for (int p = 0; p < NSPLIT; ++p) s += g_c2p[(bh * NSPLIT + p) * 64 + tid];
        s_c2[tid] = s;
    }
    __syncthreads();
    if (tid < 64) {
        int d = tid;
        float r = 0.f;
#pragma unroll 8
        for (int f = 0; f < 64; ++f) r += s_c2[f] * sW[f * 64 + d];
        s_ai2[d] = 1.f / (r + EPSV);
    }
    __syncthreads();
    // cfin[f] = sum_d (sum_p Mp[f,d]) * ai2[d]; thread = (f, dgroup of 16)
    {
        int f = tid & 63, g = tid >> 6;
        const float* mp = g_Mp + (size_t)bh * NSPLIT * 4096;
        float partial = 0.f;
#pragma unroll
        for (int dd = 0; dd < 16; ++dd) {
            int d = g * 16 + dd;
            float mv = 0.f;
#pragma unroll
            for (int p = 0; p < NSPLIT; ++p) mv += mp[p * 4096 + f * 64 + d];
            partial += mv * s_ai2[d];
        }
        s_p[g][f] = partial;
    }
    __syncthreads();
    if (tid < 64) {
        int b = bh / NH, head = bh % NH;
        g_cfin[b * NE + head * 64 + tid] = s_p[0][tid] + s_p[1][tid] + s_p[2][tid] + s_p[3][tid];
    }
}

// ---------------- K5: out projection of the 2 unique rows ----------------
__global__ void __launch_bounds__(256) outrow_kernel(const float* __restrict__ out_w,
                                                     const float* __restrict__ out_b) {
    int b = blockIdx.y;
    int warp = threadIdx.x >> 5, lane = threadIdx.x & 31;
    int j = blockIdx.x * 8 + warp;
    const float* c = g_cfin + b * NE;
    const float* wrow = out_w + (size_t)j * NE;
    float acc = 0.f;
    for (int e = lane; e < NE; e += 32) acc += c[e] * wrow[e];
    acc = red32(acc);
    if (lane == 0) g_yrow[b * FIN + j] = acc + out_b[j];
}

// ---------------- K6: broadcast rows to all positions ----------------
__global__ void __launch_bounds__(256) bcast_kernel(float* __restrict__ out) {
    int idx = blockIdx.x * 256 + threadIdx.x;
    const int per_row = FIN / 4;
    int j4 = idx % per_row;
    int bs = idx / per_row;
    int b = bs >> 10;
    float4 v = ((const float4*)(g_yrow + b * FIN))[j4];
    ((float4*)out)[idx] = v;
}

// ---------------- launch ----------------
extern "C" void kernel_launch(void* const* d_in, const int* in_sizes, int n_in,
                              void* d_out, int out_size) {
    const float* x       = (const float*)d_in[0];
    const float* embed_w = (const float*)d_in[1];
    const float* embed_b = (const float*)d_in[2];
    const float* nnmf_w  = (const float*)d_in[3];
    const float* out_w   = (const float*)d_in[4];
    const float* out_b   = (const float*)d_in[5];
    float* out = (float*)d_out;

    wnorm_kernel<<<1, 64>>>(nnmf_w);
    embed_gemm_kernel<<<dim3(NE / 64, (NB * NS) / 128), 256>>>(x, embed_w, embed_b);
    nnmf_kernel<<<dim3((NB * NS) / 32, NH), 256>>>();
    g1_kernel<<<dim3(NSPLIT, NBH), 256>>>();
    alpha01_kernel<<<NBH, 256>>>();
    pass2_kernel<<<dim3(NSPLIT, NBH), 256>>>();
    alpha2cfin_kernel<<<NBH, 256>>>();
    outrow_kernel<<<dim3(NE / 8, NB), 256>>>(out_w, out_b);
    bcast_kernel<<<(NB * NS * (FIN / 4)) / 256, 256>>>(out);
}

// round 4
// speedup vs baseline: 1.2363x; 1.1203x over previous
#include <cuda_runtime.h>
#include <cuda_bf16.h>
#include <cstdint>

#define NB 2
#define NS 1024
#define FIN 768
#define NE 768
#define NH 12
#define NBH (NB * NH)
#define NDH 64
#define NFH 64
#define NSPLIT 16
#define OSPL (NS / NSPLIT)   // 64 tokens per split
#define MIN_POS 1e-6f
#define EPSV 1e-20f
#define K3 2304              // tripled K for bf16-split GEMM

// ---------------- scratch (device globals; no allocation) ----------------
__device__ __align__(16) float g_Wn[NFH * NDH];                 // normalized W [f][d]
__device__ __align__(16) float g_Wt[NDH * NFH];                 // transposed normalized W [d][f]
__device__ __align__(16) __nv_bfloat16 g_Abf[2048 * K3];        // [hi | hi | lo] of X
__device__ __align__(16) __nv_bfloat16 g_Wbf[768 * K3];         // [hi | lo | hi] of embed_w
__device__ __align__(16) float g_xe[NB * NS * NE];              // clipped embed output
__device__ __align__(16) float g_h[NBH * NS * NFH];             // h   [bh][s][f]
__device__ __align__(16) float g_hri[NBH * NS * NDH];           // rec*inp [bh][s][d]
__device__ __align__(16) float g_G1p[NBH * NSPLIT * 64 * 64];   // partial h^T*hri
__device__ __align__(16) float g_Mp[NBH * NSPLIT * 64 * 64];    // partial h^T*(w01*hri)
__device__ __align__(16) float g_csp[NBH * NSPLIT * 64];        // partial colsum(h)
__device__ __align__(16) float g_c2p[NBH * NSPLIT * 64];        // partial c2
__device__ __align__(16) float g_aiA[NBH * 64];                 // arec_inv iter0
__device__ __align__(16) float g_aiB[NBH * 64];                 // arec_inv iter1
__device__ __align__(16) float g_cfin[NB * NE];                 // final mixed row per batch
__device__ __align__(16) float g_yrow[NB * FIN];                // final projected row per batch

// ---------------- helpers ----------------
__device__ __forceinline__ float red16(float v) {
    v += __shfl_xor_sync(0xffffffffu, v, 8);
    v += __shfl_xor_sync(0xffffffffu, v, 4);
    v += __shfl_xor_sync(0xffffffffu, v, 2);
    v += __shfl_xor_sync(0xffffffffu, v, 1);
    return v;
}
__device__ __forceinline__ float red32(float v) {
    v += __shfl_xor_sync(0xffffffffu, v, 16);
    return red16(v);
}
__device__ __forceinline__ uint32_t pack2(__nv_bfloat16 a, __nv_bfloat16 b) {
    __nv_bfloat162 t = __halves2bfloat162(a, b);
    return *reinterpret_cast<uint32_t*>(&t);
}
__device__ __forceinline__ void ldsm4(uint32_t* r, uint32_t addr) {
    asm volatile("ldmatrix.sync.aligned.m8n8.x4.shared.b16 {%0,%1,%2,%3}, [%4];"
                 : "=r"(r[0]), "=r"(r[1]), "=r"(r[2]), "=r"(r[3]) : "r"(addr));
}
__device__ __forceinline__ void mma_bf16(float* c, const uint32_t* a, uint32_t b0, uint32_t b1) {
    asm volatile(
        "mma.sync.aligned.m16n8k16.row.col.f32.bf16.bf16.f32 "
        "{%0,%1,%2,%3}, {%4,%5,%6,%7}, {%8,%9}, {%0,%1,%2,%3};\n"
        : "+f"(c[0]), "+f"(c[1]), "+f"(c[2]), "+f"(c[3])
        : "r"(a[0]), "r"(a[1]), "r"(a[2]), "r"(a[3]), "r"(b0), "r"(b1));
}

// ---------------- K1: normalize nnmf_w rows (+ transpose) ----------------
__global__ void wnorm_kernel(const float* __restrict__ nnmf_w) {
    int f = threadIdx.x;  // 0..63
    float s = 0.f;
#pragma unroll
    for (int d = 0; d < NDH; ++d) s += nnmf_w[f * NDH + d];
    s = fmaxf(s, EPSV);
    float inv = 1.f / s;
#pragma unroll
    for (int d = 0; d < NDH; ++d) {
        float v = nnmf_w[f * NDH + d] * inv;
        g_Wn[f * NDH + d] = v;
        g_Wt[d * NFH + f] = v;
    }
}

// ---------------- K2a: bf16 split conversion of X and embed_w ----------------
// 2816 rows total (2048 X + 768 W), 192 float4 per row.
__global__ void __launch_bounds__(256) conv_kernel(const float* __restrict__ X,
                                                   const float* __restrict__ Wm) {
    int i = blockIdx.x * 256 + threadIdx.x;
    int row = i / 192, q = (i % 192) * 4;
    const float* src = (row < 2048) ? X + (size_t)row * 768 + q
                                    : Wm + (size_t)(row - 2048) * 768 + q;
    float4 v = *(const float4*)src;
    float xs[4] = {v.x, v.y, v.z, v.w};
    __nv_bfloat16 hi[4], lo[4];
#pragma unroll
    for (int j = 0; j < 4; ++j) {
        hi[j] = __float2bfloat16(xs[j]);
        lo[j] = __float2bfloat16(xs[j] - __bfloat162float(hi[j]));
    }
    uint2 hv = make_uint2(pack2(hi[0], hi[1]), pack2(hi[2], hi[3]));
    uint2 lv = make_uint2(pack2(lo[0], lo[1]), pack2(lo[2], lo[3]));
    if (row < 2048) {
        __nv_bfloat16* dst = g_Abf + (size_t)row * K3 + q;
        *(uint2*)(dst)        = hv;   // seg1: hi
        *(uint2*)(dst + 768)  = hv;   // seg2: hi
        *(uint2*)(dst + 1536) = lv;   // seg3: lo
    } else {
        __nv_bfloat16* dst = g_Wbf + (size_t)(row - 2048) * K3 + q;
        *(uint2*)(dst)        = hv;   // seg1: hi
        *(uint2*)(dst + 768)  = lv;   // seg2: lo
        *(uint2*)(dst + 1536) = hv;   // seg3: hi
    }
}

// ---------------- K2b: embed GEMM via mma.sync bf16, K=2304 ----------------
// BM=128, BN=64, BK=32. 256 threads = 8 warps (4 m x 2 n), warp = 32m x 32n.
// SMEM row stride 40 bf16 (80B) -> conflict-free ldmatrix.
__global__ void __launch_bounds__(256) embed_mma_kernel(const float* __restrict__ bias) {
    __shared__ __align__(16) __nv_bfloat16 As[128 * 40];
    __shared__ __align__(16) __nv_bfloat16 Bs[64 * 40];
    int tid = threadIdx.x;
    int bm = blockIdx.y * 128, bn = blockIdx.x * 64;
    int wid = tid >> 5, lane = tid & 31;
    int wm = wid & 3, wn = wid >> 2;

    float c[2][4][4];
#pragma unroll
    for (int mt = 0; mt < 2; ++mt)
#pragma unroll
        for (int nt = 0; nt < 4; ++nt)
#pragma unroll
            for (int r = 0; r < 4; ++r) c[mt][nt][r] = 0.f;

    // ldmatrix base addresses (element offsets; +kk at use time)
    uint32_t a_base[2], b_base[2];
#pragma unroll
    for (int mt = 0; mt < 2; ++mt) {
        int row = wm * 32 + mt * 16 + (lane & 15);
        int colhalf = lane >> 4;
        a_base[mt] = (uint32_t)__cvta_generic_to_shared(&As[row * 40 + colhalf * 8]);
    }
#pragma unroll
    for (int bt = 0; bt < 2; ++bt) {
        int n = wn * 32 + bt * 16 + ((lane >> 4) << 3) + (lane & 7);
        int khalf = (lane >> 3) & 1;
        b_base[bt] = (uint32_t)__cvta_generic_to_shared(&Bs[n * 40 + khalf * 8]);
    }

    for (int ks = 0; ks < K3 / 32; ++ks) {
        int k0 = ks * 32;
        // load A: 512 16B-chunks, 2 per thread
#pragma unroll
        for (int r = 0; r < 2; ++r) {
            int q = tid + r * 256;
            int m = q >> 2, cch = q & 3;
            *(uint4*)&As[m * 40 + cch * 8] =
                *(const uint4*)&g_Abf[(size_t)(bm + m) * K3 + k0 + cch * 8];
        }
        // load B: 256 chunks, 1 per thread
        {
            int n = tid >> 2, cch = tid & 3;
            *(uint4*)&Bs[n * 40 + cch * 8] =
                *(const uint4*)&g_Wbf[(size_t)(bn + n) * K3 + k0 + cch * 8];
        }
        __syncthreads();
#pragma unroll
        for (int kh = 0; kh < 2; ++kh) {
            int kk = kh * 16;
            uint32_t a[2][4], b[2][4];
            ldsm4(a[0], a_base[0] + kk * 2);
            ldsm4(a[1], a_base[1] + kk * 2);
            ldsm4(b[0], b_base[0] + kk * 2);
            ldsm4(b[1], b_base[1] + kk * 2);
#pragma unroll
            for (int mt = 0; mt < 2; ++mt)
#pragma unroll
                for (int nt = 0; nt < 4; ++nt)
                    mma_bf16(c[mt][nt], a[mt], b[nt >> 1][(nt & 1) * 2], b[nt >> 1][(nt & 1) * 2 + 1]);
        }
        __syncthreads();
    }

    // epilogue: bias + clip, write fp32
#pragma unroll
    for (int mt = 0; mt < 2; ++mt) {
#pragma unroll
        for (int nt = 0; nt < 4; ++nt) {
            int m0 = bm + wm * 32 + mt * 16 + (lane >> 2);
            int n0 = bn + wn * 32 + nt * 8 + (lane & 3) * 2;
            float2 bv = *(const float2*)&bias[n0];
            float2 o0, o1;
            o0.x = fmaxf(c[mt][nt][0] + bv.x, MIN_POS);
            o0.y = fmaxf(c[mt][nt][1] + bv.y, MIN_POS);
            o1.x = fmaxf(c[mt][nt][2] + bv.x, MIN_POS);
            o1.y = fmaxf(c[mt][nt][3] + bv.y, MIN_POS);
            *(float2*)&g_xe[(size_t)m0 * NE + n0] = o0;
            *(float2*)&g_xe[(size_t)(m0 + 8) * NE + n0] = o1;
        }
    }
}

// ---------------- K3: fused NNMF, 4 tokens/thread, 64 tokens/block ----------------
// dynamic smem: sW[64*64], sWt[64*68], s_h[64*64], s_r[64*64]
#define NN_SW 0
#define NN_SWT 4096
#define NN_SH (4096 + 64 * 68)
#define NN_SR (NN_SH + 4096)
#define NN_SMEM_FLOATS (NN_SR + 4096)
__global__ void __launch_bounds__(256) nnmf_kernel4() {
    extern __shared__ float sm[];
    float* sW = sm + NN_SW;    // [f][d], stride 64
    float* sWt = sm + NN_SWT;  // [d][f], stride 68
    float* s_h = sm + NN_SH;   // [tok][f], stride 64
    float* s_r = sm + NN_SR;   // [tok][d], stride 64

    int head = blockIdx.y;
    int tile = blockIdx.x;     // 0..31, 64 tokens each
    int tid = threadIdx.x;
    int d4 = tid & 15;
    int tg = tid >> 4;
    int tokbase = tile * 64;

    for (int i = tid; i < 4096; i += 256) sW[i] = g_Wn[i];
    for (int i = tid; i < 4096; i += 256) {
        int d = i >> 6, f = i & 63;
        sWt[d * 68 + f] = g_Wt[i];
    }

    // inp: l1norm per token over 64 dims
    float inp[4][4];
#pragma unroll
    for (int t = 0; t < 4; ++t) {
        int tok = tokbase + tg * 4 + t;
        float4 x = *(const float4*)&g_xe[(size_t)tok * NE + head * 64 + d4 * 4];
        float s = red16(x.x + x.y + x.z + x.w);
        float iv = 1.f / fmaxf(s, EPSV);
        inp[t][0] = x.x * iv; inp[t][1] = x.y * iv; inp[t][2] = x.z * iv; inp[t][3] = x.w * iv;
    }
    float hr[4][4];
    const float hinit = 1.f / 64.f;
#pragma unroll
    for (int t = 0; t < 4; ++t) {
#pragma unroll
        for (int i = 0; i < 4; ++i) hr[t][i] = hinit;
        *(float4*)&s_h[(tg * 4 + t) * 64 + d4 * 4] = make_float4(hinit, hinit, hinit, hinit);
    }
    __syncthreads();

    float rn[4][4];
    for (int it = 0; it < 3; ++it) {
        // rec-phase: rec[d] = sum_f h[f] * W[f][d]
        float a[4][4] = {};
#pragma unroll 8
        for (int ff = 0; ff < 64; ++ff) {
            float4 w = *(const float4*)&sW[ff * 64 + d4 * 4];
            float h0 = s_h[(tg * 4 + 0) * 64 + ff];
            float h1 = s_h[(tg * 4 + 1) * 64 + ff];
            float h2 = s_h[(tg * 4 + 2) * 64 + ff];
            float h3 = s_h[(tg * 4 + 3) * 64 + ff];
            a[0][0] += h0 * w.x; a[0][1] += h0 * w.y; a[0][2] += h0 * w.z; a[0][3] += h0 * w.w;
            a[1][0] += h1 * w.x; a[1][1] += h1 * w.y; a[1][2] += h1 * w.z; a[1][3] += h1 * w.w;
            a[2][0] += h2 * w.x; a[2][1] += h2 * w.y; a[2][2] += h2 * w.z; a[2][3] += h2 * w.w;
            a[3][0] += h3 * w.x; a[3][1] += h3 * w.y; a[3][2] += h3 * w.z; a[3][3] += h3 * w.w;
        }
#pragma unroll
        for (int t = 0; t < 4; ++t) {
#pragma unroll
            for (int i = 0; i < 4; ++i) a[t][i] = fmaxf(a[t][i], MIN_POS);
            float p = red16(a[t][0] + a[t][1] + a[t][2] + a[t][3]);
            float iv = 1.f / fmaxf(p, EPSV);
            float q[4];
#pragma unroll
            for (int i = 0; i < 4; ++i) {
                rn[t][i] = a[t][i] * iv;
                q[i] = inp[t][i] / rn[t][i];
            }
            *(float4*)&s_r[(tg * 4 + t) * 64 + d4 * 4] = make_float4(q[0], q[1], q[2], q[3]);
        }
        __syncthreads();

        // t-phase: t[f] = sum_d ratio[d] * W[f][d] = sum_d ratio[d] * Wt[d][f]
        float b[4][4] = {};
#pragma unroll 8
        for (int d = 0; d < 64; ++d) {
            float4 wt = *(const float4*)&sWt[d * 68 + d4 * 4];
            float r0 = s_r[(tg * 4 + 0) * 64 + d];
            float r1 = s_r[(tg * 4 + 1) * 64 + d];
            float r2 = s_r[(tg * 4 + 2) * 64 + d];
            float r3 = s_r[(tg * 4 + 3) * 64 + d];
            b[0][0] += r0 * wt.x; b[0][1] += r0 * wt.y; b[0][2] += r0 * wt.z; b[0][3] += r0 * wt.w;
            b[1][0] += r1 * wt.x; b[1][1] += r1 * wt.y; b[1][2] += r1 * wt.z; b[1][3] += r1 * wt.w;
            b[2][0] += r2 * wt.x; b[2][1] += r2 * wt.y; b[2][2] += r2 * wt.z; b[2][3] += r2 * wt.w;
            b[3][0] += r3 * wt.x; b[3][1] += r3 * wt.y; b[3][2] += r3 * wt.z; b[3][3] += r3 * wt.w;
        }
#pragma unroll
        for (int t = 0; t < 4; ++t) {
            float hn[4];
#pragma unroll
            for (int i = 0; i < 4; ++i) hn[i] = fmaxf(hr[t][i] * b[t][i], MIN_POS);
            float hs = red16(hn[0] + hn[1] + hn[2] + hn[3]);
            float ih = 1.f / fmaxf(hs, EPSV);
#pragma unroll
            for (int i = 0; i < 4; ++i) hr[t][i] = hn[i] * ih;
            *(float4*)&s_h[(tg * 4 + t) * 64 + d4 * 4] =
                make_float4(hr[t][0], hr[t][1], hr[t][2], hr[t][3]);
        }
        __syncthreads();
    }

    // final l1norm + writes
#pragma unroll
    for (int t = 0; t < 4; ++t) {
        float hs = red16(hr[t][0] + hr[t][1] + hr[t][2] + hr[t][3]);
        float ih = 1.f / fmaxf(hs, EPSV);
        int token = tokbase + tg * 4 + t;
        int bi = token >> 10, si = token & 1023;
        size_t base = ((size_t)((bi * NH + head) * NS + si)) * 64 + d4 * 4;
        *(float4*)&g_h[base] =
            make_float4(hr[t][0] * ih, hr[t][1] * ih, hr[t][2] * ih, hr[t][3] * ih);
        *(float4*)&g_hri[base] =
            make_float4(rn[t][0] * inp[t][0], rn[t][1] * inp[t][1],
                        rn[t][2] * inp[t][2], rn[t][3] * inp[t][3]);
    }
}

// ---------------- K4a: G1 = h^T * hri partials + colsum(h) partials ----------------
__global__ void __launch_bounds__(256) g1_kernel() {
    __shared__ __align__(16) float s_h[16][68];
    __shared__ __align__(16) float s_r[16][68];
    int split = blockIdx.x, bh = blockIdx.y;
    int tid = threadIdx.x;
    int f4 = tid & 15, d4 = tid >> 4;
    int lo = tid >> 4, lq = tid & 15;
    const float* hb = g_h + ((size_t)bh * NS + split * OSPL) * 64;
    const float* rb = g_hri + ((size_t)bh * NS + split * OSPL) * 64;

    float acc[4][4] = {};
    float cs[4] = {};
    for (int c = 0; c < OSPL / 16; ++c) {
        *(float4*)&s_h[lo][lq * 4] = *(const float4*)&hb[(c * 16 + lo) * 64 + lq * 4];
        *(float4*)&s_r[lo][lq * 4] = *(const float4*)&rb[(c * 16 + lo) * 64 + lq * 4];
        __syncthreads();
#pragma unroll
        for (int o = 0; o < 16; ++o) {
            float4 hv = *(const float4*)&s_h[o][f4 * 4];
            float4 rv = *(const float4*)&s_r[o][d4 * 4];
            float hvv[4] = {hv.x, hv.y, hv.z, hv.w};
            float rvv[4] = {rv.x, rv.y, rv.z, rv.w};
#pragma unroll
            for (int i = 0; i < 4; i++)
#pragma unroll
                for (int j = 0; j < 4; j++) acc[i][j] += hvv[i] * rvv[j];
            if (d4 == 0) {
#pragma unroll
                for (int i = 0; i < 4; i++) cs[i] += hvv[i];
            }
        }
        __syncthreads();
    }
    float* gp = g_G1p + ((size_t)(bh * NSPLIT + split)) * 4096;
#pragma unroll
    for (int i = 0; i < 4; i++)
#pragma unroll
        for (int j = 0; j < 4; j++) gp[(f4 * 4 + i) * 64 + d4 * 4 + j] = acc[i][j];
    if (d4 == 0) {
#pragma unroll
        for (int i = 0; i < 4; i++) g_csp[(bh * NSPLIT + split) * 64 + f4 * 4 + i] = cs[i];
    }
}

// ---------------- K4b: iterations 0+1 in closed form ----------------
__global__ void __launch_bounds__(256) alpha01_kernel() {
    __shared__ float sW[4096];
    __shared__ float sG[4096];
    __shared__ float s_c0[64], s_ai0[64], s_c1[64];
    int bh = blockIdx.x, tid = threadIdx.x;

    for (int i = tid; i < 4096; i += 256) sW[i] = g_Wn[i];
    const float* gp = g_G1p + (size_t)bh * NSPLIT * 4096;
    for (int i = tid; i < 4096; i += 256) {
        float s = 0.f;
#pragma unroll
        for (int p = 0; p < NSPLIT; ++p) s += gp[p * 4096 + i];
        sG[i] = s;
    }
    if (tid < 64) {
        float s = 0.f;
#pragma unroll
        for (int p = 0; p < NSPLIT; ++p) s += g_csp[(bh * NSPLIT + p) * 64 + tid];
        s_c0[tid] = s;
    }
    __syncthreads();
    if (tid < 64) {
        int d = tid;
        float r = 0.f;
#pragma unroll 8
        for (int f = 0; f < 64; ++f) r += s_c0[f] * sW[f * 64 + d];
        float ai = 1.f / (r + EPSV);
        s_ai0[d] = ai;
        g_aiA[bh * 64 + d] = ai;
    }
    __syncthreads();
    if (tid < 64) {
        int f = tid;
        float c1 = 0.f;
#pragma unroll 8
        for (int dd = 0; dd < 64; ++dd) {
            int d = (dd + f) & 63;
            c1 += sG[f * 64 + d] * s_ai0[d];
        }
        s_c1[f] = c1;
    }
    __syncthreads();
    if (tid < 64) {
        int d = tid;
        float r = 0.f;
#pragma unroll 8
        for (int f = 0; f < 64; ++f) r += s_c1[f] * sW[f * 64 + d];
        g_aiB[bh * 64 + d] = 1.f / (r + EPSV);
    }
}

// ---------------- K4c: pass2 — w01 per token, partial c2, partial M ----------------
__global__ void __launch_bounds__(256) pass2_kernel() {
    __shared__ __align__(16) float s_h[16][68];
    __shared__ __align__(16) float s_r[16][68];
    __shared__ float s_ai0[64], s_ai1[64];
    __shared__ float s_w[16];
    int split = blockIdx.x, bh = blockIdx.y;
    int tid = threadIdx.x;
    int f4 = tid & 15, d4 = tid >> 4;
    int lo = tid >> 4, lq = tid & 15;
    if (tid < 64) s_ai0[tid] = g_aiA[bh * 64 + tid];
    else if (tid < 128) s_ai1[tid - 64] = g_aiB[bh * 64 + tid - 64];

    const float* hb = g_h + ((size_t)bh * NS + split * OSPL) * 64;
    const float* rb = g_hri + ((size_t)bh * NS + split * OSPL) * 64;

    float accM[4][4] = {};
    float cs[4] = {};
    for (int c = 0; c < OSPL / 16; ++c) {
        *(float4*)&s_h[lo][lq * 4] = *(const float4*)&hb[(c * 16 + lo) * 64 + lq * 4];
        *(float4*)&s_r[lo][lq * 4] = *(const float4*)&rb[(c * 16 + lo) * 64 + lq * 4];
        __syncthreads();
        {
            int tt = tid >> 4;
            float4 v = *(const float4*)&s_r[tt][lq * 4];
            int base = lq * 4;
            float u0 = v.x * s_ai0[base] + v.y * s_ai0[base + 1] + v.z * s_ai0[base + 2] + v.w * s_ai0[base + 3];
            float u1 = v.x * s_ai1[base] + v.y * s_ai1[base + 1] + v.z * s_ai1[base + 2] + v.w * s_ai1[base + 3];
            u0 = red16(u0);
            u1 = red16(u1);
            if (lq == 0) s_w[tt] = u0 * u1;
        }
        __syncthreads();
#pragma unroll
        for (int o = 0; o < 16; ++o) {
            float wo = s_w[o];
            float4 hv = *(const float4*)&s_h[o][f4 * 4];
            float4 rv = *(const float4*)&s_r[o][d4 * 4];
            float hw[4] = {hv.x * wo, hv.y * wo, hv.z * wo, hv.w * wo};
            float rvv[4] = {rv.x, rv.y, rv.z, rv.w};
#pragma unroll
            for (int i = 0; i < 4; i++)
#pragma unroll
                for (int j = 0; j < 4; j++) accM[i][j] += hw[i] * rvv[j];
            if (d4 == 0) {
#pragma unroll
                for (int i = 0; i < 4; i++) cs[i] += hw[i];
            }
        }
        __syncthreads();
    }
    float* mp = g_Mp + ((size_t)(bh * NSPLIT + split)) * 4096;
#pragma unroll
    for (int i = 0; i < 4; i++)
#pragma unroll
        for (int j = 0; j < 4; j++) mp[(f4 * 4 + i) * 64 + d4 * 4 + j] = accM[i][j];
    if (d4 == 0) {
#pragma unroll
        for (int i = 0; i < 4; i++) g_c2p[(bh * NSPLIT + split) * 64 + f4 * 4 + i] = cs[i];
    }
}

// ---------------- K4d: ai2 + cfin = (sum M)·ai2 ----------------
__global__ void __launch_bounds__(256) alpha2cfin_kernel() {
    __shared__ float sW[4096];
    __shared__ float s_c2[64];
    __shared__ float s_ai2[64];
    __shared__ float s_p[4][64];
    int bh = blockIdx.x, tid = threadIdx.x;
    for (int i = tid; i < 4096; i += 256) sW[i] = g_Wn[i];
    if (tid < 64) {
        float s = 0.f;
#pragma unroll
        for (int p = 0; p < NSPLIT; ++p) s += g_c2p[(bh * NSPLIT + p) * 64 + tid];
        s_c2[tid] = s;
    }
    __syncthreads();
    if (tid < 64) {
        int d = tid;
        float r = 0.f;
#pragma unroll 8
        for (int f = 0; f < 64; ++f) r += s_c2[f] * sW[f * 64 + d];
        s_ai2[d] = 1.f / (r + EPSV);
    }
    __syncthreads();
    {
        int f = tid & 63, g = tid >> 6;
        const float* mp = g_Mp + (size_t)bh * NSPLIT * 4096;
        float partial = 0.f;
#pragma unroll
        for (int dd = 0; dd < 16; ++dd) {
            int d = g * 16 + dd;
            float mv = 0.f;
#pragma unroll
            for (int p = 0; p < NSPLIT; ++p) mv += mp[p * 4096 + f * 64 + d];
            partial += mv * s_ai2[d];
        }
        s_p[g][f] = partial;
    }
    __syncthreads();
    if (tid < 64) {
        int b = bh / NH, head = bh % NH;
        g_cfin[b * NE + head * 64 + tid] = s_p[0][tid] + s_p[1][tid] + s_p[2][tid] + s_p[3][tid];
    }
}

// ---------------- K5: out projection of the 2 unique rows ----------------
__global__ void __launch_bounds__(256) outrow_kernel(const float* __restrict__ out_w,
                                                     const float* __restrict__ out_b) {
    int b = blockIdx.y;
    int warp = threadIdx.x >> 5, lane = threadIdx.x & 31;
    int j = blockIdx.x * 8 + warp;
    const float* c = g_cfin + b * NE;
    const float* wrow = out_w + (size_t)j * NE;
    float acc = 0.f;
    for (int e = lane; e < NE; e += 32) acc += c[e] * wrow[e];
    acc = red32(acc);
    if (lane == 0) g_yrow[b * FIN + j] = acc + out_b[j];
}

// ---------------- K6: broadcast rows to all positions ----------------
__global__ void __launch_bounds__(256) bcast_kernel(float* __restrict__ out) {
    int idx = blockIdx.x * 256 + threadIdx.x;
    const int per_row = FIN / 4;
    int j4 = idx % per_row;
    int bs = idx / per_row;
    int b = bs >> 10;
    float4 v = ((const float4*)(g_yrow + b * FIN))[j4];
    ((float4*)out)[idx] = v;
}

// ---------------- launch ----------------
extern "C" void kernel_launch(void* const* d_in, const int* in_sizes, int n_in,
                              void* d_out, int out_size) {
    const float* x       = (const float*)d_in[0];
    const float* embed_w = (const float*)d_in[1];
    const float* embed_b = (const float*)d_in[2];
    const float* nnmf_w  = (const float*)d_in[3];
    const float* out_w   = (const float*)d_in[4];
    const float* out_b   = (const float*)d_in[5];
    float* out = (float*)d_out;

    static bool attr_set = false;
    if (!attr_set) {
        cudaFuncSetAttribute(nnmf_kernel4, cudaFuncAttributeMaxDynamicSharedMemorySize,
                             NN_SMEM_FLOATS * (int)sizeof(float));
        attr_set = true;
    }

    wnorm_kernel<<<1, 64>>>(nnmf_w);
    conv_kernel<<<2112, 256>>>(x, embed_w);
    embed_mma_kernel<<<dim3(NE / 64, (NB * NS) / 128), 256>>>(embed_b);
    nnmf_kernel4<<<dim3((NB * NS) / 64, NH), 256, NN_SMEM_FLOATS * sizeof(float)>>>();
    g1_kernel<<<dim3(NSPLIT, NBH), 256>>>();
    alpha01_kernel<<<NBH, 256>>>();
    pass2_kernel<<<dim3(NSPLIT, NBH), 256>>>();
    alpha2cfin_kernel<<<NBH, 256>>>();
    outrow_kernel<<<dim3(NE / 8, NB), 256>>>(out_w, out_b);
    bcast_kernel<<<(NB * NS * (FIN / 4)) / 256, 256>>>(out);
}

// round 5
// speedup vs baseline: 1.2693x; 1.0267x over previous
#include <cuda_runtime.h>
#include <cuda_bf16.h>
#include <cstdint>

#define NB 2
#define NS 1024
#define FIN 768
#define NE 768
#define NH 12
#define NBH (NB * NH)
#define NDH 64
#define NFH 64
#define NSPLIT 16
#define OSPL (NS / NSPLIT)   // 64 tokens per split (pass2)
#define NSG 32               // g1 splits (32 tokens each, fused in nnmf)
#define MIN_POS 1e-6f
#define EPSV 1e-20f
#define K3 2304              // tripled K for bf16-split GEMM

// ---------------- scratch (device globals; no allocation) ----------------
__device__ __align__(16) float g_Wn[NFH * NDH];                 // normalized W [f][d]
__device__ __align__(16) float g_Wt[NDH * NFH];                 // transposed normalized W [d][f]
__device__ __align__(16) __nv_bfloat16 g_Abf[2048 * K3];        // [hi | hi | lo] of X
__device__ __align__(16) __nv_bfloat16 g_Wbf[768 * K3];         // [hi | lo | hi] of embed_w
__device__ __align__(16) float g_xe[NB * NS * NE];              // clipped embed output
__device__ __align__(16) float g_h[NBH * NS * NFH];             // h   [bh][s][f]
__device__ __align__(16) float g_hri[NBH * NS * NDH];           // rec*inp [bh][s][d]
__device__ __align__(16) float g_G1p[NBH * NSG * 64 * 64];      // partial h^T*hri
__device__ __align__(16) float g_Mp[NBH * NSPLIT * 64 * 64];    // partial h^T*(w01*hri)
__device__ __align__(16) float g_csp[NBH * NSG * 64];           // partial colsum(h)
__device__ __align__(16) float g_c2p[NBH * NSPLIT * 64];        // partial c2
__device__ __align__(16) float g_aiA[NBH * 64];                 // arec_inv iter0
__device__ __align__(16) float g_aiB[NBH * 64];                 // arec_inv iter1
__device__ __align__(16) float g_cfin[NB * NE];                 // final mixed row per batch
__device__ __align__(16) float g_yrow[NB * FIN];                // final projected row per batch

// ---------------- helpers ----------------
__device__ __forceinline__ float red16(float v) {
    v += __shfl_xor_sync(0xffffffffu, v, 8);
    v += __shfl_xor_sync(0xffffffffu, v, 4);
    v += __shfl_xor_sync(0xffffffffu, v, 2);
    v += __shfl_xor_sync(0xffffffffu, v, 1);
    return v;
}
__device__ __forceinline__ float red32(float v) {
    v += __shfl_xor_sync(0xffffffffu, v, 16);
    return red16(v);
}
__device__ __forceinline__ uint32_t pack2(__nv_bfloat16 a, __nv_bfloat16 b) {
    __nv_bfloat162 t = __halves2bfloat162(a, b);
    return *reinterpret_cast<uint32_t*>(&t);
}
__device__ __forceinline__ void ldsm4(uint32_t* r, uint32_t addr) {
    asm volatile("ldmatrix.sync.aligned.m8n8.x4.shared.b16 {%0,%1,%2,%3}, [%4];"
                 : "=r"(r[0]), "=r"(r[1]), "=r"(r[2]), "=r"(r[3]) : "r"(addr));
}
__device__ __forceinline__ void mma_bf16(float* c, const uint32_t* a, uint32_t b0, uint32_t b1) {
    asm volatile(
        "mma.sync.aligned.m16n8k16.row.col.f32.bf16.bf16.f32 "
        "{%0,%1,%2,%3}, {%4,%5,%6,%7}, {%8,%9}, {%0,%1,%2,%3};\n"
        : "+f"(c[0]), "+f"(c[1]), "+f"(c[2]), "+f"(c[3])
        : "r"(a[0]), "r"(a[1]), "r"(a[2]), "r"(a[3]), "r"(b0), "r"(b1));
}

// ---------------- K1: normalize nnmf_w rows (+ transpose) ----------------
__global__ void wnorm_kernel(const float* __restrict__ nnmf_w) {
    int f = threadIdx.x;  // 0..63
    float s = 0.f;
#pragma unroll
    for (int d = 0; d < NDH; ++d) s += nnmf_w[f * NDH + d];
    s = fmaxf(s, EPSV);
    float inv = 1.f / s;
#pragma unroll
    for (int d = 0; d < NDH; ++d) {
        float v = nnmf_w[f * NDH + d] * inv;
        g_Wn[f * NDH + d] = v;
        g_Wt[d * NFH + f] = v;
    }
}

// ---------------- K2a: bf16 split conversion of X and embed_w ----------------
__global__ void __launch_bounds__(256) conv_kernel(const float* __restrict__ X,
                                                   const float* __restrict__ Wm) {
    int i = blockIdx.x * 256 + threadIdx.x;
    int row = i / 192, q = (i % 192) * 4;
    const float* src = (row < 2048) ? X + (size_t)row * 768 + q
                                    : Wm + (size_t)(row - 2048) * 768 + q;
    float4 v = *(const float4*)src;
    float xs[4] = {v.x, v.y, v.z, v.w};
    __nv_bfloat16 hi[4], lo[4];
#pragma unroll
    for (int j = 0; j < 4; ++j) {
        hi[j] = __float2bfloat16(xs[j]);
        lo[j] = __float2bfloat16(xs[j] - __bfloat162float(hi[j]));
    }
    uint2 hv = make_uint2(pack2(hi[0], hi[1]), pack2(hi[2], hi[3]));
    uint2 lv = make_uint2(pack2(lo[0], lo[1]), pack2(lo[2], lo[3]));
    if (row < 2048) {
        __nv_bfloat16* dst = g_Abf + (size_t)row * K3 + q;
        *(uint2*)(dst)        = hv;
        *(uint2*)(dst + 768)  = hv;
        *(uint2*)(dst + 1536) = lv;
    } else {
        __nv_bfloat16* dst = g_Wbf + (size_t)(row - 2048) * K3 + q;
        *(uint2*)(dst)        = hv;
        *(uint2*)(dst + 768)  = lv;
        *(uint2*)(dst + 1536) = hv;
    }
}

// ---------------- K2b: embed GEMM via mma.sync bf16, K=2304 ----------------
__global__ void __launch_bounds__(256) embed_mma_kernel(const float* __restrict__ bias) {
    __shared__ __align__(16) __nv_bfloat16 As[128 * 40];
    __shared__ __align__(16) __nv_bfloat16 Bs[64 * 40];
    int tid = threadIdx.x;
    int bm = blockIdx.y * 128, bn = blockIdx.x * 64;
    int wid = tid >> 5, lane = tid & 31;
    int wm = wid & 3, wn = wid >> 2;

    float c[2][4][4];
#pragma unroll
    for (int mt = 0; mt < 2; ++mt)
#pragma unroll
        for (int nt = 0; nt < 4; ++nt)
#pragma unroll
            for (int r = 0; r < 4; ++r) c[mt][nt][r] = 0.f;

    uint32_t a_base[2], b_base[2];
#pragma unroll
    for (int mt = 0; mt < 2; ++mt) {
        int row = wm * 32 + mt * 16 + (lane & 15);
        int colhalf = lane >> 4;
        a_base[mt] = (uint32_t)__cvta_generic_to_shared(&As[row * 40 + colhalf * 8]);
    }
#pragma unroll
    for (int bt = 0; bt < 2; ++bt) {
        int n = wn * 32 + bt * 16 + ((lane >> 4) << 3) + (lane & 7);
        int khalf = (lane >> 3) & 1;
        b_base[bt] = (uint32_t)__cvta_generic_to_shared(&Bs[n * 40 + khalf * 8]);
    }

    for (int ks = 0; ks < K3 / 32; ++ks) {
        int k0 = ks * 32;
#pragma unroll
        for (int r = 0; r < 2; ++r) {
            int q = tid + r * 256;
            int m = q >> 2, cch = q & 3;
            *(uint4*)&As[m * 40 + cch * 8] =
                *(const uint4*)&g_Abf[(size_t)(bm + m) * K3 + k0 + cch * 8];
        }
        {
            int n = tid >> 2, cch = tid & 3;
            *(uint4*)&Bs[n * 40 + cch * 8] =
                *(const uint4*)&g_Wbf[(size_t)(bn + n) * K3 + k0 + cch * 8];
        }
        __syncthreads();
#pragma unroll
        for (int kh = 0; kh < 2; ++kh) {
            int kk = kh * 16;
            uint32_t a[2][4], b[2][4];
            ldsm4(a[0], a_base[0] + kk * 2);
            ldsm4(a[1], a_base[1] + kk * 2);
            ldsm4(b[0], b_base[0] + kk * 2);
            ldsm4(b[1], b_base[1] + kk * 2);
#pragma unroll
            for (int mt = 0; mt < 2; ++mt)
#pragma unroll
                for (int nt = 0; nt < 4; ++nt)
                    mma_bf16(c[mt][nt], a[mt], b[nt >> 1][(nt & 1) * 2], b[nt >> 1][(nt & 1) * 2 + 1]);
        }
        __syncthreads();
    }

#pragma unroll
    for (int mt = 0; mt < 2; ++mt) {
#pragma unroll
        for (int nt = 0; nt < 4; ++nt) {
            int m0 = bm + wm * 32 + mt * 16 + (lane >> 2);
            int n0 = bn + wn * 32 + nt * 8 + (lane & 3) * 2;
            float2 bv = *(const float2*)&bias[n0];
            float2 o0, o1;
            o0.x = fmaxf(c[mt][nt][0] + bv.x, MIN_POS);
            o0.y = fmaxf(c[mt][nt][1] + bv.y, MIN_POS);
            o1.x = fmaxf(c[mt][nt][2] + bv.x, MIN_POS);
            o1.y = fmaxf(c[mt][nt][3] + bv.y, MIN_POS);
            *(float2*)&g_xe[(size_t)m0 * NE + n0] = o0;
            *(float2*)&g_xe[(size_t)(m0 + 8) * NE + n0] = o1;
        }
    }
}

// ---------------- K3: fused NNMF (2 tokens/thread, 32 tokens/block) + G1 partial ----------------
// dynamic smem: sW[64*64] + sWt[64*64] + s_h[32*64] + s_r[32*64] = 12288 floats = 48KB
__global__ void __launch_bounds__(256) nnmf_kernel() {
    extern __shared__ float sm[];
    float* sW  = sm;             // [f][d], stride 64 (row-wise reads)
    float* sWt = sm + 4096;      // [d][f], stride 64 (row-wise reads)
    float* s_h = sm + 8192;      // [tok][f]
    float* s_r = sm + 10240;     // [tok][d]

    int head = blockIdx.y;
    int tile = blockIdx.x;       // 0..63 (32 tokens each)
    int tid = threadIdx.x;
    int d4 = tid & 15;
    int tg = tid >> 4;
    int t0 = tg * 2, t1 = tg * 2 + 1;
    int tokbase = tile * 32;

    for (int i = tid; i < 4096; i += 256) sW[i] = g_Wn[i];
    for (int i = tid; i < 4096; i += 256) sWt[i] = g_Wt[i];

    // inp: l1norm per token over 64 dims
    float inp0[4], inp1[4];
    {
        const float4 x0 = *(const float4*)&g_xe[(size_t)(tokbase + t0) * NE + head * 64 + d4 * 4];
        const float4 x1 = *(const float4*)&g_xe[(size_t)(tokbase + t1) * NE + head * 64 + d4 * 4];
        float s0 = red16(x0.x + x0.y + x0.z + x0.w);
        float s1 = red16(x1.x + x1.y + x1.z + x1.w);
        float i0 = 1.f / fmaxf(s0, EPSV), i1 = 1.f / fmaxf(s1, EPSV);
        inp0[0] = x0.x * i0; inp0[1] = x0.y * i0; inp0[2] = x0.z * i0; inp0[3] = x0.w * i0;
        inp1[0] = x1.x * i1; inp1[1] = x1.y * i1; inp1[2] = x1.z * i1; inp1[3] = x1.w * i1;
    }
    float hr0[4], hr1[4];
    const float hinit = 1.f / 64.f;
#pragma unroll
    for (int i = 0; i < 4; i++) { hr0[i] = hinit; hr1[i] = hinit; }
    *(float4*)&s_h[t0 * 64 + d4 * 4] = make_float4(hinit, hinit, hinit, hinit);
    *(float4*)&s_h[t1 * 64 + d4 * 4] = make_float4(hinit, hinit, hinit, hinit);
    __syncthreads();

    float rn0[4], rn1[4];

    for (int it = 0; it < 3; ++it) {
        // rec-phase: rec[d] = sum_f h[f] * W[f][d]
        float a0[4] = {}, a1[4] = {};
#pragma unroll 16
        for (int ff = 0; ff < 64; ++ff) {
            float4 w = *(const float4*)&sW[ff * 64 + d4 * 4];
            float h0 = s_h[t0 * 64 + ff], h1 = s_h[t1 * 64 + ff];
            a0[0] += h0 * w.x; a0[1] += h0 * w.y; a0[2] += h0 * w.z; a0[3] += h0 * w.w;
            a1[0] += h1 * w.x; a1[1] += h1 * w.y; a1[2] += h1 * w.z; a1[3] += h1 * w.w;
        }
#pragma unroll
        for (int i = 0; i < 4; i++) { a0[i] = fmaxf(a0[i], MIN_POS); a1[i] = fmaxf(a1[i], MIN_POS); }
        float p0 = red16(a0[0] + a0[1] + a0[2] + a0[3]);
        float p1 = red16(a1[0] + a1[1] + a1[2] + a1[3]);
        float iv0 = 1.f / fmaxf(p0, EPSV), iv1 = 1.f / fmaxf(p1, EPSV);
        float q0[4], q1[4];
#pragma unroll
        for (int i = 0; i < 4; i++) {
            rn0[i] = a0[i] * iv0; rn1[i] = a1[i] * iv1;
            q0[i] = inp0[i] / rn0[i]; q1[i] = inp1[i] / rn1[i];
        }
        *(float4*)&s_r[t0 * 64 + d4 * 4] = make_float4(q0[0], q0[1], q0[2], q0[3]);
        *(float4*)&s_r[t1 * 64 + d4 * 4] = make_float4(q1[0], q1[1], q1[2], q1[3]);
        __syncthreads();

        // t-phase: t[f] = sum_d ratio[d] * Wt[d][f]  (row-wise, conflict-free)
        float b0[4] = {}, b1[4] = {};
#pragma unroll 16
        for (int d = 0; d < 64; ++d) {
            float4 wt = *(const float4*)&sWt[d * 64 + d4 * 4];
            float r0 = s_r[t0 * 64 + d], r1 = s_r[t1 * 64 + d];
            b0[0] += r0 * wt.x; b0[1] += r0 * wt.y; b0[2] += r0 * wt.z; b0[3] += r0 * wt.w;
            b1[0] += r1 * wt.x; b1[1] += r1 * wt.y; b1[2] += r1 * wt.z; b1[3] += r1 * wt.w;
        }
        float hn0[4], hn1[4];
#pragma unroll
        for (int i = 0; i < 4; i++) {
            hn0[i] = fmaxf(hr0[i] * b0[i], MIN_POS);
            hn1[i] = fmaxf(hr1[i] * b1[i], MIN_POS);
        }
        float hs0 = red16(hn0[0] + hn0[1] + hn0[2] + hn0[3]);
        float hs1 = red16(hn1[0] + hn1[1] + hn1[2] + hn1[3]);
        float ih0 = 1.f / fmaxf(hs0, EPSV), ih1 = 1.f / fmaxf(hs1, EPSV);
#pragma unroll
        for (int i = 0; i < 4; i++) { hr0[i] = hn0[i] * ih0; hr1[i] = hn1[i] * ih1; }
        __syncthreads();   // protect s_r readers before overwrite next iter / s_h write
        *(float4*)&s_h[t0 * 64 + d4 * 4] = make_float4(hr0[0], hr0[1], hr0[2], hr0[3]);
        *(float4*)&s_h[t1 * 64 + d4 * 4] = make_float4(hr1[0], hr1[1], hr1[2], hr1[3]);
        __syncthreads();
    }

    // final l1norm of h; write normalized h and hri into smem + gmem
    float hs0 = red16(hr0[0] + hr0[1] + hr0[2] + hr0[3]);
    float hs1 = red16(hr1[0] + hr1[1] + hr1[2] + hr1[3]);
    float ih0 = 1.f / fmaxf(hs0, EPSV), ih1 = 1.f / fmaxf(hs1, EPSV);
    float4 hf0 = make_float4(hr0[0] * ih0, hr0[1] * ih0, hr0[2] * ih0, hr0[3] * ih0);
    float4 hf1 = make_float4(hr1[0] * ih1, hr1[1] * ih1, hr1[2] * ih1, hr1[3] * ih1);
    float4 ri0 = make_float4(rn0[0] * inp0[0], rn0[1] * inp0[1], rn0[2] * inp0[2], rn0[3] * inp0[3]);
    float4 ri1 = make_float4(rn1[0] * inp1[0], rn1[1] * inp1[1], rn1[2] * inp1[2], rn1[3] * inp1[3]);
    *(float4*)&s_h[t0 * 64 + d4 * 4] = hf0;
    *(float4*)&s_h[t1 * 64 + d4 * 4] = hf1;
    *(float4*)&s_r[t0 * 64 + d4 * 4] = ri0;
    *(float4*)&s_r[t1 * 64 + d4 * 4] = ri1;

    int token0 = tokbase + t0, token1 = tokbase + t1;
    int b0i = token0 >> 10, s0i = token0 & 1023;
    int b1i = token1 >> 10, s1i = token1 & 1023;
    size_t base0 = ((size_t)((b0i * NH + head) * NS + s0i)) * 64 + d4 * 4;
    size_t base1 = ((size_t)((b1i * NH + head) * NS + s1i)) * 64 + d4 * 4;
    *(float4*)&g_h[base0] = hf0;
    *(float4*)&g_h[base1] = hf1;
    *(float4*)&g_hri[base0] = ri0;
    *(float4*)&g_hri[base1] = ri1;
    __syncthreads();

    // ---- fused G1 partial: G1[f,d] = sum_o h[o,f]*hri[o,d], cs[f] = sum_o h[o,f] ----
    {
        int f4 = tid & 15, dd4 = tid >> 4;
        float acc[4][4] = {};
        float cs[4] = {};
#pragma unroll 8
        for (int o = 0; o < 32; ++o) {
            float4 hv = *(const float4*)&s_h[o * 64 + f4 * 4];
            float4 rv = *(const float4*)&s_r[o * 64 + dd4 * 4];
            float hvv[4] = {hv.x, hv.y, hv.z, hv.w};
            float rvv[4] = {rv.x, rv.y, rv.z, rv.w};
#pragma unroll
            for (int i = 0; i < 4; i++)
#pragma unroll
                for (int j = 0; j < 4; j++) acc[i][j] += hvv[i] * rvv[j];
            if (dd4 == 0) {
#pragma unroll
                for (int i = 0; i < 4; i++) cs[i] += hvv[i];
            }
        }
        int bb = tile >> 5;               // batch of this tile
        int gsplit = tile & 31;           // 32-token split index within batch
        int bh = bb * NH + head;
        float* gp = g_G1p + ((size_t)(bh * NSG + gsplit)) * 4096;
#pragma unroll
        for (int i = 0; i < 4; i++)
#pragma unroll
            for (int j = 0; j < 4; j++) gp[(f4 * 4 + i) * 64 + dd4 * 4 + j] = acc[i][j];
        if (dd4 == 0) {
#pragma unroll
            for (int i = 0; i < 4; i++) g_csp[(bh * NSG + gsplit) * 64 + f4 * 4 + i] = cs[i];
        }
    }
}

// ---------------- K4b: iterations 0+1 in closed form ----------------
__global__ void __launch_bounds__(256) alpha01_kernel() {
    __shared__ float sW[4096];
    __shared__ float sG[4096];
    __shared__ float s_c0[64], s_ai0[64], s_c1[64];
    int bh = blockIdx.x, tid = threadIdx.x;

    for (int i = tid; i < 4096; i += 256) sW[i] = g_Wn[i];
    const float* gp = g_G1p + (size_t)bh * NSG * 4096;
    for (int i = tid; i < 4096; i += 256) {
        float s = 0.f;
#pragma unroll
        for (int p = 0; p < NSG; ++p) s += gp[p * 4096 + i];
        sG[i] = s;
    }
    if (tid < 64) {
        float s = 0.f;
#pragma unroll
        for (int p = 0; p < NSG; ++p) s += g_csp[(bh * NSG + p) * 64 + tid];
        s_c0[tid] = s;
    }
    __syncthreads();
    if (tid < 64) {
        int d = tid;
        float r = 0.f;
#pragma unroll 8
        for (int f = 0; f < 64; ++f) r += s_c0[f] * sW[f * 64 + d];
        float ai = 1.f / (r + EPSV);
        s_ai0[d] = ai;
        g_aiA[bh * 64 + d] = ai;
    }
    __syncthreads();
    if (tid < 64) {
        int f = tid;
        float c1 = 0.f;
#pragma unroll 8
        for (int dd = 0; dd < 64; ++dd) {
            int d = (dd + f) & 63;
            c1 += sG[f * 64 + d] * s_ai0[d];
        }
        s_c1[f] = c1;
    }
    __syncthreads();
    if (tid < 64) {
        int d = tid;
        float r = 0.f;
#pragma unroll 8
        for (int f = 0; f < 64; ++f) r += s_c1[f] * sW[f * 64 + d];
        g_aiB[bh * 64 + d] = 1.f / (r + EPSV);
    }
}

// ---------------- K4c: pass2 — w01 per token, partial c2, partial M ----------------
__global__ void __launch_bounds__(256) pass2_kernel() {
    __shared__ __align__(16) float s_h[16][68];
    __shared__ __align__(16) float s_r[16][68];
    __shared__ float s_ai0[64], s_ai1[64];
    __shared__ float s_w[16];
    int split = blockIdx.x, bh = blockIdx.y;
    int tid = threadIdx.x;
    int f4 = tid & 15, d4 = tid >> 4;
    int lo = tid >> 4, lq = tid & 15;
    if (tid < 64) s_ai0[tid] = g_aiA[bh * 64 + tid];
    else if (tid < 128) s_ai1[tid - 64] = g_aiB[bh * 64 + tid - 64];

    const float* hb = g_h + ((size_t)bh * NS + split * OSPL) * 64;
    const float* rb = g_hri + ((size_t)bh * NS + split * OSPL) * 64;

    float accM[4][4] = {};
    float cs[4] = {};
    for (int c = 0; c < OSPL / 16; ++c) {
        *(float4*)&s_h[lo][lq * 4] = *(const float4*)&hb[(c * 16 + lo) * 64 + lq * 4];
        *(float4*)&s_r[lo][lq * 4] = *(const float4*)&rb[(c * 16 + lo) * 64 + lq * 4];
        __syncthreads();
        {
            int tt = tid >> 4;
            float4 v = *(const float4*)&s_r[tt][lq * 4];
            int base = lq * 4;
            float u0 = v.x * s_ai0[base] + v.y * s_ai0[base + 1] + v.z * s_ai0[base + 2] + v.w * s_ai0[base + 3];
            float u1 = v.x * s_ai1[base] + v.y * s_ai1[base + 1] + v.z * s_ai1[base + 2] + v.w * s_ai1[base + 3];
            u0 = red16(u0);
            u1 = red16(u1);
            if (lq == 0) s_w[tt] = u0 * u1;
        }
        __syncthreads();
#pragma unroll
        for (int o = 0; o < 16; ++o) {
            float wo = s_w[o];
            float4 hv = *(const float4*)&s_h[o][f4 * 4];
            float4 rv = *(const float4*)&s_r[o][d4 * 4];
            float hw[4] = {hv.x * wo, hv.y * wo, hv.z * wo, hv.w * wo};
            float rvv[4] = {rv.x, rv.y, rv.z, rv.w};
#pragma unroll
            for (int i = 0; i < 4; i++)
#pragma unroll
                for (int j = 0; j < 4; j++) accM[i][j] += hw[i] * rvv[j];
            if (d4 == 0) {
#pragma unroll
                for (int i = 0; i < 4; i++) cs[i] += hw[i];
            }
        }
        __syncthreads();
    }
    float* mp = g_Mp + ((size_t)(bh * NSPLIT + split)) * 4096;
#pragma unroll
    for (int i = 0; i < 4; i++)
#pragma unroll
        for (int j = 0; j < 4; j++) mp[(f4 * 4 + i) * 64 + d4 * 4 + j] = accM[i][j];
    if (d4 == 0) {
#pragma unroll
        for (int i = 0; i < 4; i++) g_c2p[(bh * NSPLIT + split) * 64 + f4 * 4 + i] = cs[i];
    }
}

// ---------------- K4d: ai2 + cfin = (sum M)·ai2 ----------------
__global__ void __launch_bounds__(256) alpha2cfin_kernel() {
    __shared__ float sW[4096];
    __shared__ float s_c2[64];
    __shared__ float s_ai2[64];
    __shared__ float s_p[4][64];
    int bh = blockIdx.x, tid = threadIdx.x;
    for (int i = tid; i < 4096; i += 256) sW[i] = g_Wn[i];
    if (tid < 64) {
        float s = 0.f;
#pragma unroll
        for (int p = 0; p < NSPLIT; ++p) s += g_c2p[(bh * NSPLIT + p) * 64 + tid];
        s_c2[tid] = s;
    }
    __syncthreads();
    if (tid < 64) {
        int d = tid;
        float r = 0.f;
#pragma unroll 8
        for (int f = 0; f < 64; ++f) r += s_c2[f] * sW[f * 64 + d];
        s_ai2[d] = 1.f / (r + EPSV);
    }
    __syncthreads();
    {
        int f = tid & 63, g = tid >> 6;
        const float* mp = g_Mp + (size_t)bh * NSPLIT * 4096;
        float partial = 0.f;
#pragma unroll
        for (int dd = 0; dd < 16; ++dd) {
            int d = g * 16 + dd;
            float mv = 0.f;
#pragma unroll
            for (int p = 0; p < NSPLIT; ++p) mv += mp[p * 4096 + f * 64 + d];
            partial += mv * s_ai2[d];
        }
        s_p[g][f] = partial;
    }
    __syncthreads();
    if (tid < 64) {
        int b = bh / NH, head = bh % NH;
        g_cfin[b * NE + head * 64 + tid] = s_p[0][tid] + s_p[1][tid] + s_p[2][tid] + s_p[3][tid];
    }
}

// ---------------- K5: out projection of the 2 unique rows ----------------
__global__ void __launch_bounds__(256) outrow_kernel(const float* __restrict__ out_w,
                                                     const float* __restrict__ out_b) {
    int b = blockIdx.y;
    int warp = threadIdx.x >> 5, lane = threadIdx.x & 31;
    int j = blockIdx.x * 8 + warp;
    const float* c = g_cfin + b * NE;
    const float* wrow = out_w + (size_t)j * NE;
    float acc = 0.f;
    for (int e = lane; e < NE; e += 32) acc += c[e] * wrow[e];
    acc = red32(acc);
    if (lane == 0) g_yrow[b * FIN + j] = acc + out_b[j];
}

// ---------------- K6: broadcast rows to all positions ----------------
__global__ void __launch_bounds__(256) bcast_kernel(float* __restrict__ out) {
    int idx = blockIdx.x * 256 + threadIdx.x;
    const int per_row = FIN / 4;
    int j4 = idx % per_row;
    int bs = idx / per_row;
    int b = bs >> 10;
    float4 v = ((const float4*)(g_yrow + b * FIN))[j4];
    ((float4*)out)[idx] = v;
}

// ---------------- launch ----------------
extern "C" void kernel_launch(void* const* d_in, const int* in_sizes, int n_in,
                              void* d_out, int out_size) {
    const float* x       = (const float*)d_in[0];
    const float* embed_w = (const float*)d_in[1];
    const float* embed_b = (const float*)d_in[2];
    const float* nnmf_w  = (const float*)d_in[3];
    const float* out_w   = (const float*)d_in[4];
    const float* out_b   = (const float*)d_in[5];
    float* out = (float*)d_out;

    static bool attr_set = false;
    if (!attr_set) {
        cudaFuncSetAttribute(nnmf_kernel, cudaFuncAttributeMaxDynamicSharedMemorySize, 49152);
        attr_set = true;
    }

    wnorm_kernel<<<1, 64>>>(nnmf_w);
    conv_kernel<<<2112, 256>>>(x, embed_w);
    embed_mma_kernel<<<dim3(NE / 64, (NB * NS) / 128), 256>>>(embed_b);
    nnmf_kernel<<<dim3((NB * NS) / 32, NH), 256, 49152>>>();
    alpha01_kernel<<<NBH, 256>>>();
    pass2_kernel<<<dim3(NSPLIT, NBH), 256>>>();
    alpha2cfin_kernel<<<NBH, 256>>>();
    outrow_kernel<<<dim3(NE / 8, NB), 256>>>(out_w, out_b);
    bcast_kernel<<<(NB * NS * (FIN / 4)) / 256, 256>>>(out);
}

// round 6
// speedup vs baseline: 1.2713x; 1.0015x over previous
#include <cuda_runtime.h>
#include <cuda_bf16.h>
#include <cstdint>

#define NB 2
#define NS 1024
#define FIN 768
#define NE 768
#define NH 12
#define NBH (NB * NH)
#define NDH 64
#define NFH 64
#define NSPLIT 16
#define OSPL (NS / NSPLIT)   // 64 tokens per split (pass2)
#define NSG 32               // g1 splits (32 tokens each, fused in nnmf)
#define MIN_POS 1e-6f
#define EPSV 1e-20f
#define K3 2304              // tripled K for bf16-split GEMM
#define TSTR 68              // padded token-row stride in nnmf smem
#define NN_SMEM_BYTES ((4096 + 4096 + 32 * TSTR * 2) * 4)

// ---------------- scratch (device globals; no allocation) ----------------
__device__ __align__(16) float g_Wn[NFH * NDH];                 // normalized W [f][d]
__device__ __align__(16) float g_Wt[NDH * NFH];                 // transposed normalized W [d][f]
__device__ __align__(16) __nv_bfloat16 g_Abf[2048 * K3];        // [hi | hi | lo] of X
__device__ __align__(16) __nv_bfloat16 g_Wbf[768 * K3];         // [hi | lo | hi] of embed_w
__device__ __align__(16) float g_xe[NB * NS * NE];              // clipped embed output
__device__ __align__(16) float g_h[NBH * NS * NFH];             // h   [bh][s][f]
__device__ __align__(16) float g_hri[NBH * NS * NDH];           // rec*inp [bh][s][d]
__device__ __align__(16) float g_G1p[NBH * NSG * 64 * 64];      // partial h^T*hri
__device__ __align__(16) float g_Mp[NBH * NSPLIT * 64 * 64];    // partial h^T*(w01*hri)
__device__ __align__(16) float g_csp[NBH * NSG * 64];           // partial colsum(h)
__device__ __align__(16) float g_c2p[NBH * NSPLIT * 64];        // partial c2
__device__ __align__(16) float g_aiA[NBH * 64];                 // arec_inv iter0
__device__ __align__(16) float g_aiB[NBH * 64];                 // arec_inv iter1
__device__ __align__(16) float g_cfin[NB * NE];                 // final mixed row per batch
__device__ __align__(16) float g_yrow[NB * FIN];                // final projected row per batch

// ---------------- helpers ----------------
__device__ __forceinline__ float red16(float v) {
    v += __shfl_xor_sync(0xffffffffu, v, 8);
    v += __shfl_xor_sync(0xffffffffu, v, 4);
    v += __shfl_xor_sync(0xffffffffu, v, 2);
    v += __shfl_xor_sync(0xffffffffu, v, 1);
    return v;
}
__device__ __forceinline__ float red32(float v) {
    v += __shfl_xor_sync(0xffffffffu, v, 16);
    return red16(v);
}
__device__ __forceinline__ uint32_t pack2(__nv_bfloat16 a, __nv_bfloat16 b) {
    __nv_bfloat162 t = __halves2bfloat162(a, b);
    return *reinterpret_cast<uint32_t*>(&t);
}
__device__ __forceinline__ void ldsm4(uint32_t* r, uint32_t addr) {
    asm volatile("ldmatrix.sync.aligned.m8n8.x4.shared.b16 {%0,%1,%2,%3}, [%4];"
                 : "=r"(r[0]), "=r"(r[1]), "=r"(r[2]), "=r"(r[3]) : "r"(addr));
}
__device__ __forceinline__ void mma_bf16(float* c, const uint32_t* a, uint32_t b0, uint32_t b1) {
    asm volatile(
        "mma.sync.aligned.m16n8k16.row.col.f32.bf16.bf16.f32 "
        "{%0,%1,%2,%3}, {%4,%5,%6,%7}, {%8,%9}, {%0,%1,%2,%3};\n"
        : "+f"(c[0]), "+f"(c[1]), "+f"(c[2]), "+f"(c[3])
        : "r"(a[0]), "r"(a[1]), "r"(a[2]), "r"(a[3]), "r"(b0), "r"(b1));
}

// ---------------- K1: normalize nnmf_w rows (+ transpose) ----------------
__global__ void wnorm_kernel(const float* __restrict__ nnmf_w) {
    int f = threadIdx.x;  // 0..63
    float s = 0.f;
#pragma unroll
    for (int d = 0; d < NDH; ++d) s += nnmf_w[f * NDH + d];
    s = fmaxf(s, EPSV);
    float inv = 1.f / s;
#pragma unroll
    for (int d = 0; d < NDH; ++d) {
        float v = nnmf_w[f * NDH + d] * inv;
        g_Wn[f * NDH + d] = v;
        g_Wt[d * NFH + f] = v;
    }
}

// ---------------- K2a: bf16 split conversion of X and embed_w ----------------
__global__ void __launch_bounds__(256) conv_kernel(const float* __restrict__ X,
                                                   const float* __restrict__ Wm) {
    int i = blockIdx.x * 256 + threadIdx.x;
    int row = i / 192, q = (i % 192) * 4;
    const float* src = (row < 2048) ? X + (size_t)row * 768 + q
                                    : Wm + (size_t)(row - 2048) * 768 + q;
    float4 v = *(const float4*)src;
    float xs[4] = {v.x, v.y, v.z, v.w};
    __nv_bfloat16 hi[4], lo[4];
#pragma unroll
    for (int j = 0; j < 4; ++j) {
        hi[j] = __float2bfloat16(xs[j]);
        lo[j] = __float2bfloat16(xs[j] - __bfloat162float(hi[j]));
    }
    uint2 hv = make_uint2(pack2(hi[0], hi[1]), pack2(hi[2], hi[3]));
    uint2 lv = make_uint2(pack2(lo[0], lo[1]), pack2(lo[2], lo[3]));
    if (row < 2048) {
        __nv_bfloat16* dst = g_Abf + (size_t)row * K3 + q;
        *(uint2*)(dst)        = hv;
        *(uint2*)(dst + 768)  = hv;
        *(uint2*)(dst + 1536) = lv;
    } else {
        __nv_bfloat16* dst = g_Wbf + (size_t)(row - 2048) * K3 + q;
        *(uint2*)(dst)        = hv;
        *(uint2*)(dst + 768)  = lv;
        *(uint2*)(dst + 1536) = hv;
    }
}

// ---------------- K2b: embed GEMM via mma.sync bf16, K=2304 ----------------
__global__ void __launch_bounds__(256) embed_mma_kernel(const float* __restrict__ bias) {
    __shared__ __align__(16) __nv_bfloat16 As[128 * 40];
    __shared__ __align__(16) __nv_bfloat16 Bs[64 * 40];
    int tid = threadIdx.x;
    int bm = blockIdx.y * 128, bn = blockIdx.x * 64;
    int wid = tid >> 5, lane = tid & 31;
    int wm = wid & 3, wn = wid >> 2;

    float c[2][4][4];
#pragma unroll
    for (int mt = 0; mt < 2; ++mt)
#pragma unroll
        for (int nt = 0; nt < 4; ++nt)
#pragma unroll
            for (int r = 0; r < 4; ++r) c[mt][nt][r] = 0.f;

    uint32_t a_base[2], b_base[2];
#pragma unroll
    for (int mt = 0; mt < 2; ++mt) {
        int row = wm * 32 + mt * 16 + (lane & 15);
        int colhalf = lane >> 4;
        a_base[mt] = (uint32_t)__cvta_generic_to_shared(&As[row * 40 + colhalf * 8]);
    }
#pragma unroll
    for (int bt = 0; bt < 2; ++bt) {
        int n = wn * 32 + bt * 16 + ((lane >> 4) << 3) + (lane & 7);
        int khalf = (lane >> 3) & 1;
        b_base[bt] = (uint32_t)__cvta_generic_to_shared(&Bs[n * 40 + khalf * 8]);
    }

    for (int ks = 0; ks < K3 / 32; ++ks) {
        int k0 = ks * 32;
#pragma unroll
        for (int r = 0; r < 2; ++r) {
            int q = tid + r * 256;
            int m = q >> 2, cch = q & 3;
            *(uint4*)&As[m * 40 + cch * 8] =
                *(const uint4*)&g_Abf[(size_t)(bm + m) * K3 + k0 + cch * 8];
        }
        {
            int n = tid >> 2, cch = tid & 3;
            *(uint4*)&Bs[n * 40 + cch * 8] =
                *(const uint4*)&g_Wbf[(size_t)(bn + n) * K3 + k0 + cch * 8];
        }
        __syncthreads();
#pragma unroll
        for (int kh = 0; kh < 2; ++kh) {
            int kk = kh * 16;
            uint32_t a[2][4], b[2][4];
            ldsm4(a[0], a_base[0] + kk * 2);
            ldsm4(a[1], a_base[1] + kk * 2);
            ldsm4(b[0], b_base[0] + kk * 2);
            ldsm4(b[1], b_base[1] + kk * 2);
#pragma unroll
            for (int mt = 0; mt < 2; ++mt)
#pragma unroll
                for (int nt = 0; nt < 4; ++nt)
                    mma_bf16(c[mt][nt], a[mt], b[nt >> 1][(nt & 1) * 2], b[nt >> 1][(nt & 1) * 2 + 1]);
        }
        __syncthreads();
    }

#pragma unroll
    for (int mt = 0; mt < 2; ++mt) {
#pragma unroll
        for (int nt = 0; nt < 4; ++nt) {
            int m0 = bm + wm * 32 + mt * 16 + (lane >> 2);
            int n0 = bn + wn * 32 + nt * 8 + (lane & 3) * 2;
            float2 bv = *(const float2*)&bias[n0];
            float2 o0, o1;
            o0.x = fmaxf(c[mt][nt][0] + bv.x, MIN_POS);
            o0.y = fmaxf(c[mt][nt][1] + bv.y, MIN_POS);
            o1.x = fmaxf(c[mt][nt][2] + bv.x, MIN_POS);
            o1.y = fmaxf(c[mt][nt][3] + bv.y, MIN_POS);
            *(float2*)&g_xe[(size_t)m0 * NE + n0] = o0;
            *(float2*)&g_xe[(size_t)(m0 + 8) * NE + n0] = o1;
        }
    }
}

// ---------------- K3: fused NNMF (2 tokens/thread, 32 tokens/block) + G1 partial ----------------
// dynamic smem: sW[4096] + sWt[4096] + s_h[32*TSTR] + s_r[32*TSTR]
__global__ void __launch_bounds__(256) nnmf_kernel() {
    extern __shared__ float sm[];
    float* sW  = sm;                    // [f][d], stride 64
    float* sWt = sm + 4096;             // [d][f], stride 64
    float* s_h = sm + 8192;             // [tok][f], stride TSTR (padded)
    float* s_r = sm + 8192 + 32 * TSTR; // [tok][d], stride TSTR (padded)

    int head = blockIdx.y;
    int tile = blockIdx.x;       // 0..63 (32 tokens each)
    int tid = threadIdx.x;
    int d4 = tid & 15;
    int tg = tid >> 4;
    int t0 = tg * 2, t1 = tg * 2 + 1;
    int tokbase = tile * 32;

    for (int i = tid; i < 4096; i += 256) sW[i] = g_Wn[i];
    for (int i = tid; i < 4096; i += 256) sWt[i] = g_Wt[i];

    // inp: l1norm per token over 64 dims
    float inp0[4], inp1[4];
    {
        const float4 x0 = *(const float4*)&g_xe[(size_t)(tokbase + t0) * NE + head * 64 + d4 * 4];
        const float4 x1 = *(const float4*)&g_xe[(size_t)(tokbase + t1) * NE + head * 64 + d4 * 4];
        float s0 = red16(x0.x + x0.y + x0.z + x0.w);
        float s1 = red16(x1.x + x1.y + x1.z + x1.w);
        float i0 = 1.f / fmaxf(s0, EPSV), i1 = 1.f / fmaxf(s1, EPSV);
        inp0[0] = x0.x * i0; inp0[1] = x0.y * i0; inp0[2] = x0.z * i0; inp0[3] = x0.w * i0;
        inp1[0] = x1.x * i1; inp1[1] = x1.y * i1; inp1[2] = x1.z * i1; inp1[3] = x1.w * i1;
    }
    float hr0[4], hr1[4];
    const float hinit = 1.f / 64.f;
#pragma unroll
    for (int i = 0; i < 4; i++) { hr0[i] = hinit; hr1[i] = hinit; }
    *(float4*)&s_h[t0 * TSTR + d4 * 4] = make_float4(hinit, hinit, hinit, hinit);
    *(float4*)&s_h[t1 * TSTR + d4 * 4] = make_float4(hinit, hinit, hinit, hinit);
    __syncthreads();

    float rn0[4], rn1[4];

    for (int it = 0; it < 3; ++it) {
        // rec-phase: rec[d] = sum_f h[f] * W[f][d]
        float a0[4] = {}, a1[4] = {};
#pragma unroll 16
        for (int ff = 0; ff < 64; ++ff) {
            float4 w = *(const float4*)&sW[ff * 64 + d4 * 4];
            float h0 = s_h[t0 * TSTR + ff], h1 = s_h[t1 * TSTR + ff];
            a0[0] += h0 * w.x; a0[1] += h0 * w.y; a0[2] += h0 * w.z; a0[3] += h0 * w.w;
            a1[0] += h1 * w.x; a1[1] += h1 * w.y; a1[2] += h1 * w.z; a1[3] += h1 * w.w;
        }
#pragma unroll
        for (int i = 0; i < 4; i++) { a0[i] = fmaxf(a0[i], MIN_POS); a1[i] = fmaxf(a1[i], MIN_POS); }
        float p0 = red16(a0[0] + a0[1] + a0[2] + a0[3]);
        float p1 = red16(a1[0] + a1[1] + a1[2] + a1[3]);
        float iv0 = 1.f / fmaxf(p0, EPSV), iv1 = 1.f / fmaxf(p1, EPSV);
        float q0[4], q1[4];
#pragma unroll
        for (int i = 0; i < 4; i++) {
            rn0[i] = a0[i] * iv0; rn1[i] = a1[i] * iv1;
            q0[i] = inp0[i] / rn0[i]; q1[i] = inp1[i] / rn1[i];
        }
        *(float4*)&s_r[t0 * TSTR + d4 * 4] = make_float4(q0[0], q0[1], q0[2], q0[3]);
        *(float4*)&s_r[t1 * TSTR + d4 * 4] = make_float4(q1[0], q1[1], q1[2], q1[3]);
        __syncthreads();

        // t-phase: t[f] = sum_d ratio[d] * Wt[d][f]
        float b0[4] = {}, b1[4] = {};
#pragma unroll 16
        for (int d = 0; d < 64; ++d) {
            float4 wt = *(const float4*)&sWt[d * 64 + d4 * 4];
            float r0 = s_r[t0 * TSTR + d], r1 = s_r[t1 * TSTR + d];
            b0[0] += r0 * wt.x; b0[1] += r0 * wt.y; b0[2] += r0 * wt.z; b0[3] += r0 * wt.w;
            b1[0] += r1 * wt.x; b1[1] += r1 * wt.y; b1[2] += r1 * wt.z; b1[3] += r1 * wt.w;
        }
        float hn0[4], hn1[4];
#pragma unroll
        for (int i = 0; i < 4; i++) {
            hn0[i] = fmaxf(hr0[i] * b0[i], MIN_POS);
            hn1[i] = fmaxf(hr1[i] * b1[i], MIN_POS);
        }
        float hs0 = red16(hn0[0] + hn0[1] + hn0[2] + hn0[3]);
        float hs1 = red16(hn1[0] + hn1[1] + hn1[2] + hn1[3]);
        float ih0 = 1.f / fmaxf(hs0, EPSV), ih1 = 1.f / fmaxf(hs1, EPSV);
#pragma unroll
        for (int i = 0; i < 4; i++) { hr0[i] = hn0[i] * ih0; hr1[i] = hn1[i] * ih1; }
        // NOTE: no barrier needed here — s_h reads all completed before sync after
        // ratio-write; s_h writes don't alias s_r. The following sync orders both
        // the new s_h for next rec-phase and s_r reuse.
        *(float4*)&s_h[t0 * TSTR + d4 * 4] = make_float4(hr0[0], hr0[1], hr0[2], hr0[3]);
        *(float4*)&s_h[t1 * TSTR + d4 * 4] = make_float4(hr1[0], hr1[1], hr1[2], hr1[3]);
        __syncthreads();
    }

    // final l1norm of h; write normalized h and hri into smem + gmem
    float hs0 = red16(hr0[0] + hr0[1] + hr0[2] + hr0[3]);
    float hs1 = red16(hr1[0] + hr1[1] + hr1[2] + hr1[3]);
    float ih0 = 1.f / fmaxf(hs0, EPSV), ih1 = 1.f / fmaxf(hs1, EPSV);
    float4 hf0 = make_float4(hr0[0] * ih0, hr0[1] * ih0, hr0[2] * ih0, hr0[3] * ih0);
    float4 hf1 = make_float4(hr1[0] * ih1, hr1[1] * ih1, hr1[2] * ih1, hr1[3] * ih1);
    float4 ri0 = make_float4(rn0[0] * inp0[0], rn0[1] * inp0[1], rn0[2] * inp0[2], rn0[3] * inp0[3]);
    float4 ri1 = make_float4(rn1[0] * inp1[0], rn1[1] * inp1[1], rn1[2] * inp1[2], rn1[3] * inp1[3]);
    *(float4*)&s_h[t0 * TSTR + d4 * 4] = hf0;
    *(float4*)&s_h[t1 * TSTR + d4 * 4] = hf1;
    *(float4*)&s_r[t0 * TSTR + d4 * 4] = ri0;
    *(float4*)&s_r[t1 * TSTR + d4 * 4] = ri1;

    int token0 = tokbase + t0, token1 = tokbase + t1;
    int b0i = token0 >> 10, s0i = token0 & 1023;
    int b1i = token1 >> 10, s1i = token1 & 1023;
    size_t base0 = ((size_t)((b0i * NH + head) * NS + s0i)) * 64 + d4 * 4;
    size_t base1 = ((size_t)((b1i * NH + head) * NS + s1i)) * 64 + d4 * 4;
    *(float4*)&g_h[base0] = hf0;
    *(float4*)&g_h[base1] = hf1;
    *(float4*)&g_hri[base0] = ri0;
    *(float4*)&g_hri[base1] = ri1;
    __syncthreads();

    // ---- fused G1 partial: G1[f,d] = sum_o h[o,f]*hri[o,d], cs[f] = sum_o h[o,f] ----
    {
        int f4 = tid & 15, dd4 = tid >> 4;
        float acc[4][4] = {};
        float cs[4] = {};
#pragma unroll 8
        for (int o = 0; o < 32; ++o) {
            float4 hv = *(const float4*)&s_h[o * TSTR + f4 * 4];
            float4 rv = *(const float4*)&s_r[o * TSTR + dd4 * 4];
            float hvv[4] = {hv.x, hv.y, hv.z, hv.w};
            float rvv[4] = {rv.x, rv.y, rv.z, rv.w};
#pragma unroll
            for (int i = 0; i < 4; i++)
#pragma unroll
                for (int j = 0; j < 4; j++) acc[i][j] += hvv[i] * rvv[j];
            if (dd4 == 0) {
#pragma unroll
                for (int i = 0; i < 4; i++) cs[i] += hvv[i];
            }
        }
        int bb = tile >> 5;
        int gsplit = tile & 31;
        int bh = bb * NH + head;
        float* gp = g_G1p + ((size_t)(bh * NSG + gsplit)) * 4096;
#pragma unroll
        for (int i = 0; i < 4; i++)
#pragma unroll
            for (int j = 0; j < 4; j++) gp[(f4 * 4 + i) * 64 + dd4 * 4 + j] = acc[i][j];
        if (dd4 == 0) {
#pragma unroll
            for (int i = 0; i < 4; i++) g_csp[(bh * NSG + gsplit) * 64 + f4 * 4 + i] = cs[i];
        }
    }
}

// ---------------- K4b: iterations 0+1 in closed form ----------------
__global__ void __launch_bounds__(256) alpha01_kernel() {
    __shared__ float sW[4096];
    __shared__ float sG[4096];
    __shared__ float s_c0[64], s_ai0[64], s_c1[64];
    int bh = blockIdx.x, tid = threadIdx.x;

    for (int i = tid; i < 4096; i += 256) sW[i] = g_Wn[i];
    const float* gp = g_G1p + (size_t)bh * NSG * 4096;
    for (int i = tid; i < 4096; i += 256) {
        float s = 0.f;
#pragma unroll
        for (int p = 0; p < NSG; ++p) s += gp[p * 4096 + i];
        sG[i] = s;
    }
    if (tid < 64) {
        float s = 0.f;
#pragma unroll
        for (int p = 0; p < NSG; ++p) s += g_csp[(bh * NSG + p) * 64 + tid];
        s_c0[tid] = s;
    }
    __syncthreads();
    if (tid < 64) {
        int d = tid;
        float r = 0.f;
#pragma unroll 8
        for (int f = 0; f < 64; ++f) r += s_c0[f] * sW[f * 64 + d];
        float ai = 1.f / (r + EPSV);
        s_ai0[d] = ai;
        g_aiA[bh * 64 + d] = ai;
    }
    __syncthreads();
    if (tid < 64) {
        int f = tid;
        float c1 = 0.f;
#pragma unroll 8
        for (int dd = 0; dd < 64; ++dd) {
            int d = (dd + f) & 63;
            c1 += sG[f * 64 + d] * s_ai0[d];
        }
        s_c1[f] = c1;
    }
    __syncthreads();
    if (tid < 64) {
        int d = tid;
        float r = 0.f;
#pragma unroll 8
        for (int f = 0; f < 64; ++f) r += s_c1[f] * sW[f * 64 + d];
        g_aiB[bh * 64 + d] = 1.f / (r + EPSV);
    }
}

// ---------------- K4c: pass2 — w01 per token, partial c2, partial M ----------------
__global__ void __launch_bounds__(256) pass2_kernel() {
    __shared__ __align__(16) float s_h[16][68];
    __shared__ __align__(16) float s_r[16][68];
    __shared__ float s_ai0[64], s_ai1[64];
    __shared__ float s_w[16];
    int split = blockIdx.x, bh = blockIdx.y;
    int tid = threadIdx.x;
    int f4 = tid & 15, d4 = tid >> 4;
    int lo = tid >> 4, lq = tid & 15;
    if (tid < 64) s_ai0[tid] = g_aiA[bh * 64 + tid];
    else if (tid < 128) s_ai1[tid - 64] = g_aiB[bh * 64 + tid - 64];

    const float* hb = g_h + ((size_t)bh * NS + split * OSPL) * 64;
    const float* rb = g_hri + ((size_t)bh * NS + split * OSPL) * 64;

    float accM[4][4] = {};
    float cs[4] = {};
    for (int c = 0; c < OSPL / 16; ++c) {
        *(float4*)&s_h[lo][lq * 4] = *(const float4*)&hb[(c * 16 + lo) * 64 + lq * 4];
        *(float4*)&s_r[lo][lq * 4] = *(const float4*)&rb[(c * 16 + lo) * 64 + lq * 4];
        __syncthreads();
        {
            int tt = tid >> 4;
            float4 v = *(const float4*)&s_r[tt][lq * 4];
            int base = lq * 4;
            float u0 = v.x * s_ai0[base] + v.y * s_ai0[base + 1] + v.z * s_ai0[base + 2] + v.w * s_ai0[base + 3];
            float u1 = v.x * s_ai1[base] + v.y * s_ai1[base + 1] + v.z * s_ai1[base + 2] + v.w * s_ai1[base + 3];
            u0 = red16(u0);
            u1 = red16(u1);
            if (lq == 0) s_w[tt] = u0 * u1;
        }
        __syncthreads();
#pragma unroll
        for (int o = 0; o < 16; ++o) {
            float wo = s_w[o];
            float4 hv = *(const float4*)&s_h[o][f4 * 4];
            float4 rv = *(const float4*)&s_r[o][d4 * 4];
            float hw[4] = {hv.x * wo, hv.y * wo, hv.z * wo, hv.w * wo};
            float rvv[4] = {rv.x, rv.y, rv.z, rv.w};
#pragma unroll
            for (int i = 0; i < 4; i++)
#pragma unroll
                for (int j = 0; j < 4; j++) accM[i][j] += hw[i] * rvv[j];
            if (d4 == 0) {
#pragma unroll
                for (int i = 0; i < 4; i++) cs[i] += hw[i];
            }
        }
        __syncthreads();
    }
    float* mp = g_Mp + ((size_t)(bh * NSPLIT + split)) * 4096;
#pragma unroll
    for (int i = 0; i < 4; i++)
#pragma unroll
        for (int j = 0; j < 4; j++) mp[(f4 * 4 + i) * 64 + d4 * 4 + j] = accM[i][j];
    if (d4 == 0) {
#pragma unroll
        for (int i = 0; i < 4; i++) g_c2p[(bh * NSPLIT + split) * 64 + f4 * 4 + i] = cs[i];
    }
}

// ---------------- K4d: ai2 + cfin = (sum M)·ai2 ----------------
__global__ void __launch_bounds__(256) alpha2cfin_kernel() {
    __shared__ float sW[4096];
    __shared__ float s_c2[64];
    __shared__ float s_ai2[64];
    __shared__ float s_p[4][64];
    int bh = blockIdx.x, tid = threadIdx.x;
    for (int i = tid; i < 4096; i += 256) sW[i] = g_Wn[i];
    if (tid < 64) {
        float s = 0.f;
#pragma unroll
        for (int p = 0; p < NSPLIT; ++p) s += g_c2p[(bh * NSPLIT + p) * 64 + tid];
        s_c2[tid] = s;
    }
    __syncthreads();
    if (tid < 64) {
        int d = tid;
        float r = 0.f;
#pragma unroll 8
        for (int f = 0; f < 64; ++f) r += s_c2[f] * sW[f * 64 + d];
        s_ai2[d] = 1.f / (r + EPSV);
    }
    __syncthreads();
    {
        int f = tid & 63, g = tid >> 6;
        const float* mp = g_Mp + (size_t)bh * NSPLIT * 4096;
        float partial = 0.f;
#pragma unroll
        for (int dd = 0; dd < 16; ++dd) {
            int d = g * 16 + dd;
            float mv = 0.f;
#pragma unroll
            for (int p = 0; p < NSPLIT; ++p) mv += mp[p * 4096 + f * 64 + d];
            partial += mv * s_ai2[d];
        }
        s_p[g][f] = partial;
    }
    __syncthreads();
    if (tid < 64) {
        int b = bh / NH, head = bh % NH;
        g_cfin[b * NE + head * 64 + tid] = s_p[0][tid] + s_p[1][tid] + s_p[2][tid] + s_p[3][tid];
    }
}

// ---------------- K5: out projection of the 2 unique rows ----------------
__global__ void __launch_bounds__(256) outrow_kernel(const float* __restrict__ out_w,
                                                     const float* __restrict__ out_b) {
    int b = blockIdx.y;
    int warp = threadIdx.x >> 5, lane = threadIdx.x & 31;
    int j = blockIdx.x * 8 + warp;
    const float* c = g_cfin + b * NE;
    const float* wrow = out_w + (size_t)j * NE;
    float acc = 0.f;
    for (int e = lane; e < NE; e += 32) acc += c[e] * wrow[e];
    acc = red32(acc);
    if (lane == 0) g_yrow[b * FIN + j] = acc + out_b[j];
}

// ---------------- K6: broadcast rows to all positions ----------------
__global__ void __launch_bounds__(256) bcast_kernel(float* __restrict__ out) {
    int idx = blockIdx.x * 256 + threadIdx.x;
    const int per_row = FIN / 4;
    int j4 = idx % per_row;
    int bs = idx / per_row;
    int b = bs >> 10;
    float4 v = ((const float4*)(g_yrow + b * FIN))[j4];
    ((float4*)out)[idx] = v;
}

// ---------------- launch ----------------
extern "C" void kernel_launch(void* const* d_in, const int* in_sizes, int n_in,
                              void* d_out, int out_size) {
    const float* x       = (const float*)d_in[0];
    const float* embed_w = (const float*)d_in[1];
    const float* embed_b = (const float*)d_in[2];
    const float* nnmf_w  = (const float*)d_in[3];
    const float* out_w   = (const float*)d_in[4];
    const float* out_b   = (const float*)d_in[5];
    float* out = (float*)d_out;

    static bool attr_set = false;
    if (!attr_set) {
        cudaFuncSetAttribute(nnmf_kernel, cudaFuncAttributeMaxDynamicSharedMemorySize,
                             NN_SMEM_BYTES);
        attr_set = true;
    }

    wnorm_kernel<<<1, 64>>>(nnmf_w);
    conv_kernel<<<2112, 256>>>(x, embed_w);
    embed_mma_kernel<<<dim3(NE / 64, (NB * NS) / 128), 256>>>(embed_b);
    nnmf_kernel<<<dim3((NB * NS) / 32, NH), 256, NN_SMEM_BYTES>>>();
    alpha01_kernel<<<NBH, 256>>>();
    pass2_kernel<<<dim3(NSPLIT, NBH), 256>>>();
    alpha2cfin_kernel<<<NBH, 256>>>();
    outrow_kernel<<<dim3(NE / 8, NB), 256>>>(out_w, out_b);
    bcast_kernel<<<(NB * NS * (FIN / 4)) / 256, 256>>>(out);
}

// round 7
// speedup vs baseline: 1.2736x; 1.0019x over previous
#include <cuda_runtime.h>
#include <cuda_bf16.h>
#include <cstdint>

#define NB 2
#define NS 1024
#define FIN 768
#define NE 768
#define NH 12
#define NBH (NB * NH)
#define NDH 64
#define NFH 64
#define NSPLIT 16
#define OSPL (NS / NSPLIT)   // 64 tokens per split (pass2)
#define NSG 32               // g1 splits (32 tokens each, fused in nnmf)
#define MIN_POS 1e-6f
#define EPSV 1e-20f
#define K3 2304              // tripled K for bf16-split GEMM
#define HSTR 36              // feature-major row stride (floats) in nnmf smem
#define TSTR 68              // token-major row stride for G1 tail
#define NN_SMEM_BYTES ((4096 + 4096 + 64 * HSTR * 2) * 4)

// ---------------- scratch (device globals; no allocation) ----------------
__device__ __align__(16) float g_Wn[NFH * NDH];                 // normalized W [f][d]
__device__ __align__(16) float g_Wt[NDH * NFH];                 // transposed normalized W [d][f]
__device__ __align__(16) __nv_bfloat16 g_Abf[2048 * K3];        // [hi | hi | lo] of X
__device__ __align__(16) __nv_bfloat16 g_Wbf[768 * K3];         // [hi | lo | hi] of embed_w
__device__ __align__(16) float g_xe[NB * NS * NE];              // clipped embed output
__device__ __align__(16) float g_h[NBH * NS * NFH];             // h   [bh][s][f]
__device__ __align__(16) float g_hri[NBH * NS * NDH];           // rec*inp [bh][s][d]
__device__ __align__(16) float g_G1p[NBH * NSG * 64 * 64];      // partial h^T*hri
__device__ __align__(16) float g_Mp[NBH * NSPLIT * 64 * 64];    // partial h^T*(w01*hri)
__device__ __align__(16) float g_csp[NBH * NSG * 64];           // partial colsum(h)
__device__ __align__(16) float g_c2p[NBH * NSPLIT * 64];        // partial c2
__device__ __align__(16) float g_aiA[NBH * 64];                 // arec_inv iter0
__device__ __align__(16) float g_aiB[NBH * 64];                 // arec_inv iter1
__device__ __align__(16) float g_cfin[NB * NE];                 // final mixed row per batch
__device__ __align__(16) float g_yrow[NB * FIN];                // final projected row per batch

// ---------------- helpers ----------------
__device__ __forceinline__ float red16(float v) {
    v += __shfl_xor_sync(0xffffffffu, v, 8);
    v += __shfl_xor_sync(0xffffffffu, v, 4);
    v += __shfl_xor_sync(0xffffffffu, v, 2);
    v += __shfl_xor_sync(0xffffffffu, v, 1);
    return v;
}
__device__ __forceinline__ float red32(float v) {
    v += __shfl_xor_sync(0xffffffffu, v, 16);
    return red16(v);
}
__device__ __forceinline__ uint32_t pack2(__nv_bfloat16 a, __nv_bfloat16 b) {
    __nv_bfloat162 t = __halves2bfloat162(a, b);
    return *reinterpret_cast<uint32_t*>(&t);
}
__device__ __forceinline__ void ldsm4(uint32_t* r, uint32_t addr) {
    asm volatile("ldmatrix.sync.aligned.m8n8.x4.shared.b16 {%0,%1,%2,%3}, [%4];"
                 : "=r"(r[0]), "=r"(r[1]), "=r"(r[2]), "=r"(r[3]) : "r"(addr));
}
__device__ __forceinline__ void mma_bf16(float* c, const uint32_t* a, uint32_t b0, uint32_t b1) {
    asm volatile(
        "mma.sync.aligned.m16n8k16.row.col.f32.bf16.bf16.f32 "
        "{%0,%1,%2,%3}, {%4,%5,%6,%7}, {%8,%9}, {%0,%1,%2,%3};\n"
        : "+f"(c[0]), "+f"(c[1]), "+f"(c[2]), "+f"(c[3])
        : "r"(a[0]), "r"(a[1]), "r"(a[2]), "r"(a[3]), "r"(b0), "r"(b1));
}

// ---------------- K1: normalize nnmf_w rows (+ transpose) ----------------
__global__ void wnorm_kernel(const float* __restrict__ nnmf_w) {
    int f = threadIdx.x;  // 0..63
    float s = 0.f;
#pragma unroll
    for (int d = 0; d < NDH; ++d) s += nnmf_w[f * NDH + d];
    s = fmaxf(s, EPSV);
    float inv = 1.f / s;
#pragma unroll
    for (int d = 0; d < NDH; ++d) {
        float v = nnmf_w[f * NDH + d] * inv;
        g_Wn[f * NDH + d] = v;
        g_Wt[d * NFH + f] = v;
    }
}

// ---------------- K2a: bf16 split conversion of X and embed_w ----------------
__global__ void __launch_bounds__(256) conv_kernel(const float* __restrict__ X,
                                                   const float* __restrict__ Wm) {
    int i = blockIdx.x * 256 + threadIdx.x;
    int row = i / 192, q = (i % 192) * 4;
    const float* src = (row < 2048) ? X + (size_t)row * 768 + q
                                    : Wm + (size_t)(row - 2048) * 768 + q;
    float4 v = *(const float4*)src;
    float xs[4] = {v.x, v.y, v.z, v.w};
    __nv_bfloat16 hi[4], lo[4];
#pragma unroll
    for (int j = 0; j < 4; ++j) {
        hi[j] = __float2bfloat16(xs[j]);
        lo[j] = __float2bfloat16(xs[j] - __bfloat162float(hi[j]));
    }
    uint2 hv = make_uint2(pack2(hi[0], hi[1]), pack2(hi[2], hi[3]));
    uint2 lv = make_uint2(pack2(lo[0], lo[1]), pack2(lo[2], lo[3]));
    if (row < 2048) {
        __nv_bfloat16* dst = g_Abf + (size_t)row * K3 + q;
        *(uint2*)(dst)        = hv;
        *(uint2*)(dst + 768)  = hv;
        *(uint2*)(dst + 1536) = lv;
    } else {
        __nv_bfloat16* dst = g_Wbf + (size_t)(row - 2048) * K3 + q;
        *(uint2*)(dst)        = hv;
        *(uint2*)(dst + 768)  = lv;
        *(uint2*)(dst + 1536) = hv;
    }
}

// ---------------- K2b: embed GEMM via mma.sync bf16, K=2304 ----------------
__global__ void __launch_bounds__(256) embed_mma_kernel(const float* __restrict__ bias) {
    __shared__ __align__(16) __nv_bfloat16 As[128 * 40];
    __shared__ __align__(16) __nv_bfloat16 Bs[64 * 40];
    int tid = threadIdx.x;
    int bm = blockIdx.y * 128, bn = blockIdx.x * 64;
    int wid = tid >> 5, lane = tid & 31;
    int wm = wid & 3, wn = wid >> 2;

    float c[2][4][4];
#pragma unroll
    for (int mt = 0; mt < 2; ++mt)
#pragma unroll
        for (int nt = 0; nt < 4; ++nt)
#pragma unroll
            for (int r = 0; r < 4; ++r) c[mt][nt][r] = 0.f;

    uint32_t a_base[2], b_base[2];
#pragma unroll
    for (int mt = 0; mt < 2; ++mt) {
        int row = wm * 32 + mt * 16 + (lane & 15);
        int colhalf = lane >> 4;
        a_base[mt] = (uint32_t)__cvta_generic_to_shared(&As[row * 40 + colhalf * 8]);
    }
#pragma unroll
    for (int bt = 0; bt < 2; ++bt) {
        int n = wn * 32 + bt * 16 + ((lane >> 4) << 3) + (lane & 7);
        int khalf = (lane >> 3) & 1;
        b_base[bt] = (uint32_t)__cvta_generic_to_shared(&Bs[n * 40 + khalf * 8]);
    }

    for (int ks = 0; ks < K3 / 32; ++ks) {
        int k0 = ks * 32;
#pragma unroll
        for (int r = 0; r < 2; ++r) {
            int q = tid + r * 256;
            int m = q >> 2, cch = q & 3;
            *(uint4*)&As[m * 40 + cch * 8] =
                *(const uint4*)&g_Abf[(size_t)(bm + m) * K3 + k0 + cch * 8];
        }
        {
            int n = tid >> 2, cch = tid & 3;
            *(uint4*)&Bs[n * 40 + cch * 8] =
                *(const uint4*)&g_Wbf[(size_t)(bn + n) * K3 + k0 + cch * 8];
        }
        __syncthreads();
#pragma unroll
        for (int kh = 0; kh < 2; ++kh) {
            int kk = kh * 16;
            uint32_t a[2][4], b[2][4];
            ldsm4(a[0], a_base[0] + kk * 2);
            ldsm4(a[1], a_base[1] + kk * 2);
            ldsm4(b[0], b_base[0] + kk * 2);
            ldsm4(b[1], b_base[1] + kk * 2);
#pragma unroll
            for (int mt = 0; mt < 2; ++mt)
#pragma unroll
                for (int nt = 0; nt < 4; ++nt)
                    mma_bf16(c[mt][nt], a[mt], b[nt >> 1][(nt & 1) * 2], b[nt >> 1][(nt & 1) * 2 + 1]);
        }
        __syncthreads();
    }

#pragma unroll
    for (int mt = 0; mt < 2; ++mt) {
#pragma unroll
        for (int nt = 0; nt < 4; ++nt) {
            int m0 = bm + wm * 32 + mt * 16 + (lane >> 2);
            int n0 = bn + wn * 32 + nt * 8 + (lane & 3) * 2;
            float2 bv = *(const float2*)&bias[n0];
            float2 o0, o1;
            o0.x = fmaxf(c[mt][nt][0] + bv.x, MIN_POS);
            o0.y = fmaxf(c[mt][nt][1] + bv.y, MIN_POS);
            o1.x = fmaxf(c[mt][nt][2] + bv.x, MIN_POS);
            o1.y = fmaxf(c[mt][nt][3] + bv.y, MIN_POS);
            *(float2*)&g_xe[(size_t)m0 * NE + n0] = o0;
            *(float2*)&g_xe[(size_t)(m0 + 8) * NE + n0] = o1;
        }
    }
}

// ---------------- K3: fused NNMF, feature-major smem, 4 tokens/thread, 128 threads ----------------
// thread = (g 0..7: token-group of 4, d4 0..15: feature-quad)
__global__ void __launch_bounds__(128) nnmf_kernel() {
    extern __shared__ float sm[];
    float* sW   = sm;                       // [f][d], stride 64
    float* sWt  = sm + 4096;                // [d][f], stride 64
    float* s_ht = sm + 8192;                // [f][tok], stride HSTR
    float* s_rt = sm + 8192 + 64 * HSTR;    // [d][tok], stride HSTR

    int head = blockIdx.y;
    int tile = blockIdx.x;       // 0..63 (32 tokens each)
    int tid = threadIdx.x;
    int d4 = tid & 15;
    int g = tid >> 4;            // 0..7
    int tokbase = tile * 32;

    for (int i = tid; i < 4096; i += 128) sW[i] = g_Wn[i];
    for (int i = tid; i < 4096; i += 128) sWt[i] = g_Wt[i];

    // inp[t][i]: l1-normalized slice for tokens g*4+t, dims d4*4+i
    float inp[4][4];
#pragma unroll
    for (int t = 0; t < 4; ++t) {
        int tok = tokbase + g * 4 + t;
        float4 x = *(const float4*)&g_xe[(size_t)tok * NE + head * 64 + d4 * 4];
        float s = red16(x.x + x.y + x.z + x.w);
        float iv = 1.f / fmaxf(s, EPSV);
        inp[t][0] = x.x * iv; inp[t][1] = x.y * iv; inp[t][2] = x.z * iv; inp[t][3] = x.w * iv;
    }

    float hr[4][4];              // h over f-slice (f = d4*4+i), per token
    const float hinit = 1.f / 64.f;
#pragma unroll
    for (int t = 0; t < 4; ++t)
#pragma unroll
        for (int i = 0; i < 4; ++i) hr[t][i] = hinit;
#pragma unroll
    for (int i = 0; i < 4; ++i)
        *(float4*)&s_ht[(d4 * 4 + i) * HSTR + g * 4] = make_float4(hinit, hinit, hinit, hinit);
    __syncthreads();

    for (int it = 0; it < 3; ++it) {
        // rec-phase: rec[d,tok] = sum_f h[f,tok] * W[f][d]
        float a[4][4] = {};      // [t][d-comp]
#pragma unroll 8
        for (int ff = 0; ff < 64; ++ff) {
            float4 w = *(const float4*)&sW[ff * 64 + d4 * 4];
            float4 h4 = *(const float4*)&s_ht[ff * HSTR + g * 4];
            a[0][0] += h4.x * w.x; a[0][1] += h4.x * w.y; a[0][2] += h4.x * w.z; a[0][3] += h4.x * w.w;
            a[1][0] += h4.y * w.x; a[1][1] += h4.y * w.y; a[1][2] += h4.y * w.z; a[1][3] += h4.y * w.w;
            a[2][0] += h4.z * w.x; a[2][1] += h4.z * w.y; a[2][2] += h4.z * w.z; a[2][3] += h4.z * w.w;
            a[3][0] += h4.w * w.x; a[3][1] += h4.w * w.y; a[3][2] += h4.w * w.z; a[3][3] += h4.w * w.w;
        }
        float qq[4][4];
#pragma unroll
        for (int t = 0; t < 4; ++t) {
#pragma unroll
            for (int i = 0; i < 4; ++i) a[t][i] = fmaxf(a[t][i], MIN_POS);
            float p = red16(a[t][0] + a[t][1] + a[t][2] + a[t][3]);
            float iv = 1.f / fmaxf(p, EPSV);
#pragma unroll
            for (int i = 0; i < 4; ++i) qq[t][i] = inp[t][i] / (a[t][i] * iv);
        }
#pragma unroll
        for (int i = 0; i < 4; ++i)
            *(float4*)&s_rt[(d4 * 4 + i) * HSTR + g * 4] =
                make_float4(qq[0][i], qq[1][i], qq[2][i], qq[3][i]);
        __syncthreads();

        // t-phase: t[f,tok] = sum_d ratio[d,tok] * Wt[d][f]
        float b[4][4] = {};
#pragma unroll 8
        for (int d = 0; d < 64; ++d) {
            float4 wt = *(const float4*)&sWt[d * 64 + d4 * 4];
            float4 r4 = *(const float4*)&s_rt[d * HSTR + g * 4];
            b[0][0] += r4.x * wt.x; b[0][1] += r4.x * wt.y; b[0][2] += r4.x * wt.z; b[0][3] += r4.x * wt.w;
            b[1][0] += r4.y * wt.x; b[1][1] += r4.y * wt.y; b[1][2] += r4.y * wt.z; b[1][3] += r4.y * wt.w;
            b[2][0] += r4.z * wt.x; b[2][1] += r4.z * wt.y; b[2][2] += r4.z * wt.z; b[2][3] += r4.z * wt.w;
            b[3][0] += r4.w * wt.x; b[3][1] += r4.w * wt.y; b[3][2] += r4.w * wt.z; b[3][3] += r4.w * wt.w;
        }
#pragma unroll
        for (int t = 0; t < 4; ++t) {
            float hn[4];
#pragma unroll
            for (int i = 0; i < 4; ++i) hn[i] = fmaxf(hr[t][i] * b[t][i], MIN_POS);
            float hs = red16(hn[0] + hn[1] + hn[2] + hn[3]);
            float ih = 1.f / fmaxf(hs, EPSV);
#pragma unroll
            for (int i = 0; i < 4; ++i) hr[t][i] = hn[i] * ih;
        }
#pragma unroll
        for (int i = 0; i < 4; ++i)
            *(float4*)&s_ht[(d4 * 4 + i) * HSTR + g * 4] =
                make_float4(hr[0][i], hr[1][i], hr[2][i], hr[3][i]);
        __syncthreads();
    }

    // final l1norm of h; reconstruct hri = inp^2 / ratio (ratio of last iter still in s_rt)
    float hf[4][4], ri[4][4];
#pragma unroll
    for (int t = 0; t < 4; ++t) {
        float hs = red16(hr[t][0] + hr[t][1] + hr[t][2] + hr[t][3]);
        float ih = 1.f / fmaxf(hs, EPSV);
#pragma unroll
        for (int i = 0; i < 4; ++i) hf[t][i] = hr[t][i] * ih;
    }
#pragma unroll
    for (int i = 0; i < 4; ++i) {
        float4 q4 = *(const float4*)&s_rt[(d4 * 4 + i) * HSTR + g * 4];
        ri[0][i] = inp[0][i] * inp[0][i] / q4.x;
        ri[1][i] = inp[1][i] * inp[1][i] / q4.y;
        ri[2][i] = inp[2][i] * inp[2][i] / q4.z;
        ri[3][i] = inp[3][i] * inp[3][i] / q4.w;
    }
    __syncthreads();   // all warps done with sW/sWt/s_rt before region reuse

    // token-major copies into reused W regions + gmem writes
    float* s_htm = sm;           // [tok][f], stride TSTR (32*68 <= 4096)
    float* s_rtm = sm + 4096;    // [tok][d], stride TSTR
#pragma unroll
    for (int t = 0; t < 4; ++t) {
        int tl = g * 4 + t;
        float4 hv = make_float4(hf[t][0], hf[t][1], hf[t][2], hf[t][3]);
        float4 rv = make_float4(ri[t][0], ri[t][1], ri[t][2], ri[t][3]);
        *(float4*)&s_htm[tl * TSTR + d4 * 4] = hv;
        *(float4*)&s_rtm[tl * TSTR + d4 * 4] = rv;
        int token = tokbase + tl;
        int bi = token >> 10, si = token & 1023;
        size_t base = ((size_t)((bi * NH + head) * NS + si)) * 64 + d4 * 4;
        *(float4*)&g_h[base] = hv;
        *(float4*)&g_hri[base] = rv;
    }
    __syncthreads();

    // ---- fused G1 partial: G1[f,d] = sum_o h[o,f]*hri[o,d], cs[f] = sum_o h[o,f] ----
    {
        int f4 = tid & 15, dg = tid >> 4;   // dg 0..7, d-cols dg*8..+7
        float acc[4][8] = {};
        float cs[4] = {};
#pragma unroll 8
        for (int o = 0; o < 32; ++o) {
            float4 hv = *(const float4*)&s_htm[o * TSTR + f4 * 4];
            float4 r0 = *(const float4*)&s_rtm[o * TSTR + dg * 8];
            float4 r1 = *(const float4*)&s_rtm[o * TSTR + dg * 8 + 4];
            float hvv[4] = {hv.x, hv.y, hv.z, hv.w};
            float rvv[8] = {r0.x, r0.y, r0.z, r0.w, r1.x, r1.y, r1.z, r1.w};
#pragma unroll
            for (int i = 0; i < 4; i++)
#pragma unroll
                for (int j = 0; j < 8; j++) acc[i][j] += hvv[i] * rvv[j];
            if (dg == 0) {
#pragma unroll
                for (int i = 0; i < 4; i++) cs[i] += hvv[i];
            }
        }
        int bb = tile >> 5;
        int gsplit = tile & 31;
        int bh = bb * NH + head;
        float* gp = g_G1p + ((size_t)(bh * NSG + gsplit)) * 4096;
#pragma unroll
        for (int i = 0; i < 4; i++) {
            *(float4*)&gp[(f4 * 4 + i) * 64 + dg * 8] =
                make_float4(acc[i][0], acc[i][1], acc[i][2], acc[i][3]);
            *(float4*)&gp[(f4 * 4 + i) * 64 + dg * 8 + 4] =
                make_float4(acc[i][4], acc[i][5], acc[i][6], acc[i][7]);
        }
        if (dg == 0) {
#pragma unroll
            for (int i = 0; i < 4; i++) g_csp[(bh * NSG + gsplit) * 64 + f4 * 4 + i] = cs[i];
        }
    }
}

// ---------------- K4b: iterations 0+1 in closed form ----------------
__global__ void __launch_bounds__(256) alpha01_kernel() {
    __shared__ float sW[4096];
    __shared__ float sG[4096];
    __shared__ float s_c0[64], s_ai0[64], s_c1[64];
    int bh = blockIdx.x, tid = threadIdx.x;

    for (int i = tid; i < 4096; i += 256) sW[i] = g_Wn[i];
    const float* gp = g_G1p + (size_t)bh * NSG * 4096;
    for (int i = tid; i < 4096; i += 256) {
        float s = 0.f;
#pragma unroll
        for (int p = 0; p < NSG; ++p) s += gp[p * 4096 + i];
        sG[i] = s;
    }
    if (tid < 64) {
        float s = 0.f;
#pragma unroll
        for (int p = 0; p < NSG; ++p) s += g_csp[(bh * NSG + p) * 64 + tid];
        s_c0[tid] = s;
    }
    __syncthreads();
    if (tid < 64) {
        int d = tid;
        float r = 0.f;
#pragma unroll 8
        for (int f = 0; f < 64; ++f) r += s_c0[f] * sW[f * 64 + d];
        float ai = 1.f / (r + EPSV);
        s_ai0[d] = ai;
        g_aiA[bh * 64 + d] = ai;
    }
    __syncthreads();
    if (tid < 64) {
        int f = tid;
        float c1 = 0.f;
#pragma unroll 8
        for (int dd = 0; dd < 64; ++dd) {
            int d = (dd + f) & 63;
            c1 += sG[f * 64 + d] * s_ai0[d];
        }
        s_c1[f] = c1;
    }
    __syncthreads();
    if (tid < 64) {
        int d = tid;
        float r = 0.f;
#pragma unroll 8
        for (int f = 0; f < 64; ++f) r += s_c1[f] * sW[f * 64 + d];
        g_aiB[bh * 64 + d] = 1.f / (r + EPSV);
    }
}

// ---------------- K4c: pass2 — w01 per token, partial c2, partial M ----------------
__global__ void __launch_bounds__(256) pass2_kernel() {
    __shared__ __align__(16) float s_h[16][68];
    __shared__ __align__(16) float s_r[16][68];
    __shared__ float s_ai0[64], s_ai1[64];
    __shared__ float s_w[16];
    int split = blockIdx.x, bh = blockIdx.y;
    int tid = threadIdx.x;
    int f4 = tid & 15, d4 = tid >> 4;
    int lo = tid >> 4, lq = tid & 15;
    if (tid < 64) s_ai0[tid] = g_aiA[bh * 64 + tid];
    else if (tid < 128) s_ai1[tid - 64] = g_aiB[bh * 64 + tid - 64];

    const float* hb = g_h + ((size_t)bh * NS + split * OSPL) * 64;
    const float* rb = g_hri + ((size_t)bh * NS + split * OSPL) * 64;

    float accM[4][4] = {};
    float cs[4] = {};
    for (int c = 0; c < OSPL / 16; ++c) {
        *(float4*)&s_h[lo][lq * 4] = *(const float4*)&hb[(c * 16 + lo) * 64 + lq * 4];
        *(float4*)&s_r[lo][lq * 4] = *(const float4*)&rb[(c * 16 + lo) * 64 + lq * 4];
        __syncthreads();
        {
            int tt = tid >> 4;
            float4 v = *(const float4*)&s_r[tt][lq * 4];
            int base = lq * 4;
            float u0 = v.x * s_ai0[base] + v.y * s_ai0[base + 1] + v.z * s_ai0[base + 2] + v.w * s_ai0[base + 3];
            float u1 = v.x * s_ai1[base] + v.y * s_ai1[base + 1] + v.z * s_ai1[base + 2] + v.w * s_ai1[base + 3];
            u0 = red16(u0);
            u1 = red16(u1);
            if (lq == 0) s_w[tt] = u0 * u1;
        }
        __syncthreads();
#pragma unroll
        for (int o = 0; o < 16; ++o) {
            float wo = s_w[o];
            float4 hv = *(const float4*)&s_h[o][f4 * 4];
            float4 rv = *(const float4*)&s_r[o][d4 * 4];
            float hw[4] = {hv.x * wo, hv.y * wo, hv.z * wo, hv.w * wo};
            float rvv[4] = {rv.x, rv.y, rv.z, rv.w};
#pragma unroll
            for (int i = 0; i < 4; i++)
#pragma unroll
                for (int j = 0; j < 4; j++) accM[i][j] += hw[i] * rvv[j];
            if (d4 == 0) {
#pragma unroll
                for (int i = 0; i < 4; i++) cs[i] += hw[i];
            }
        }
        __syncthreads();
    }
    float* mp = g_Mp + ((size_t)(bh * NSPLIT + split)) * 4096;
#pragma unroll
    for (int i = 0; i < 4; i++)
#pragma unroll
        for (int j = 0; j < 4; j++) mp[(f4 * 4 + i) * 64 + d4 * 4 + j] = accM[i][j];
    if (d4 == 0) {
#pragma unroll
        for (int i = 0; i < 4; i++) g_c2p[(bh * NSPLIT + split) * 64 + f4 * 4 + i] = cs[i];
    }
}

// ---------------- K4d: ai2 + cfin = (sum M)·ai2 ----------------
__global__ void __launch_bounds__(256) alpha2cfin_kernel() {
    __shared__ float sW[4096];
    __shared__ float s_c2[64];
    __shared__ float s_ai2[64];
    __shared__ float s_p[4][64];
    int bh = blockIdx.x, tid = threadIdx.x;
    for (int i = tid; i < 4096; i += 256) sW[i] = g_Wn[i];
    if (tid < 64) {
        float s = 0.f;
#pragma unroll
        for (int p = 0; p < NSPLIT; ++p) s += g_c2p[(bh * NSPLIT + p) * 64 + tid];
        s_c2[tid] = s;
    }
    __syncthreads();
    if (tid < 64) {
        int d = tid;
        float r = 0.f;
#pragma unroll 8
        for (int f = 0; f < 64; ++f) r += s_c2[f] * sW[f * 64 + d];
        s_ai2[d] = 1.f / (r + EPSV);
    }
    __syncthreads();
    {
        int f = tid & 63, g = tid >> 6;
        const float* mp = g_Mp + (size_t)bh * NSPLIT * 4096;
        float partial = 0.f;
#pragma unroll
        for (int dd = 0; dd < 16; ++dd) {
            int d = g * 16 + dd;
            float mv = 0.f;
#pragma unroll
            for (int p = 0; p < NSPLIT; ++p) mv += mp[p * 4096 + f * 64 + d];
            partial += mv * s_ai2[d];
        }
        s_p[g][f] = partial;
    }
    __syncthreads();
    if (tid < 64) {
        int b = bh / NH, head = bh % NH;
        g_cfin[b * NE + head * 64 + tid] = s_p[0][tid] + s_p[1][tid] + s_p[2][tid] + s_p[3][tid];
    }
}

// ---------------- K5: out projection of the 2 unique rows ----------------
__global__ void __launch_bounds__(256) outrow_kernel(const float* __restrict__ out_w,
                                                     const float* __restrict__ out_b) {
    int b = blockIdx.y;
    int warp = threadIdx.x >> 5, lane = threadIdx.x & 31;
    int j = blockIdx.x * 8 + warp;
    const float* c = g_cfin + b * NE;
    const float* wrow = out_w + (size_t)j * NE;
    float acc = 0.f;
    for (int e = lane; e < NE; e += 32) acc += c[e] * wrow[e];
    acc = red32(acc);
    if (lane == 0) g_yrow[b * FIN + j] = acc + out_b[j];
}

// ---------------- K6: broadcast rows to all positions ----------------
__global__ void __launch_bounds__(256) bcast_kernel(float* __restrict__ out) {
    int idx = blockIdx.x * 256 + threadIdx.x;
    const int per_row = FIN / 4;
    int j4 = idx % per_row;
    int bs = idx / per_row;
    int b = bs >> 10;
    float4 v = ((const float4*)(g_yrow + b * FIN))[j4];
    ((float4*)out)[idx] = v;
}

// ---------------- launch ----------------
extern "C" void kernel_launch(void* const* d_in, const int* in_sizes, int n_in,
                              void* d_out, int out_size) {
    const float* x       = (const float*)d_in[0];
    const float* embed_w = (const float*)d_in[1];
    const float* embed_b = (const float*)d_in[2];
    const float* nnmf_w  = (const float*)d_in[3];
    const float* out_w   = (const float*)d_in[4];
    const float* out_b   = (const float*)d_in[5];
    float* out = (float*)d_out;

    static bool attr_set = false;
    if (!attr_set) {
        cudaFuncSetAttribute(nnmf_kernel, cudaFuncAttributeMaxDynamicSharedMemorySize,
                             NN_SMEM_BYTES);
        attr_set = true;
    }

    wnorm_kernel<<<1, 64>>>(nnmf_w);
    conv_kernel<<<2112, 256>>>(x, embed_w);
    embed_mma_kernel<<<dim3(NE / 64, (NB * NS) / 128), 256>>>(embed_b);
    nnmf_kernel<<<dim3((NB * NS) / 32, NH), 128, NN_SMEM_BYTES>>>();
    alpha01_kernel<<<NBH, 256>>>();
    pass2_kernel<<<dim3(NSPLIT, NBH), 256>>>();
    alpha2cfin_kernel<<<NBH, 256>>>();
    outrow_kernel<<<dim3(NE / 8, NB), 256>>>(out_w, out_b);
    bcast_kernel<<<(NB * NS * (FIN / 4)) / 256, 256>>>(out);
}

// round 8
// speedup vs baseline: 1.4234x; 1.1176x over previous
#include <cuda_runtime.h>
#include <cuda_bf16.h>
#include <cstdint>

#define NB 2
#define NS 1024
#define FIN 768
#define NE 768
#define NH 12
#define NBH (NB * NH)
#define NDH 64
#define NFH 64
#define NSPLIT 16
#define OSPL (NS / NSPLIT)   // 64 tokens per split (pass2)
#define NSG 16               // g1 splits (64 tokens each, fused in nnmf)
#define MIN_POS 1e-6f
#define EPSV 1e-20f
#define K3 2304              // tripled K for bf16-split GEMM
#define HSTR 68              // feature-major row stride (floats): 64 tokens + 4 pad
#define NN_SMEM_BYTES ((4096 + 4096 + 64 * HSTR * 2) * 4)

typedef unsigned long long u64;

// ---------------- scratch (device globals; no allocation) ----------------
__device__ __align__(16) float g_Wn[NFH * NDH];                 // normalized W [f][d]
__device__ __align__(16) float g_Wt[NDH * NFH];                 // transposed normalized W [d][f]
__device__ __align__(16) __nv_bfloat16 g_Abf[2048 * K3];        // [hi | hi | lo] of X
__device__ __align__(16) __nv_bfloat16 g_Wbf[768 * K3];         // [hi | lo | hi] of embed_w
__device__ __align__(16) float g_xe[NB * NS * NE];              // clipped embed output
__device__ __align__(16) float g_h[NBH * NS * NFH];             // h   [bh][s][f]
__device__ __align__(16) float g_hri[NBH * NS * NDH];           // rec*inp [bh][s][d]
__device__ __align__(16) float g_G1p[NBH * NSG * 64 * 64];      // partial h^T*hri
__device__ __align__(16) float g_Mp[NBH * NSPLIT * 64 * 64];    // partial h^T*(w01*hri)
__device__ __align__(16) float g_csp[NBH * NSG * 64];           // partial colsum(h)
__device__ __align__(16) float g_c2p[NBH * NSPLIT * 64];        // partial c2
__device__ __align__(16) float g_aiA[NBH * 64];                 // arec_inv iter0
__device__ __align__(16) float g_aiB[NBH * 64];                 // arec_inv iter1
__device__ __align__(16) float g_cfin[NB * NE];                 // final mixed row per batch
__device__ __align__(16) float g_yrow[NB * FIN];                // final projected row per batch

// ---------------- helpers ----------------
__device__ __forceinline__ float red16(float v) {
    v += __shfl_xor_sync(0xffffffffu, v, 8);
    v += __shfl_xor_sync(0xffffffffu, v, 4);
    v += __shfl_xor_sync(0xffffffffu, v, 2);
    v += __shfl_xor_sync(0xffffffffu, v, 1);
    return v;
}
__device__ __forceinline__ float red32(float v) {
    v += __shfl_xor_sync(0xffffffffu, v, 16);
    return red16(v);
}
__device__ __forceinline__ uint32_t pack2(__nv_bfloat16 a, __nv_bfloat16 b) {
    __nv_bfloat162 t = __halves2bfloat162(a, b);
    return *reinterpret_cast<uint32_t*>(&t);
}
__device__ __forceinline__ void ldsm4(uint32_t* r, uint32_t addr) {
    asm volatile("ldmatrix.sync.aligned.m8n8.x4.shared.b16 {%0,%1,%2,%3}, [%4];"
                 : "=r"(r[0]), "=r"(r[1]), "=r"(r[2]), "=r"(r[3]) : "r"(addr));
}
__device__ __forceinline__ void mma_bf16(float* c, const uint32_t* a, uint32_t b0, uint32_t b1) {
    asm volatile(
        "mma.sync.aligned.m16n8k16.row.col.f32.bf16.bf16.f32 "
        "{%0,%1,%2,%3}, {%4,%5,%6,%7}, {%8,%9}, {%0,%1,%2,%3};\n"
        : "+f"(c[0]), "+f"(c[1]), "+f"(c[2]), "+f"(c[3])
        : "r"(a[0]), "r"(a[1]), "r"(a[2]), "r"(a[3]), "r"(b0), "r"(b1));
}
// packed fp32x2 helpers (FFMA2 is PTX-only; ptxas never auto-fuses)
__device__ __forceinline__ u64 fma2(u64 a, u64 b, u64 c) {
    u64 d;
    asm("fma.rn.f32x2 %0, %1, %2, %3;" : "=l"(d) : "l"(a), "l"(b), "l"(c));
    return d;
}
__device__ __forceinline__ u64 dup2(float x) {
    u64 d;
    uint32_t r = __float_as_uint(x);
    asm("mov.b64 %0, {%1, %2};" : "=l"(d) : "r"(r), "r"(r));
    return d;
}
__device__ __forceinline__ float2 unpk2(u64 v) {
    uint32_t lo, hi;
    asm("mov.b64 {%0, %1}, %2;" : "=r"(lo), "=r"(hi) : "l"(v));
    return make_float2(__uint_as_float(lo), __uint_as_float(hi));
}

// ---------------- K1: normalize nnmf_w rows (+ transpose) ----------------
__global__ void wnorm_kernel(const float* __restrict__ nnmf_w) {
    int f = threadIdx.x;  // 0..63
    float s = 0.f;
#pragma unroll
    for (int d = 0; d < NDH; ++d) s += nnmf_w[f * NDH + d];
    s = fmaxf(s, EPSV);
    float inv = 1.f / s;
#pragma unroll
    for (int d = 0; d < NDH; ++d) {
        float v = nnmf_w[f * NDH + d] * inv;
        g_Wn[f * NDH + d] = v;
        g_Wt[d * NFH + f] = v;
    }
}

// ---------------- K2a: bf16 split conversion of X and embed_w ----------------
__global__ void __launch_bounds__(256) conv_kernel(const float* __restrict__ X,
                                                   const float* __restrict__ Wm) {
    int i = blockIdx.x * 256 + threadIdx.x;
    int row = i / 192, q = (i % 192) * 4;
    const float* src = (row < 2048) ? X + (size_t)row * 768 + q
                                    : Wm + (size_t)(row - 2048) * 768 + q;
    float4 v = *(const float4*)src;
    float xs[4] = {v.x, v.y, v.z, v.w};
    __nv_bfloat16 hi[4], lo[4];
#pragma unroll
    for (int j = 0; j < 4; ++j) {
        hi[j] = __float2bfloat16(xs[j]);
        lo[j] = __float2bfloat16(xs[j] - __bfloat162float(hi[j]));
    }
    uint2 hv = make_uint2(pack2(hi[0], hi[1]), pack2(hi[2], hi[3]));
    uint2 lv = make_uint2(pack2(lo[0], lo[1]), pack2(lo[2], lo[3]));
    if (row < 2048) {
        __nv_bfloat16* dst = g_Abf + (size_t)row * K3 + q;
        *(uint2*)(dst)        = hv;
        *(uint2*)(dst + 768)  = hv;
        *(uint2*)(dst + 1536) = lv;
    } else {
        __nv_bfloat16* dst = g_Wbf + (size_t)(row - 2048) * K3 + q;
        *(uint2*)(dst)        = hv;
        *(uint2*)(dst + 768)  = lv;
        *(uint2*)(dst + 1536) = hv;
    }
}

// ---------------- K2b: embed GEMM via mma.sync bf16, K=2304 ----------------
__global__ void __launch_bounds__(256) embed_mma_kernel(const float* __restrict__ bias) {
    __shared__ __align__(16) __nv_bfloat16 As[128 * 40];
    __shared__ __align__(16) __nv_bfloat16 Bs[64 * 40];
    int tid = threadIdx.x;
    int bm = blockIdx.y * 128, bn = blockIdx.x * 64;
    int wid = tid >> 5, lane = tid & 31;
    int wm = wid & 3, wn = wid >> 2;

    float c[2][4][4];
#pragma unroll
    for (int mt = 0; mt < 2; ++mt)
#pragma unroll
        for (int nt = 0; nt < 4; ++nt)
#pragma unroll
            for (int r = 0; r < 4; ++r) c[mt][nt][r] = 0.f;

    uint32_t a_base[2], b_base[2];
#pragma unroll
    for (int mt = 0; mt < 2; ++mt) {
        int row = wm * 32 + mt * 16 + (lane & 15);
        int colhalf = lane >> 4;
        a_base[mt] = (uint32_t)__cvta_generic_to_shared(&As[row * 40 + colhalf * 8]);
    }
#pragma unroll
    for (int bt = 0; bt < 2; ++bt) {
        int n = wn * 32 + bt * 16 + ((lane >> 4) << 3) + (lane & 7);
        int khalf = (lane >> 3) & 1;
        b_base[bt] = (uint32_t)__cvta_generic_to_shared(&Bs[n * 40 + khalf * 8]);
    }

    for (int ks = 0; ks < K3 / 32; ++ks) {
        int k0 = ks * 32;
#pragma unroll
        for (int r = 0; r < 2; ++r) {
            int q = tid + r * 256;
            int m = q >> 2, cch = q & 3;
            *(uint4*)&As[m * 40 + cch * 8] =
                *(const uint4*)&g_Abf[(size_t)(bm + m) * K3 + k0 + cch * 8];
        }
        {
            int n = tid >> 2, cch = tid & 3;
            *(uint4*)&Bs[n * 40 + cch * 8] =
                *(const uint4*)&g_Wbf[(size_t)(bn + n) * K3 + k0 + cch * 8];
        }
        __syncthreads();
#pragma unroll
        for (int kh = 0; kh < 2; ++kh) {
            int kk = kh * 16;
            uint32_t a[2][4], b[2][4];
            ldsm4(a[0], a_base[0] + kk * 2);
            ldsm4(a[1], a_base[1] + kk * 2);
            ldsm4(b[0], b_base[0] + kk * 2);
            ldsm4(b[1], b_base[1] + kk * 2);
#pragma unroll
            for (int mt = 0; mt < 2; ++mt)
#pragma unroll
                for (int nt = 0; nt < 4; ++nt)
                    mma_bf16(c[mt][nt], a[mt], b[nt >> 1][(nt & 1) * 2], b[nt >> 1][(nt & 1) * 2 + 1]);
        }
        __syncthreads();
    }

#pragma unroll
    for (int mt = 0; mt < 2; ++mt) {
#pragma unroll
        for (int nt = 0; nt < 4; ++nt) {
            int m0 = bm + wm * 32 + mt * 16 + (lane >> 2);
            int n0 = bn + wn * 32 + nt * 8 + (lane & 3) * 2;
            float2 bv = *(const float2*)&bias[n0];
            float2 o0, o1;
            o0.x = fmaxf(c[mt][nt][0] + bv.x, MIN_POS);
            o0.y = fmaxf(c[mt][nt][1] + bv.y, MIN_POS);
            o1.x = fmaxf(c[mt][nt][2] + bv.x, MIN_POS);
            o1.y = fmaxf(c[mt][nt][3] + bv.y, MIN_POS);
            *(float2*)&g_xe[(size_t)m0 * NE + n0] = o0;
            *(float2*)&g_xe[(size_t)(m0 + 8) * NE + n0] = o1;
        }
    }
}

// ---------------- K3: fused NNMF, FFMA2-packed, 64 tokens/block, 256 threads ----------------
// thread = (g 0..15: token-group of 4, d4 0..15: feature-quad)
__global__ void __launch_bounds__(256, 3) nnmf_kernel() {
    extern __shared__ float sm[];
    float* sW   = sm;                       // [f][d], stride 64
    float* sWt  = sm + 4096;                // [d][f], stride 64
    float* s_ht = sm + 8192;                // [f][tok], stride HSTR
    float* s_rt = sm + 8192 + 64 * HSTR;    // [d][tok], stride HSTR

    int head = blockIdx.y;
    int tile = blockIdx.x;       // 0..31 (64 tokens each)
    int tid = threadIdx.x;
    int d4 = tid & 15;
    int g = tid >> 4;            // 0..15
    int tokbase = tile * 64;

    for (int i = tid; i < 4096; i += 256) sW[i] = g_Wn[i];
    for (int i = tid; i < 4096; i += 256) sWt[i] = g_Wt[i];

    // inp[t][i]: l1-normalized slice for tokens g*4+t, dims d4*4+i
    float inp[4][4];
#pragma unroll
    for (int t = 0; t < 4; ++t) {
        int tok = tokbase + g * 4 + t;
        float4 x = *(const float4*)&g_xe[(size_t)tok * NE + head * 64 + d4 * 4];
        float s = red16(x.x + x.y + x.z + x.w);
        float iv = 1.f / fmaxf(s, EPSV);
        inp[t][0] = x.x * iv; inp[t][1] = x.y * iv; inp[t][2] = x.z * iv; inp[t][3] = x.w * iv;
    }

    float hr[4][4];
    const float hinit = 1.f / 64.f;
#pragma unroll
    for (int t = 0; t < 4; ++t)
#pragma unroll
        for (int i = 0; i < 4; ++i) hr[t][i] = hinit;
#pragma unroll
    for (int i = 0; i < 4; ++i)
        *(float4*)&s_ht[(d4 * 4 + i) * HSTR + g * 4] = make_float4(hinit, hinit, hinit, hinit);
    __syncthreads();

    for (int it = 0; it < 3; ++it) {
        // rec-phase: a[i][p] packed over token-pairs
        u64 a[4][2] = {};
#pragma unroll 8
        for (int ff = 0; ff < 64; ++ff) {
            ulonglong2 hp = *(const ulonglong2*)&s_ht[ff * HSTR + g * 4];
            float4 w = *(const float4*)&sW[ff * 64 + d4 * 4];
            u64 w0 = dup2(w.x), w1 = dup2(w.y), w2 = dup2(w.z), w3 = dup2(w.w);
            a[0][0] = fma2(w0, hp.x, a[0][0]); a[0][1] = fma2(w0, hp.y, a[0][1]);
            a[1][0] = fma2(w1, hp.x, a[1][0]); a[1][1] = fma2(w1, hp.y, a[1][1]);
            a[2][0] = fma2(w2, hp.x, a[2][0]); a[2][1] = fma2(w2, hp.y, a[2][1]);
            a[3][0] = fma2(w3, hp.x, a[3][0]); a[3][1] = fma2(w3, hp.y, a[3][1]);
        }
        // unpack to av[t][i], clamp, per-token l1 over all 64 dims
        float av[4][4];
#pragma unroll
        for (int i = 0; i < 4; ++i) {
            float2 u0 = unpk2(a[i][0]), u1 = unpk2(a[i][1]);
            av[0][i] = fmaxf(u0.x, MIN_POS); av[1][i] = fmaxf(u0.y, MIN_POS);
            av[2][i] = fmaxf(u1.x, MIN_POS); av[3][i] = fmaxf(u1.y, MIN_POS);
        }
        float pm[4];
#pragma unroll
        for (int t = 0; t < 4; ++t)
            pm[t] = fmaxf(red16(av[t][0] + av[t][1] + av[t][2] + av[t][3]), EPSV);
        // ratio = inp * pm / av, stored feature-major
#pragma unroll
        for (int i = 0; i < 4; ++i) {
            float q0 = __fdividef(inp[0][i] * pm[0], av[0][i]);
            float q1 = __fdividef(inp[1][i] * pm[1], av[1][i]);
            float q2 = __fdividef(inp[2][i] * pm[2], av[2][i]);
            float q3 = __fdividef(inp[3][i] * pm[3], av[3][i]);
            *(float4*)&s_rt[(d4 * 4 + i) * HSTR + g * 4] = make_float4(q0, q1, q2, q3);
        }
        __syncthreads();

        // t-phase: b[i][p] packed
        u64 b[4][2] = {};
#pragma unroll 8
        for (int d = 0; d < 64; ++d) {
            ulonglong2 rp = *(const ulonglong2*)&s_rt[d * HSTR + g * 4];
            float4 wt = *(const float4*)&sWt[d * 64 + d4 * 4];
            u64 w0 = dup2(wt.x), w1 = dup2(wt.y), w2 = dup2(wt.z), w3 = dup2(wt.w);
            b[0][0] = fma2(w0, rp.x, b[0][0]); b[0][1] = fma2(w0, rp.y, b[0][1]);
            b[1][0] = fma2(w1, rp.x, b[1][0]); b[1][1] = fma2(w1, rp.y, b[1][1]);
            b[2][0] = fma2(w2, rp.x, b[2][0]); b[2][1] = fma2(w2, rp.y, b[2][1]);
            b[3][0] = fma2(w3, rp.x, b[3][0]); b[3][1] = fma2(w3, rp.y, b[3][1]);
        }
        float bv[4][4];
#pragma unroll
        for (int i = 0; i < 4; ++i) {
            float2 u0 = unpk2(b[i][0]), u1 = unpk2(b[i][1]);
            bv[0][i] = u0.x; bv[1][i] = u0.y; bv[2][i] = u1.x; bv[3][i] = u1.y;
        }
#pragma unroll
        for (int t = 0; t < 4; ++t) {
            float hn[4];
#pragma unroll
            for (int i = 0; i < 4; ++i) hn[i] = fmaxf(hr[t][i] * bv[t][i], MIN_POS);
            float hs = red16(hn[0] + hn[1] + hn[2] + hn[3]);
            float ih = 1.f / fmaxf(hs, EPSV);
#pragma unroll
            for (int i = 0; i < 4; ++i) hr[t][i] = hn[i] * ih;
        }
#pragma unroll
        for (int i = 0; i < 4; ++i)
            *(float4*)&s_ht[(d4 * 4 + i) * HSTR + g * 4] =
                make_float4(hr[0][i], hr[1][i], hr[2][i], hr[3][i]);
        __syncthreads();
    }

    // final l1norm of h; reconstruct hri = inp^2 / ratio (last ratio still in s_rt)
    float hf[4][4], ri[4][4];
#pragma unroll
    for (int t = 0; t < 4; ++t) {
        float hs = red16(hr[t][0] + hr[t][1] + hr[t][2] + hr[t][3]);
        float ih = 1.f / fmaxf(hs, EPSV);
#pragma unroll
        for (int i = 0; i < 4; ++i) hf[t][i] = hr[t][i] * ih;
    }
#pragma unroll
    for (int i = 0; i < 4; ++i) {
        float4 q4 = *(const float4*)&s_rt[(d4 * 4 + i) * HSTR + g * 4];
        ri[0][i] = __fdividef(inp[0][i] * inp[0][i], q4.x);
        ri[1][i] = __fdividef(inp[1][i] * inp[1][i], q4.y);
        ri[2][i] = __fdividef(inp[2][i] * inp[2][i], q4.z);
        ri[3][i] = __fdividef(inp[3][i] * inp[3][i], q4.w);
    }
    __syncthreads();   // done with sW/sWt/s_ht/s_rt before region reuse

    // token-major copies into reused W regions + gmem writes
    float* s_htm = sm;           // [tok][f], stride 64 (64*64 = 4096 exact)
    float* s_rtm = sm + 4096;    // [tok][d], stride 64
#pragma unroll
    for (int t = 0; t < 4; ++t) {
        int tl = g * 4 + t;
        float4 hv = make_float4(hf[t][0], hf[t][1], hf[t][2], hf[t][3]);
        float4 rv = make_float4(ri[t][0], ri[t][1], ri[t][2], ri[t][3]);
        *(float4*)&s_htm[tl * 64 + d4 * 4] = hv;
        *(float4*)&s_rtm[tl * 64 + d4 * 4] = rv;
        int token = tokbase + tl;
        int bi = token >> 10, si = token & 1023;
        size_t base = ((size_t)((bi * NH + head) * NS + si)) * 64 + d4 * 4;
        *(float4*)&g_h[base] = hv;
        *(float4*)&g_hri[base] = rv;
    }
    __syncthreads();

    // ---- fused G1 partial (packed over d-pairs): G1[f,d] = sum_o h[o,f]*hri[o,d] ----
    {
        int f4 = tid & 15, dg = tid >> 4;   // dg 0..15: d-quad
        u64 acc[4][2] = {};
        float cs[4] = {};
#pragma unroll 8
        for (int o = 0; o < 64; ++o) {
            float4 hv = *(const float4*)&s_htm[o * 64 + f4 * 4];
            ulonglong2 rp = *(const ulonglong2*)&s_rtm[o * 64 + dg * 4];
            u64 h0 = dup2(hv.x), h1 = dup2(hv.y), h2 = dup2(hv.z), h3 = dup2(hv.w);
            acc[0][0] = fma2(h0, rp.x, acc[0][0]); acc[0][1] = fma2(h0, rp.y, acc[0][1]);
            acc[1][0] = fma2(h1, rp.x, acc[1][0]); acc[1][1] = fma2(h1, rp.y, acc[1][1]);
            acc[2][0] = fma2(h2, rp.x, acc[2][0]); acc[2][1] = fma2(h2, rp.y, acc[2][1]);
            acc[3][0] = fma2(h3, rp.x, acc[3][0]); acc[3][1] = fma2(h3, rp.y, acc[3][1]);
            if (dg == 0) { cs[0] += hv.x; cs[1] += hv.y; cs[2] += hv.z; cs[3] += hv.w; }
        }
        int bb = tile >> 4;               // batch of this tile (16 tiles per batch)
        int gsplit = tile & 15;
        int bh = bb * NH + head;
        float* gp = g_G1p + ((size_t)(bh * NSG + gsplit)) * 4096;
#pragma unroll
        for (int i = 0; i < 4; i++) {
            ulonglong2 st; st.x = acc[i][0]; st.y = acc[i][1];
            *(ulonglong2*)&gp[(f4 * 4 + i) * 64 + dg * 4] = st;
        }
        if (dg == 0) {
#pragma unroll
            for (int i = 0; i < 4; i++) g_csp[(bh * NSG + gsplit) * 64 + f4 * 4 + i] = cs[i];
        }
    }
}

// ---------------- K4b: iterations 0+1 in closed form ----------------
__global__ void __launch_bounds__(256) alpha01_kernel() {
    __shared__ float sW[4096];
    __shared__ float sG[4096];
    __shared__ float s_c0[64], s_ai0[64], s_c1[64];
    int bh = blockIdx.x, tid = threadIdx.x;

    for (int i = tid; i < 4096; i += 256) sW[i] = g_Wn[i];
    const float* gp = g_G1p + (size_t)bh * NSG * 4096;
    for (int i = tid; i < 4096; i += 256) {
        float s = 0.f;
#pragma unroll
        for (int p = 0; p < NSG; ++p) s += gp[p * 4096 + i];
        sG[i] = s;
    }
    if (tid < 64) {
        float s = 0.f;
#pragma unroll
        for (int p = 0; p < NSG; ++p) s += g_csp[(bh * NSG + p) * 64 + tid];
        s_c0[tid] = s;
    }
    __syncthreads();
    if (tid < 64) {
        int d = tid;
        float r = 0.f;
#pragma unroll 8
        for (int f = 0; f < 64; ++f) r += s_c0[f] * sW[f * 64 + d];
        float ai = 1.f / (r + EPSV);
        s_ai0[d] = ai;
        g_aiA[bh * 64 + d] = ai;
    }
    __syncthreads();
    if (tid < 64) {
        int f = tid;
        float c1 = 0.f;
#pragma unroll 8
        for (int dd = 0; dd < 64; ++dd) {
            int d = (dd + f) & 63;
            c1 += sG[f * 64 + d] * s_ai0[d];
        }
        s_c1[f] = c1;
    }
    __syncthreads();
    if (tid < 64) {
        int d = tid;
        float r = 0.f;
#pragma unroll 8
        for (int f = 0; f < 64; ++f) r += s_c1[f] * sW[f * 64 + d];
        g_aiB[bh * 64 + d] = 1.f / (r + EPSV);
    }
}

// ---------------- K4c: pass2 — w01 per token, partial c2, partial M ----------------
__global__ void __launch_bounds__(256) pass2_kernel() {
    __shared__ __align__(16) float s_h[16][68];
    __shared__ __align__(16) float s_r[16][68];
    __shared__ float s_ai0[64], s_ai1[64];
    __shared__ float s_w[16];
    int split = blockIdx.x, bh = blockIdx.y;
    int tid = threadIdx.x;
    int f4 = tid & 15, d4 = tid >> 4;
    int lo = tid >> 4, lq = tid & 15;
    if (tid < 64) s_ai0[tid] = g_aiA[bh * 64 + tid];
    else if (tid < 128) s_ai1[tid - 64] = g_aiB[bh * 64 + tid - 64];

    const float* hb = g_h + ((size_t)bh * NS + split * OSPL) * 64;
    const float* rb = g_hri + ((size_t)bh * NS + split * OSPL) * 64;

    float accM[4][4] = {};
    float cs[4] = {};
    for (int c = 0; c < OSPL / 16; ++c) {
        *(float4*)&s_h[lo][lq * 4] = *(const float4*)&hb[(c * 16 + lo) * 64 + lq * 4];
        *(float4*)&s_r[lo][lq * 4] = *(const float4*)&rb[(c * 16 + lo) * 64 + lq * 4];
        __syncthreads();
        {
            int tt = tid >> 4;
            float4 v = *(const float4*)&s_r[tt][lq * 4];
            int base = lq * 4;
            float u0 = v.x * s_ai0[base] + v.y * s_ai0[base + 1] + v.z * s_ai0[base + 2] + v.w * s_ai0[base + 3];
            float u1 = v.x * s_ai1[base] + v.y * s_ai1[base + 1] + v.z * s_ai1[base + 2] + v.w * s_ai1[base + 3];
            u0 = red16(u0);
            u1 = red16(u1);
            if (lq == 0) s_w[tt] = u0 * u1;
        }
        __syncthreads();
#pragma unroll
        for (int o = 0; o < 16; ++o) {
            float wo = s_w[o];
            float4 hv = *(const float4*)&s_h[o][f4 * 4];
            float4 rv = *(const float4*)&s_r[o][d4 * 4];
            float hw[4] = {hv.x * wo, hv.y * wo, hv.z * wo, hv.w * wo};
            float rvv[4] = {rv.x, rv.y, rv.z, rv.w};
#pragma unroll
            for (int i = 0; i < 4; i++)
#pragma unroll
                for (int j = 0; j < 4; j++) accM[i][j] += hw[i] * rvv[j];
            if (d4 == 0) {
#pragma unroll
                for (int i = 0; i < 4; i++) cs[i] += hw[i];
            }
        }
        __syncthreads();
    }
    float* mp = g_Mp + ((size_t)(bh * NSPLIT + split)) * 4096;
#pragma unroll
    for (int i = 0; i < 4; i++)
#pragma unroll
        for (int j = 0; j < 4; j++) mp[(f4 * 4 + i) * 64 + d4 * 4 + j] = accM[i][j];
    if (d4 == 0) {
#pragma unroll
        for (int i = 0; i < 4; i++) g_c2p[(bh * NSPLIT + split) * 64 + f4 * 4 + i] = cs[i];
    }
}

// ---------------- K4d: ai2 + cfin = (sum M)·ai2 ----------------
__global__ void __launch_bounds__(256) alpha2cfin_kernel() {
    __shared__ float sW[4096];
    __shared__ float s_c2[64];
    __shared__ float s_ai2[64];
    __shared__ float s_p[4][64];
    int bh = blockIdx.x, tid = threadIdx.x;
    for (int i = tid; i < 4096; i += 256) sW[i] = g_Wn[i];
    if (tid < 64) {
        float s = 0.f;
#pragma unroll
        for (int p = 0; p < NSPLIT; ++p) s += g_c2p[(bh * NSPLIT + p) * 64 + tid];
        s_c2[tid] = s;
    }
    __syncthreads();
    if (tid < 64) {
        int d = tid;
        float r = 0.f;
#pragma unroll 8
        for (int f = 0; f < 64; ++f) r += s_c2[f] * sW[f * 64 + d];
        s_ai2[d] = 1.f / (r + EPSV);
    }
    __syncthreads();
    {
        int f = tid & 63, g = tid >> 6;
        const float* mp = g_Mp + (size_t)bh * NSPLIT * 4096;
        float partial = 0.f;
#pragma unroll
        for (int dd = 0; dd < 16; ++dd) {
            int d = g * 16 + dd;
            float mv = 0.f;
#pragma unroll
            for (int p = 0; p < NSPLIT; ++p) mv += mp[p * 4096 + f * 64 + d];
            partial += mv * s_ai2[d];
        }
        s_p[g][f] = partial;
    }
    __syncthreads();
    if (tid < 64) {
        int b = bh / NH, head = bh % NH;
        g_cfin[b * NE + head * 64 + tid] = s_p[0][tid] + s_p[1][tid] + s_p[2][tid] + s_p[3][tid];
    }
}

// ---------------- K5: out projection of the 2 unique rows ----------------
__global__ void __launch_bounds__(256) outrow_kernel(const float* __restrict__ out_w,
                                                     const float* __restrict__ out_b) {
    int b = blockIdx.y;
    int warp = threadIdx.x >> 5, lane = threadIdx.x & 31;
    int j = blockIdx.x * 8 + warp;
    const float* c = g_cfin + b * NE;
    const float* wrow = out_w + (size_t)j * NE;
    float acc = 0.f;
    for (int e = lane; e < NE; e += 32) acc += c[e] * wrow[e];
    acc = red32(acc);
    if (lane == 0) g_yrow[b * FIN + j] = acc + out_b[j];
}

// ---------------- K6: broadcast rows to all positions ----------------
__global__ void __launch_bounds__(256) bcast_kernel(float* __restrict__ out) {
    int idx = blockIdx.x * 256 + threadIdx.x;
    const int per_row = FIN / 4;
    int j4 = idx % per_row;
    int bs = idx / per_row;
    int b = bs >> 10;
    float4 v = ((const float4*)(g_yrow + b * FIN))[j4];
    ((float4*)out)[idx] = v;
}

// ---------------- launch ----------------
extern "C" void kernel_launch(void* const* d_in, const int* in_sizes, int n_in,
                              void* d_out, int out_size) {
    const float* x       = (const float*)d_in[0];
    const float* embed_w = (const float*)d_in[1];
    const float* embed_b = (const float*)d_in[2];
    const float* nnmf_w  = (const float*)d_in[3];
    const float* out_w   = (const float*)d_in[4];
    const float* out_b   = (const float*)d_in[5];
    float* out = (float*)d_out;

    static bool attr_set = false;
    if (!attr_set) {
        cudaFuncSetAttribute(nnmf_kernel, cudaFuncAttributeMaxDynamicSharedMemorySize,
                             NN_SMEM_BYTES);
        attr_set = true;
    }

    wnorm_kernel<<<1, 64>>>(nnmf_w);
    conv_kernel<<<2112, 256>>>(x, embed_w);
    embed_mma_kernel<<<dim3(NE / 64, (NB * NS) / 128), 256>>>(embed_b);
    nnmf_kernel<<<dim3((NB * NS) / 64, NH), 256, NN_SMEM_BYTES>>>();
    alpha01_kernel<<<NBH, 256>>>();
    pass2_kernel<<<dim3(NSPLIT, NBH), 256>>>();
    alpha2cfin_kernel<<<NBH, 256>>>();
    outrow_kernel<<<dim3(NE / 8, NB), 256>>>(out_w, out_b);
    bcast_kernel<<<(NB * NS * (FIN / 4)) / 256, 256>>>(out);
}

// round 9
// speedup vs baseline: 1.4626x; 1.0275x over previous
#include <cuda_runtime.h>
#include <cuda_bf16.h>
#include <cstdint>

#define NB 2
#define NS 1024
#define FIN 768
#define NE 768
#define NH 12
#define NBH (NB * NH)
#define NDH 64
#define NFH 64
#define NSPLIT 16
#define OSPL (NS / NSPLIT)   // 64 tokens per split (pass2)
#define NSG 16               // g1 splits (64 tokens each, fused in nnmf)
#define MIN_POS 1e-6f
#define EPSV 1e-20f
#define K3 2304              // tripled K for bf16-split GEMM
#define HSTR 68              // feature-major row stride (floats): 64 tokens + 4 pad
#define NN_SMEM_BYTES ((4096 + 4096 + 64 * HSTR * 2) * 4)

typedef unsigned long long u64;

// ---------------- scratch (device globals; no allocation) ----------------
__device__ __align__(16) float g_Wn[NFH * NDH];                 // normalized W [f][d]
__device__ __align__(16) float g_Wt[NDH * NFH];                 // transposed normalized W [d][f]
__device__ __align__(16) float g_rec0[NDH];                     // (1/64)*colsum(W) — iteration-0 rec
__device__ __align__(16) __nv_bfloat16 g_Abf[2048 * K3];        // [hi | hi | lo] of X
__device__ __align__(16) __nv_bfloat16 g_Wbf[768 * K3];         // [hi | lo | hi] of embed_w
__device__ __align__(16) float g_xe[NB * NS * NE];              // clipped embed output
__device__ __align__(16) float g_h[NBH * NS * NFH];             // h   [bh][s][f]
__device__ __align__(16) float g_hri[NBH * NS * NDH];           // rec*inp [bh][s][d]
__device__ __align__(16) float g_G1p[NBH * NSG * 64 * 64];      // partial h^T*hri
__device__ __align__(16) float g_Mp[NBH * NSPLIT * 64 * 64];    // partial h^T*(w01*hri)
__device__ __align__(16) float g_csp[NBH * NSG * 64];           // partial colsum(h)
__device__ __align__(16) float g_c2p[NBH * NSPLIT * 64];        // partial c2
__device__ __align__(16) float g_aiA[NBH * 64];                 // arec_inv iter0
__device__ __align__(16) float g_aiB[NBH * 64];                 // arec_inv iter1
__device__ __align__(16) float g_cfin[NB * NE];                 // final mixed row per batch
__device__ __align__(16) float g_yrow[NB * FIN];                // final projected row per batch

// ---------------- helpers ----------------
__device__ __forceinline__ float red16(float v) {
    v += __shfl_xor_sync(0xffffffffu, v, 8);
    v += __shfl_xor_sync(0xffffffffu, v, 4);
    v += __shfl_xor_sync(0xffffffffu, v, 2);
    v += __shfl_xor_sync(0xffffffffu, v, 1);
    return v;
}
__device__ __forceinline__ float red32(float v) {
    v += __shfl_xor_sync(0xffffffffu, v, 16);
    return red16(v);
}
__device__ __forceinline__ uint32_t pack2(__nv_bfloat16 a, __nv_bfloat16 b) {
    __nv_bfloat162 t = __halves2bfloat162(a, b);
    return *reinterpret_cast<uint32_t*>(&t);
}
__device__ __forceinline__ void ldsm4(uint32_t* r, uint32_t addr) {
    asm volatile("ldmatrix.sync.aligned.m8n8.x4.shared.b16 {%0,%1,%2,%3}, [%4];"
                 : "=r"(r[0]), "=r"(r[1]), "=r"(r[2]), "=r"(r[3]) : "r"(addr));
}
__device__ __forceinline__ void mma_bf16(float* c, const uint32_t* a, uint32_t b0, uint32_t b1) {
    asm volatile(
        "mma.sync.aligned.m16n8k16.row.col.f32.bf16.bf16.f32 "
        "{%0,%1,%2,%3}, {%4,%5,%6,%7}, {%8,%9}, {%0,%1,%2,%3};\n"
        : "+f"(c[0]), "+f"(c[1]), "+f"(c[2]), "+f"(c[3])
        : "r"(a[0]), "r"(a[1]), "r"(a[2]), "r"(a[3]), "r"(b0), "r"(b1));
}
// packed fp32x2 helpers (FFMA2 is PTX-only; ptxas never auto-fuses)
__device__ __forceinline__ u64 fma2(u64 a, u64 b, u64 c) {
    u64 d;
    asm("fma.rn.f32x2 %0, %1, %2, %3;" : "=l"(d) : "l"(a), "l"(b), "l"(c));
    return d;
}
__device__ __forceinline__ u64 dup2(float x) {
    u64 d;
    uint32_t r = __float_as_uint(x);
    asm("mov.b64 %0, {%1, %2};" : "=l"(d) : "r"(r), "r"(r));
    return d;
}
__device__ __forceinline__ float2 unpk2(u64 v) {
    uint32_t lo, hi;
    asm("mov.b64 {%0, %1}, %2;" : "=r"(lo), "=r"(hi) : "l"(v));
    return make_float2(__uint_as_float(lo), __uint_as_float(hi));
}

// ---------------- K1: normalize nnmf_w rows (+ transpose + rec0) ----------------
__global__ void wnorm_kernel(const float* __restrict__ nnmf_w) {
    int f = threadIdx.x;  // 0..63
    float s = 0.f;
#pragma unroll
    for (int d = 0; d < NDH; ++d) s += nnmf_w[f * NDH + d];
    s = fmaxf(s, EPSV);
    float inv = 1.f / s;
#pragma unroll
    for (int d = 0; d < NDH; ++d) {
        float v = nnmf_w[f * NDH + d] * inv;
        g_Wn[f * NDH + d] = v;
        g_Wt[d * NFH + f] = v;
    }
    __syncthreads();
    // rec0[d] = (1/64) * sum_f Wn[f][d]  (iteration-0 reconstruction, uniform h)
    {
        int d = f;
        float c = 0.f;
#pragma unroll
        for (int ff = 0; ff < NFH; ++ff) c += g_Wn[ff * NDH + d];
        g_rec0[d] = c * (1.f / 64.f);
    }
}

// ---------------- K2a: bf16 split conversion of X and embed_w ----------------
__global__ void __launch_bounds__(256) conv_kernel(const float* __restrict__ X,
                                                   const float* __restrict__ Wm) {
    int i = blockIdx.x * 256 + threadIdx.x;
    int row = i / 192, q = (i % 192) * 4;
    const float* src = (row < 2048) ? X + (size_t)row * 768 + q
                                    : Wm + (size_t)(row - 2048) * 768 + q;
    float4 v = *(const float4*)src;
    float xs[4] = {v.x, v.y, v.z, v.w};
    __nv_bfloat16 hi[4], lo[4];
#pragma unroll
    for (int j = 0; j < 4; ++j) {
        hi[j] = __float2bfloat16(xs[j]);
        lo[j] = __float2bfloat16(xs[j] - __bfloat162float(hi[j]));
    }
    uint2 hv = make_uint2(pack2(hi[0], hi[1]), pack2(hi[2], hi[3]));
    uint2 lv = make_uint2(pack2(lo[0], lo[1]), pack2(lo[2], lo[3]));
    if (row < 2048) {
        __nv_bfloat16* dst = g_Abf + (size_t)row * K3 + q;
        *(uint2*)(dst)        = hv;
        *(uint2*)(dst + 768)  = hv;
        *(uint2*)(dst + 1536) = lv;
    } else {
        __nv_bfloat16* dst = g_Wbf + (size_t)(row - 2048) * K3 + q;
        *(uint2*)(dst)        = hv;
        *(uint2*)(dst + 768)  = lv;
        *(uint2*)(dst + 1536) = hv;
    }
}

// ---------------- K2b: embed GEMM via mma.sync bf16, K=2304 ----------------
__global__ void __launch_bounds__(256) embed_mma_kernel(const float* __restrict__ bias) {
    __shared__ __align__(16) __nv_bfloat16 As[128 * 40];
    __shared__ __align__(16) __nv_bfloat16 Bs[64 * 40];
    int tid = threadIdx.x;
    int bm = blockIdx.y * 128, bn = blockIdx.x * 64;
    int wid = tid >> 5, lane = tid & 31;
    int wm = wid & 3, wn = wid >> 2;

    float c[2][4][4];
#pragma unroll
    for (int mt = 0; mt < 2; ++mt)
#pragma unroll
        for (int nt = 0; nt < 4; ++nt)
#pragma unroll
            for (int r = 0; r < 4; ++r) c[mt][nt][r] = 0.f;

    uint32_t a_base[2], b_base[2];
#pragma unroll
    for (int mt = 0; mt < 2; ++mt) {
        int row = wm * 32 + mt * 16 + (lane & 15);
        int colhalf = lane >> 4;
        a_base[mt] = (uint32_t)__cvta_generic_to_shared(&As[row * 40 + colhalf * 8]);
    }
#pragma unroll
    for (int bt = 0; bt < 2; ++bt) {
        int n = wn * 32 + bt * 16 + ((lane >> 4) << 3) + (lane & 7);
        int khalf = (lane >> 3) & 1;
        b_base[bt] = (uint32_t)__cvta_generic_to_shared(&Bs[n * 40 + khalf * 8]);
    }

    for (int ks = 0; ks < K3 / 32; ++ks) {
        int k0 = ks * 32;
#pragma unroll
        for (int r = 0; r < 2; ++r) {
            int q = tid + r * 256;
            int m = q >> 2, cch = q & 3;
            *(uint4*)&As[m * 40 + cch * 8] =
                *(const uint4*)&g_Abf[(size_t)(bm + m) * K3 + k0 + cch * 8];
        }
        {
            int n = tid >> 2, cch = tid & 3;
            *(uint4*)&Bs[n * 40 + cch * 8] =
                *(const uint4*)&g_Wbf[(size_t)(bn + n) * K3 + k0 + cch * 8];
        }
        __syncthreads();
#pragma unroll
        for (int kh = 0; kh < 2; ++kh) {
            int kk = kh * 16;
            uint32_t a[2][4], b[2][4];
            ldsm4(a[0], a_base[0] + kk * 2);
            ldsm4(a[1], a_base[1] + kk * 2);
            ldsm4(b[0], b_base[0] + kk * 2);
            ldsm4(b[1], b_base[1] + kk * 2);
#pragma unroll
            for (int mt = 0; mt < 2; ++mt)
#pragma unroll
                for (int nt = 0; nt < 4; ++nt)
                    mma_bf16(c[mt][nt], a[mt], b[nt >> 1][(nt & 1) * 2], b[nt >> 1][(nt & 1) * 2 + 1]);
        }
        __syncthreads();
    }

#pragma unroll
    for (int mt = 0; mt < 2; ++mt) {
#pragma unroll
        for (int nt = 0; nt < 4; ++nt) {
            int m0 = bm + wm * 32 + mt * 16 + (lane >> 2);
            int n0 = bn + wn * 32 + nt * 8 + (lane & 3) * 2;
            float2 bv = *(const float2*)&bias[n0];
            float2 o0, o1;
            o0.x = fmaxf(c[mt][nt][0] + bv.x, MIN_POS);
            o0.y = fmaxf(c[mt][nt][1] + bv.y, MIN_POS);
            o1.x = fmaxf(c[mt][nt][2] + bv.x, MIN_POS);
            o1.y = fmaxf(c[mt][nt][3] + bv.y, MIN_POS);
            *(float2*)&g_xe[(size_t)m0 * NE + n0] = o0;
            *(float2*)&g_xe[(size_t)(m0 + 8) * NE + n0] = o1;
        }
    }
}

// ---------------- K3: fused NNMF, FFMA2-packed, pm=1 identity, it0 folded ----------------
// thread = (g 0..15: token-group of 4, d4 0..15: feature-quad)
__global__ void __launch_bounds__(256, 3) nnmf_kernel() {
    extern __shared__ float sm[];
    float* sW   = sm;                       // [f][d], stride 64
    float* sWt  = sm + 4096;                // [d][f], stride 64
    float* s_ht = sm + 8192;                // [f][tok], stride HSTR
    float* s_rt = sm + 8192 + 64 * HSTR;    // [d][tok], stride HSTR

    int head = blockIdx.y;
    int tile = blockIdx.x;       // 0..31 (64 tokens each)
    int tid = threadIdx.x;
    int d4 = tid & 15;
    int g = tid >> 4;            // 0..15
    int tokbase = tile * 64;

    for (int i = tid; i < 4096; i += 256) sW[i] = g_Wn[i];
    for (int i = tid; i < 4096; i += 256) sWt[i] = g_Wt[i];

    // inp[t][i]: l1-normalized slice for tokens g*4+t, dims d4*4+i
    float inp[4][4];
#pragma unroll
    for (int t = 0; t < 4; ++t) {
        int tok = tokbase + g * 4 + t;
        float4 x = *(const float4*)&g_xe[(size_t)tok * NE + head * 64 + d4 * 4];
        float s = red16(x.x + x.y + x.z + x.w);
        float iv = 1.f / fmaxf(s, EPSV);
        inp[t][0] = x.x * iv; inp[t][1] = x.y * iv; inp[t][2] = x.z * iv; inp[t][3] = x.w * iv;
    }

    // iteration-0 rec is the precomputed rec0 vector (uniform h); pm = 1 analytically
    {
        float4 r0 = *(const float4*)&g_rec0[d4 * 4];
        float rd[4] = {1.f / fmaxf(r0.x, MIN_POS), 1.f / fmaxf(r0.y, MIN_POS),
                       1.f / fmaxf(r0.z, MIN_POS), 1.f / fmaxf(r0.w, MIN_POS)};
#pragma unroll
        for (int i = 0; i < 4; ++i)
            *(float4*)&s_rt[(d4 * 4 + i) * HSTR + g * 4] =
                make_float4(inp[0][i] * rd[i], inp[1][i] * rd[i],
                            inp[2][i] * rd[i], inp[3][i] * rd[i]);
    }
    __syncthreads();

    const float hinit = 1.f / 64.f;
    float hr[4][4];
    float ri[4][4];   // hri = rec_clamped * inp (pm=1), captured in last rec phase

    for (int it = 0; it < 3; ++it) {
        if (it > 0) {
            // rec-phase: a[i][p] packed over token-pairs; row-sum == 1 analytically
            u64 a[4][2] = {};
#pragma unroll 8
            for (int ff = 0; ff < 64; ++ff) {
                ulonglong2 hp = *(const ulonglong2*)&s_ht[ff * HSTR + g * 4];
                float4 w = *(const float4*)&sW[ff * 64 + d4 * 4];
                u64 w0 = dup2(w.x), w1 = dup2(w.y), w2 = dup2(w.z), w3 = dup2(w.w);
                a[0][0] = fma2(w0, hp.x, a[0][0]); a[0][1] = fma2(w0, hp.y, a[0][1]);
                a[1][0] = fma2(w1, hp.x, a[1][0]); a[1][1] = fma2(w1, hp.y, a[1][1]);
                a[2][0] = fma2(w2, hp.x, a[2][0]); a[2][1] = fma2(w2, hp.y, a[2][1]);
                a[3][0] = fma2(w3, hp.x, a[3][0]); a[3][1] = fma2(w3, hp.y, a[3][1]);
            }
            float av[4][4];
#pragma unroll
            for (int i = 0; i < 4; ++i) {
                float2 u0 = unpk2(a[i][0]), u1 = unpk2(a[i][1]);
                av[0][i] = fmaxf(u0.x, MIN_POS); av[1][i] = fmaxf(u0.y, MIN_POS);
                av[2][i] = fmaxf(u1.x, MIN_POS); av[3][i] = fmaxf(u1.y, MIN_POS);
            }
            if (it == 2) {
#pragma unroll
                for (int t = 0; t < 4; ++t)
#pragma unroll
                    for (int i = 0; i < 4; ++i) ri[t][i] = av[t][i] * inp[t][i];
            }
            // ratio = inp / rec_clamped (pm = 1)
#pragma unroll
            for (int i = 0; i < 4; ++i) {
                float q0 = __fdividef(inp[0][i], av[0][i]);
                float q1 = __fdividef(inp[1][i], av[1][i]);
                float q2 = __fdividef(inp[2][i], av[2][i]);
                float q3 = __fdividef(inp[3][i], av[3][i]);
                *(float4*)&s_rt[(d4 * 4 + i) * HSTR + g * 4] = make_float4(q0, q1, q2, q3);
            }
            __syncthreads();
        }

        // t-phase: b[i][p] packed
        u64 b[4][2] = {};
#pragma unroll 8
        for (int d = 0; d < 64; ++d) {
            ulonglong2 rp = *(const ulonglong2*)&s_rt[d * HSTR + g * 4];
            float4 wt = *(const float4*)&sWt[d * 64 + d4 * 4];
            u64 w0 = dup2(wt.x), w1 = dup2(wt.y), w2 = dup2(wt.z), w3 = dup2(wt.w);
            b[0][0] = fma2(w0, rp.x, b[0][0]); b[0][1] = fma2(w0, rp.y, b[0][1]);
            b[1][0] = fma2(w1, rp.x, b[1][0]); b[1][1] = fma2(w1, rp.y, b[1][1]);
            b[2][0] = fma2(w2, rp.x, b[2][0]); b[2][1] = fma2(w2, rp.y, b[2][1]);
            b[3][0] = fma2(w3, rp.x, b[3][0]); b[3][1] = fma2(w3, rp.y, b[3][1]);
        }
        float bv[4][4];
#pragma unroll
        for (int i = 0; i < 4; ++i) {
            float2 u0 = unpk2(b[i][0]), u1 = unpk2(b[i][1]);
            bv[0][i] = u0.x; bv[1][i] = u0.y; bv[2][i] = u1.x; bv[3][i] = u1.y;
        }
#pragma unroll
        for (int t = 0; t < 4; ++t) {
            float hn[4];
#pragma unroll
            for (int i = 0; i < 4; ++i) {
                float pre = (it == 0) ? hinit : hr[t][i];
                hn[i] = fmaxf(pre * bv[t][i], MIN_POS);
            }
            float hs = red16(hn[0] + hn[1] + hn[2] + hn[3]);
            float ih = 1.f / fmaxf(hs, EPSV);
#pragma unroll
            for (int i = 0; i < 4; ++i) hr[t][i] = hn[i] * ih;
        }
        if (it < 2) {
#pragma unroll
            for (int i = 0; i < 4; ++i)
                *(float4*)&s_ht[(d4 * 4 + i) * HSTR + g * 4] =
                    make_float4(hr[0][i], hr[1][i], hr[2][i], hr[3][i]);
            __syncthreads();
        }
    }

    // final l1norm of h (matches reference's extra normalize)
    float hf[4][4];
#pragma unroll
    for (int t = 0; t < 4; ++t) {
        float hs = red16(hr[t][0] + hr[t][1] + hr[t][2] + hr[t][3]);
        float ih = 1.f / fmaxf(hs, EPSV);
#pragma unroll
        for (int i = 0; i < 4; ++i) hf[t][i] = hr[t][i] * ih;
    }
    __syncthreads();   // done with sW/sWt/s_ht/s_rt before region reuse

    // token-major copies into reused W regions + gmem writes
    float* s_htm = sm;           // [tok][f], stride 64 (64*64 = 4096 exact)
    float* s_rtm = sm + 4096;    // [tok][d], stride 64
#pragma unroll
    for (int t = 0; t < 4; ++t) {
        int tl = g * 4 + t;
        float4 hv = make_float4(hf[t][0], hf[t][1], hf[t][2], hf[t][3]);
        float4 rv = make_float4(ri[t][0], ri[t][1], ri[t][2], ri[t][3]);
        *(float4*)&s_htm[tl * 64 + d4 * 4] = hv;
        *(float4*)&s_rtm[tl * 64 + d4 * 4] = rv;
        int token = tokbase + tl;
        int bi = token >> 10, si = token & 1023;
        size_t base = ((size_t)((bi * NH + head) * NS + si)) * 64 + d4 * 4;
        *(float4*)&g_h[base] = hv;
        *(float4*)&g_hri[base] = rv;
    }
    __syncthreads();

    // ---- fused G1 partial (packed over d-pairs): G1[f,d] = sum_o h[o,f]*hri[o,d] ----
    {
        int f4 = tid & 15, dg = tid >> 4;   // dg 0..15: d-quad
        u64 acc[4][2] = {};
        float cs[4] = {};
#pragma unroll 8
        for (int o = 0; o < 64; ++o) {
            float4 hv = *(const float4*)&s_htm[o * 64 + f4 * 4];
            ulonglong2 rp = *(const ulonglong2*)&s_rtm[o * 64 + dg * 4];
            u64 h0 = dup2(hv.x), h1 = dup2(hv.y), h2 = dup2(hv.z), h3 = dup2(hv.w);
            acc[0][0] = fma2(h0, rp.x, acc[0][0]); acc[0][1] = fma2(h0, rp.y, acc[0][1]);
            acc[1][0] = fma2(h1, rp.x, acc[1][0]); acc[1][1] = fma2(h1, rp.y, acc[1][1]);
            acc[2][0] = fma2(h2, rp.x, acc[2][0]); acc[2][1] = fma2(h2, rp.y, acc[2][1]);
            acc[3][0] = fma2(h3, rp.x, acc[3][0]); acc[3][1] = fma2(h3, rp.y, acc[3][1]);
            if (dg == 0) { cs[0] += hv.x; cs[1] += hv.y; cs[2] += hv.z; cs[3] += hv.w; }
        }
        int bb = tile >> 4;               // batch of this tile (16 tiles per batch)
        int gsplit = tile & 15;
        int bh = bb * NH + head;
        float* gp = g_G1p + ((size_t)(bh * NSG + gsplit)) * 4096;
#pragma unroll
        for (int i = 0; i < 4; i++) {
            ulonglong2 st; st.x = acc[i][0]; st.y = acc[i][1];
            *(ulonglong2*)&gp[(f4 * 4 + i) * 64 + dg * 4] = st;
        }
        if (dg == 0) {
#pragma unroll
            for (int i = 0; i < 4; i++) g_csp[(bh * NSG + gsplit) * 64 + f4 * 4 + i] = cs[i];
        }
    }
}

// ---------------- K4b: iterations 0+1 in closed form ----------------
__global__ void __launch_bounds__(256) alpha01_kernel() {
    __shared__ float sW[4096];
    __shared__ float sG[4096];
    __shared__ float s_c0[64], s_ai0[64], s_c1[64];
    int bh = blockIdx.x, tid = threadIdx.x;

    for (int i = tid; i < 4096; i += 256) sW[i] = g_Wn[i];
    const float* gp = g_G1p + (size_t)bh * NSG * 4096;
    for (int i = tid; i < 4096; i += 256) {
        float s = 0.f;
#pragma unroll
        for (int p = 0; p < NSG; ++p) s += gp[p * 4096 + i];
        sG[i] = s;
    }
    if (tid < 64) {
        float s = 0.f;
#pragma unroll
        for (int p = 0; p < NSG; ++p) s += g_csp[(bh * NSG + p) * 64 + tid];
        s_c0[tid] = s;
    }
    __syncthreads();
    if (tid < 64) {
        int d = tid;
        float r = 0.f;
#pragma unroll 8
        for (int f = 0; f < 64; ++f) r += s_c0[f] * sW[f * 64 + d];
        float ai = 1.f / (r + EPSV);
        s_ai0[d] = ai;
        g_aiA[bh * 64 + d] = ai;
    }
    __syncthreads();
    if (tid < 64) {
        int f = tid;
        float c1 = 0.f;
#pragma unroll 8
        for (int dd = 0; dd < 64; ++dd) {
            int d = (dd + f) & 63;
            c1 += sG[f * 64 + d] * s_ai0[d];
        }
        s_c1[f] = c1;
    }
    __syncthreads();
    if (tid < 64) {
        int d = tid;
        float r = 0.f;
#pragma unroll 8
        for (int f = 0; f < 64; ++f) r += s_c1[f] * sW[f * 64 + d];
        g_aiB[bh * 64 + d] = 1.f / (r + EPSV);
    }
}

// ---------------- K4c: pass2 — w01 per token, partial c2, partial M ----------------
__global__ void __launch_bounds__(256) pass2_kernel() {
    __shared__ __align__(16) float s_h[16][68];
    __shared__ __align__(16) float s_r[16][68];
    __shared__ float s_ai0[64], s_ai1[64];
    __shared__ float s_w[16];
    int split = blockIdx.x, bh = blockIdx.y;
    int tid = threadIdx.x;
    int f4 = tid & 15, d4 = tid >> 4;
    int lo = tid >> 4, lq = tid & 15;
    if (tid < 64) s_ai0[tid] = g_aiA[bh * 64 + tid];
    else if (tid < 128) s_ai1[tid - 64] = g_aiB[bh * 64 + tid - 64];

    const float* hb = g_h + ((size_t)bh * NS + split * OSPL) * 64;
    const float* rb = g_hri + ((size_t)bh * NS + split * OSPL) * 64;

    float accM[4][4] = {};
    float cs[4] = {};
    for (int c = 0; c < OSPL / 16; ++c) {
        *(float4*)&s_h[lo][lq * 4] = *(const float4*)&hb[(c * 16 + lo) * 64 + lq * 4];
        *(float4*)&s_r[lo][lq * 4] = *(const float4*)&rb[(c * 16 + lo) * 64 + lq * 4];
        __syncthreads();
        {
            int tt = tid >> 4;
            float4 v = *(const float4*)&s_r[tt][lq * 4];
            int base = lq * 4;
            float u0 = v.x * s_ai0[base] + v.y * s_ai0[base + 1] + v.z * s_ai0[base + 2] + v.w * s_ai0[base + 3];
            float u1 = v.x * s_ai1[base] + v.y * s_ai1[base + 1] + v.z * s_ai1[base + 2] + v.w * s_ai1[base + 3];
            u0 = red16(u0);
            u1 = red16(u1);
            if (lq == 0) s_w[tt] = u0 * u1;
        }
        __syncthreads();
#pragma unroll
        for (int o = 0; o < 16; ++o) {
            float wo = s_w[o];
            float4 hv = *(const float4*)&s_h[o][f4 * 4];
            float4 rv = *(const float4*)&s_r[o][d4 * 4];
            float hw[4] = {hv.x * wo, hv.y * wo, hv.z * wo, hv.w * wo};
            float rvv[4] = {rv.x, rv.y, rv.z, rv.w};
#pragma unroll
            for (int i = 0; i < 4; i++)
#pragma unroll
                for (int j = 0; j < 4; j++) accM[i][j] += hw[i] * rvv[j];
            if (d4 == 0) {
#pragma unroll
                for (int i = 0; i < 4; i++) cs[i] += hw[i];
            }
        }
        __syncthreads();
    }
    float* mp = g_Mp + ((size_t)(bh * NSPLIT + split)) * 4096;
#pragma unroll
    for (int i = 0; i < 4; i++)
#pragma unroll
        for (int j = 0; j < 4; j++) mp[(f4 * 4 + i) * 64 + d4 * 4 + j] = accM[i][j];
    if (d4 == 0) {
#pragma unroll
        for (int i = 0; i < 4; i++) g_c2p[(bh * NSPLIT + split) * 64 + f4 * 4 + i] = cs[i];
    }
}

// ---------------- K4d: ai2 + cfin = (sum M)·ai2 ----------------
__global__ void __launch_bounds__(256) alpha2cfin_kernel() {
    __shared__ float sW[4096];
    __shared__ float s_c2[64];
    __shared__ float s_ai2[64];
    __shared__ float s_p[4][64];
    int bh = blockIdx.x, tid = threadIdx.x;
    for (int i = tid; i < 4096; i += 256) sW[i] = g_Wn[i];
    if (tid < 64) {
        float s = 0.f;
#pragma unroll
        for (int p = 0; p < NSPLIT; ++p) s += g_c2p[(bh * NSPLIT + p) * 64 + tid];
        s_c2[tid] = s;
    }
    __syncthreads();
    if (tid < 64) {
        int d = tid;
        float r = 0.f;
#pragma unroll 8
        for (int f = 0; f < 64; ++f) r += s_c2[f] * sW[f * 64 + d];
        s_ai2[d] = 1.f / (r + EPSV);
    }
    __syncthreads();
    {
        int f = tid & 63, g = tid >> 6;
        const float* mp = g_Mp + (size_t)bh * NSPLIT * 4096;
        float partial = 0.f;
#pragma unroll
        for (int dd = 0; dd < 16; ++dd) {
            int d = g * 16 + dd;
            float mv = 0.f;
#pragma unroll
            for (int p = 0; p < NSPLIT; ++p) mv += mp[p * 4096 + f * 64 + d];
            partial += mv * s_ai2[d];
        }
        s_p[g][f] = partial;
    }
    __syncthreads();
    if (tid < 64) {
        int b = bh / NH, head = bh % NH;
        g_cfin[b * NE + head * 64 + tid] = s_p[0][tid] + s_p[1][tid] + s_p[2][tid] + s_p[3][tid];
    }
}

// ---------------- K5: out projection of the 2 unique rows ----------------
__global__ void __launch_bounds__(256) outrow_kernel(const float* __restrict__ out_w,
                                                     const float* __restrict__ out_b) {
    int b = blockIdx.y;
    int warp = threadIdx.x >> 5, lane = threadIdx.x & 31;
    int j = blockIdx.x * 8 + warp;
    const float* c = g_cfin + b * NE;
    const float* wrow = out_w + (size_t)j * NE;
    float acc = 0.f;
    for (int e = lane; e < NE; e += 32) acc += c[e] * wrow[e];
    acc = red32(acc);
    if (lane == 0) g_yrow[b * FIN + j] = acc + out_b[j];
}

// ---------------- K6: broadcast rows to all positions ----------------
__global__ void __launch_bounds__(256) bcast_kernel(float* __restrict__ out) {
    int idx = blockIdx.x * 256 + threadIdx.x;
    const int per_row = FIN / 4;
    int j4 = idx % per_row;
    int bs = idx / per_row;
    int b = bs >> 10;
    float4 v = ((const float4*)(g_yrow + b * FIN))[j4];
    ((float4*)out)[idx] = v;
}

// ---------------- launch ----------------
extern "C" void kernel_launch(void* const* d_in, const int* in_sizes, int n_in,
                              void* d_out, int out_size) {
    const float* x       = (const float*)d_in[0];
    const float* embed_w = (const float*)d_in[1];
    const float* embed_b = (const float*)d_in[2];
    const float* nnmf_w  = (const float*)d_in[3];
    const float* out_w   = (const float*)d_in[4];
    const float* out_b   = (const float*)d_in[5];
    float* out = (float*)d_out;

    static bool attr_set = false;
    if (!attr_set) {
        cudaFuncSetAttribute(nnmf_kernel, cudaFuncAttributeMaxDynamicSharedMemorySize,
                             NN_SMEM_BYTES);
        attr_set = true;
    }

    wnorm_kernel<<<1, 64>>>(nnmf_w);
    conv_kernel<<<2112, 256>>>(x, embed_w);
    embed_mma_kernel<<<dim3(NE / 64, (NB * NS) / 128), 256>>>(embed_b);
    nnmf_kernel<<<dim3((NB * NS) / 64, NH), 256, NN_SMEM_BYTES>>>();
    alpha01_kernel<<<NBH, 256>>>();
    pass2_kernel<<<dim3(NSPLIT, NBH), 256>>>();
    alpha2cfin_kernel<<<NBH, 256>>>();
    outrow_kernel<<<dim3(NE / 8, NB), 256>>>(out_w, out_b);
    bcast_kernel<<<(NB * NS * (FIN / 4)) / 256, 256>>>(out);
}

// round 10
// speedup vs baseline: 1.4649x; 1.0016x over previous
#include <cuda_runtime.h>
#include <cuda_bf16.h>
#include <cstdint>

#define NB 2
#define NS 1024
#define FIN 768
#define NE 768
#define NH 12
#define NBH (NB * NH)
#define NDH 64
#define NFH 64
#define NSPLIT 16
#define OSPL (NS / NSPLIT)   // 64 tokens per split (pass2)
#define NSG 16               // g1 splits (64 tokens each, fused in nnmf)
#define MIN_POS 1e-6f
#define EPSV 1e-20f
#define K2 1536              // [hi|lo] storage width for bf16-split GEMM
#define HSTR 68              // feature-major row stride (floats): 64 tokens + 4 pad
#define NN_SMEM_BYTES ((4096 + 4096 + 64 * HSTR * 2) * 4)

typedef unsigned long long u64;

// ---------------- scratch (device globals; no allocation) ----------------
__device__ __align__(16) float g_Wn[NFH * NDH];                 // normalized W [f][d]
__device__ __align__(16) float g_Wt[NDH * NFH];                 // transposed normalized W [d][f]
__device__ __align__(16) float g_rec0[NDH];                     // (1/64)*colsum(W) — iteration-0 rec
__device__ __align__(16) __nv_bfloat16 g_Abf[2048 * K2];        // [hi | lo] of X
__device__ __align__(16) __nv_bfloat16 g_Wbf[768 * K2];         // [hi | lo] of embed_w
__device__ __align__(16) float g_xe[NB * NS * NE];              // clipped embed output
__device__ __align__(16) float g_h[NBH * NS * NFH];             // h   [bh][s][f]
__device__ __align__(16) float g_hri[NBH * NS * NDH];           // rec*inp [bh][s][d]
__device__ __align__(16) float g_G1p[NBH * NSG * 64 * 64];      // partial h^T*hri
__device__ __align__(16) float g_Mp[NBH * NSPLIT * 64 * 64];    // partial h^T*(w01*hri)
__device__ __align__(16) float g_csp[NBH * NSG * 64];           // partial colsum(h)
__device__ __align__(16) float g_c2p[NBH * NSPLIT * 64];        // partial c2
__device__ __align__(16) float g_aiA[NBH * 64];                 // arec_inv iter0
__device__ __align__(16) float g_aiB[NBH * 64];                 // arec_inv iter1
__device__ __align__(16) float g_cfin[NB * NE];                 // final mixed row per batch
__device__ __align__(16) float g_yrow[NB * FIN];                // final projected row per batch

// ---------------- helpers ----------------
__device__ __forceinline__ float red16(float v) {
    v += __shfl_xor_sync(0xffffffffu, v, 8);
    v += __shfl_xor_sync(0xffffffffu, v, 4);
    v += __shfl_xor_sync(0xffffffffu, v, 2);
    v += __shfl_xor_sync(0xffffffffu, v, 1);
    return v;
}
__device__ __forceinline__ float red32(float v) {
    v += __shfl_xor_sync(0xffffffffu, v, 16);
    return red16(v);
}
__device__ __forceinline__ uint32_t pack2(__nv_bfloat16 a, __nv_bfloat16 b) {
    __nv_bfloat162 t = __halves2bfloat162(a, b);
    return *reinterpret_cast<uint32_t*>(&t);
}
__device__ __forceinline__ void ldsm4(uint32_t* r, uint32_t addr) {
    asm volatile("ldmatrix.sync.aligned.m8n8.x4.shared.b16 {%0,%1,%2,%3}, [%4];"
                 : "=r"(r[0]), "=r"(r[1]), "=r"(r[2]), "=r"(r[3]) : "r"(addr));
}
__device__ __forceinline__ void mma_bf16(float* c, const uint32_t* a, uint32_t b0, uint32_t b1) {
    asm volatile(
        "mma.sync.aligned.m16n8k16.row.col.f32.bf16.bf16.f32 "
        "{%0,%1,%2,%3}, {%4,%5,%6,%7}, {%8,%9}, {%0,%1,%2,%3};\n"
        : "+f"(c[0]), "+f"(c[1]), "+f"(c[2]), "+f"(c[3])
        : "r"(a[0]), "r"(a[1]), "r"(a[2]), "r"(a[3]), "r"(b0), "r"(b1));
}
// packed fp32x2 helpers (FFMA2 is PTX-only; ptxas never auto-fuses)
__device__ __forceinline__ u64 fma2(u64 a, u64 b, u64 c) {
    u64 d;
    asm("fma.rn.f32x2 %0, %1, %2, %3;" : "=l"(d) : "l"(a), "l"(b), "l"(c));
    return d;
}
__device__ __forceinline__ u64 dup2(float x) {
    u64 d;
    uint32_t r = __float_as_uint(x);
    asm("mov.b64 %0, {%1, %2};" : "=l"(d) : "r"(r), "r"(r));
    return d;
}
__device__ __forceinline__ float2 unpk2(u64 v) {
    uint32_t lo, hi;
    asm("mov.b64 {%0, %1}, %2;" : "=r"(lo), "=r"(hi) : "l"(v));
    return make_float2(__uint_as_float(lo), __uint_as_float(hi));
}

// ---------------- K2a: bf16 split conversion ([hi|lo]) + fused wnorm (last block) ----------------
// 2816 data rows * 192 float4 = 540672 items in blocks 0..2111; block 2112 does wnorm.
__global__ void __launch_bounds__(256) conv_kernel(const float* __restrict__ X,
                                                   const float* __restrict__ Wm,
                                                   const float* __restrict__ nnmf_w) {
    if (blockIdx.x == 2112) {
        int f = threadIdx.x;
        if (f < 64) {
            float s = 0.f;
#pragma unroll
            for (int d = 0; d < NDH; ++d) s += nnmf_w[f * NDH + d];
            s = fmaxf(s, EPSV);
            float inv = 1.f / s;
#pragma unroll
            for (int d = 0; d < NDH; ++d) {
                float v = nnmf_w[f * NDH + d] * inv;
                g_Wn[f * NDH + d] = v;
                g_Wt[d * NFH + f] = v;
            }
        }
        __syncthreads();
        if (f < 64) {
            float c = 0.f;
#pragma unroll
            for (int ff = 0; ff < NFH; ++ff) c += g_Wn[ff * NDH + f];
            g_rec0[f] = c * (1.f / 64.f);
        }
        return;
    }
    int i = blockIdx.x * 256 + threadIdx.x;
    int row = i / 192, q = (i % 192) * 4;
    const float* src = (row < 2048) ? X + (size_t)row * 768 + q
                                    : Wm + (size_t)(row - 2048) * 768 + q;
    float4 v = *(const float4*)src;
    float xs[4] = {v.x, v.y, v.z, v.w};
    __nv_bfloat16 hi[4], lo[4];
#pragma unroll
    for (int j = 0; j < 4; ++j) {
        hi[j] = __float2bfloat16(xs[j]);
        lo[j] = __float2bfloat16(xs[j] - __bfloat162float(hi[j]));
    }
    uint2 hv = make_uint2(pack2(hi[0], hi[1]), pack2(hi[2], hi[3]));
    uint2 lv = make_uint2(pack2(lo[0], lo[1]), pack2(lo[2], lo[3]));
    __nv_bfloat16* dst = (row < 2048) ? g_Abf + (size_t)row * K2 + q
                                      : g_Wbf + (size_t)(row - 2048) * K2 + q;
    *(uint2*)(dst)       = hv;
    *(uint2*)(dst + 768) = lv;
}

// ---------------- K2b: embed GEMM via mma.sync bf16, virtual K=2304 over [hi|lo] ----------------
// segment map: A uses hi,hi,lo; B uses hi,lo,hi.
__global__ void __launch_bounds__(256) embed_mma_kernel(const float* __restrict__ bias) {
    __shared__ __align__(16) __nv_bfloat16 As[128 * 40];
    __shared__ __align__(16) __nv_bfloat16 Bs[64 * 40];
    int tid = threadIdx.x;
    int bm = blockIdx.y * 128, bn = blockIdx.x * 64;
    int wid = tid >> 5, lane = tid & 31;
    int wm = wid & 3, wn = wid >> 2;

    float c[2][4][4];
#pragma unroll
    for (int mt = 0; mt < 2; ++mt)
#pragma unroll
        for (int nt = 0; nt < 4; ++nt)
#pragma unroll
            for (int r = 0; r < 4; ++r) c[mt][nt][r] = 0.f;

    uint32_t a_base[2], b_base[2];
#pragma unroll
    for (int mt = 0; mt < 2; ++mt) {
        int row = wm * 32 + mt * 16 + (lane & 15);
        int colhalf = lane >> 4;
        a_base[mt] = (uint32_t)__cvta_generic_to_shared(&As[row * 40 + colhalf * 8]);
    }
#pragma unroll
    for (int bt = 0; bt < 2; ++bt) {
        int n = wn * 32 + bt * 16 + ((lane >> 4) << 3) + (lane & 7);
        int khalf = (lane >> 3) & 1;
        b_base[bt] = (uint32_t)__cvta_generic_to_shared(&Bs[n * 40 + khalf * 8]);
    }

    for (int ks = 0; ks < 72; ++ks) {
        // source k-offset in the [hi|lo] storage
        int kA = (ks < 48) ? (ks % 24) * 32 : 768 + (ks - 48) * 32;
        int kB = (ks < 24) ? ks * 32 : (ks < 48) ? 768 + (ks - 24) * 32 : (ks - 48) * 32;
#pragma unroll
        for (int r = 0; r < 2; ++r) {
            int q = tid + r * 256;
            int m = q >> 2, cch = q & 3;
            *(uint4*)&As[m * 40 + cch * 8] =
                *(const uint4*)&g_Abf[(size_t)(bm + m) * K2 + kA + cch * 8];
        }
        {
            int n = tid >> 2, cch = tid & 3;
            *(uint4*)&Bs[n * 40 + cch * 8] =
                *(const uint4*)&g_Wbf[(size_t)(bn + n) * K2 + kB + cch * 8];
        }
        __syncthreads();
#pragma unroll
        for (int kh = 0; kh < 2; ++kh) {
            int kk = kh * 16;
            uint32_t a[2][4], b[2][4];
            ldsm4(a[0], a_base[0] + kk * 2);
            ldsm4(a[1], a_base[1] + kk * 2);
            ldsm4(b[0], b_base[0] + kk * 2);
            ldsm4(b[1], b_base[1] + kk * 2);
#pragma unroll
            for (int mt = 0; mt < 2; ++mt)
#pragma unroll
                for (int nt = 0; nt < 4; ++nt)
                    mma_bf16(c[mt][nt], a[mt], b[nt >> 1][(nt & 1) * 2], b[nt >> 1][(nt & 1) * 2 + 1]);
        }
        __syncthreads();
    }

#pragma unroll
    for (int mt = 0; mt < 2; ++mt) {
#pragma unroll
        for (int nt = 0; nt < 4; ++nt) {
            int m0 = bm + wm * 32 + mt * 16 + (lane >> 2);
            int n0 = bn + wn * 32 + nt * 8 + (lane & 3) * 2;
            float2 bv = *(const float2*)&bias[n0];
            float2 o0, o1;
            o0.x = fmaxf(c[mt][nt][0] + bv.x, MIN_POS);
            o0.y = fmaxf(c[mt][nt][1] + bv.y, MIN_POS);
            o1.x = fmaxf(c[mt][nt][2] + bv.x, MIN_POS);
            o1.y = fmaxf(c[mt][nt][3] + bv.y, MIN_POS);
            *(float2*)&g_xe[(size_t)m0 * NE + n0] = o0;
            *(float2*)&g_xe[(size_t)(m0 + 8) * NE + n0] = o1;
        }
    }
}

// ---------------- K3: fused NNMF (unchanged from R9 — committed win) ----------------
__global__ void __launch_bounds__(256, 3) nnmf_kernel() {
    extern __shared__ float sm[];
    float* sW   = sm;                       // [f][d], stride 64
    float* sWt  = sm + 4096;                // [d][f], stride 64
    float* s_ht = sm + 8192;                // [f][tok], stride HSTR
    float* s_rt = sm + 8192 + 64 * HSTR;    // [d][tok], stride HSTR

    int head = blockIdx.y;
    int tile = blockIdx.x;       // 0..31 (64 tokens each)
    int tid = threadIdx.x;
    int d4 = tid & 15;
    int g = tid >> 4;            // 0..15
    int tokbase = tile * 64;

    for (int i = tid; i < 4096; i += 256) sW[i] = g_Wn[i];
    for (int i = tid; i < 4096; i += 256) sWt[i] = g_Wt[i];

    float inp[4][4];
#pragma unroll
    for (int t = 0; t < 4; ++t) {
        int tok = tokbase + g * 4 + t;
        float4 x = *(const float4*)&g_xe[(size_t)tok * NE + head * 64 + d4 * 4];
        float s = red16(x.x + x.y + x.z + x.w);
        float iv = 1.f / fmaxf(s, EPSV);
        inp[t][0] = x.x * iv; inp[t][1] = x.y * iv; inp[t][2] = x.z * iv; inp[t][3] = x.w * iv;
    }

    {
        float4 r0 = *(const float4*)&g_rec0[d4 * 4];
        float rd[4] = {1.f / fmaxf(r0.x, MIN_POS), 1.f / fmaxf(r0.y, MIN_POS),
                       1.f / fmaxf(r0.z, MIN_POS), 1.f / fmaxf(r0.w, MIN_POS)};
#pragma unroll
        for (int i = 0; i < 4; ++i)
            *(float4*)&s_rt[(d4 * 4 + i) * HSTR + g * 4] =
                make_float4(inp[0][i] * rd[i], inp[1][i] * rd[i],
                            inp[2][i] * rd[i], inp[3][i] * rd[i]);
    }
    __syncthreads();

    const float hinit = 1.f / 64.f;
    float hr[4][4];
    float ri[4][4];

    for (int it = 0; it < 3; ++it) {
        if (it > 0) {
            u64 a[4][2] = {};
#pragma unroll 8
            for (int ff = 0; ff < 64; ++ff) {
                ulonglong2 hp = *(const ulonglong2*)&s_ht[ff * HSTR + g * 4];
                float4 w = *(const float4*)&sW[ff * 64 + d4 * 4];
                u64 w0 = dup2(w.x), w1 = dup2(w.y), w2 = dup2(w.z), w3 = dup2(w.w);
                a[0][0] = fma2(w0, hp.x, a[0][0]); a[0][1] = fma2(w0, hp.y, a[0][1]);
                a[1][0] = fma2(w1, hp.x, a[1][0]); a[1][1] = fma2(w1, hp.y, a[1][1]);
                a[2][0] = fma2(w2, hp.x, a[2][0]); a[2][1] = fma2(w2, hp.y, a[2][1]);
                a[3][0] = fma2(w3, hp.x, a[3][0]); a[3][1] = fma2(w3, hp.y, a[3][1]);
            }
            float av[4][4];
#pragma unroll
            for (int i = 0; i < 4; ++i) {
                float2 u0 = unpk2(a[i][0]), u1 = unpk2(a[i][1]);
                av[0][i] = fmaxf(u0.x, MIN_POS); av[1][i] = fmaxf(u0.y, MIN_POS);
                av[2][i] = fmaxf(u1.x, MIN_POS); av[3][i] = fmaxf(u1.y, MIN_POS);
            }
            if (it == 2) {
#pragma unroll
                for (int t = 0; t < 4; ++t)
#pragma unroll
                    for (int i = 0; i < 4; ++i) ri[t][i] = av[t][i] * inp[t][i];
            }
#pragma unroll
            for (int i = 0; i < 4; ++i) {
                float q0 = __fdividef(inp[0][i], av[0][i]);
                float q1 = __fdividef(inp[1][i], av[1][i]);
                float q2 = __fdividef(inp[2][i], av[2][i]);
                float q3 = __fdividef(inp[3][i], av[3][i]);
                *(float4*)&s_rt[(d4 * 4 + i) * HSTR + g * 4] = make_float4(q0, q1, q2, q3);
            }
            __syncthreads();
        }

        u64 b[4][2] = {};
#pragma unroll 8
        for (int d = 0; d < 64; ++d) {
            ulonglong2 rp = *(const ulonglong2*)&s_rt[d * HSTR + g * 4];
            float4 wt = *(const float4*)&sWt[d * 64 + d4 * 4];
            u64 w0 = dup2(wt.x), w1 = dup2(wt.y), w2 = dup2(wt.z), w3 = dup2(wt.w);
            b[0][0] = fma2(w0, rp.x, b[0][0]); b[0][1] = fma2(w0, rp.y, b[0][1]);
            b[1][0] = fma2(w1, rp.x, b[1][0]); b[1][1] = fma2(w1, rp.y, b[1][1]);
            b[2][0] = fma2(w2, rp.x, b[2][0]); b[2][1] = fma2(w2, rp.y, b[2][1]);
            b[3][0] = fma2(w3, rp.x, b[3][0]); b[3][1] = fma2(w3, rp.y, b[3][1]);
        }
        float bv[4][4];
#pragma unroll
        for (int i = 0; i < 4; ++i) {
            float2 u0 = unpk2(b[i][0]), u1 = unpk2(b[i][1]);
            bv[0][i] = u0.x; bv[1][i] = u0.y; bv[2][i] = u1.x; bv[3][i] = u1.y;
        }
#pragma unroll
        for (int t = 0; t < 4; ++t) {
            float hn[4];
#pragma unroll
            for (int i = 0; i < 4; ++i) {
                float pre = (it == 0) ? hinit : hr[t][i];
                hn[i] = fmaxf(pre * bv[t][i], MIN_POS);
            }
            float hs = red16(hn[0] + hn[1] + hn[2] + hn[3]);
            float ih = 1.f / fmaxf(hs, EPSV);
#pragma unroll
            for (int i = 0; i < 4; ++i) hr[t][i] = hn[i] * ih;
        }
        if (it < 2) {
#pragma unroll
            for (int i = 0; i < 4; ++i)
                *(float4*)&s_ht[(d4 * 4 + i) * HSTR + g * 4] =
                    make_float4(hr[0][i], hr[1][i], hr[2][i], hr[3][i]);
            __syncthreads();
        }
    }

    float hf[4][4];
#pragma unroll
    for (int t = 0; t < 4; ++t) {
        float hs = red16(hr[t][0] + hr[t][1] + hr[t][2] + hr[t][3]);
        float ih = 1.f / fmaxf(hs, EPSV);
#pragma unroll
        for (int i = 0; i < 4; ++i) hf[t][i] = hr[t][i] * ih;
    }
    __syncthreads();

    float* s_htm = sm;           // [tok][f], stride 64
    float* s_rtm = sm + 4096;    // [tok][d], stride 64
#pragma unroll
    for (int t = 0; t < 4; ++t) {
        int tl = g * 4 + t;
        float4 hv = make_float4(hf[t][0], hf[t][1], hf[t][2], hf[t][3]);
        float4 rv = make_float4(ri[t][0], ri[t][1], ri[t][2], ri[t][3]);
        *(float4*)&s_htm[tl * 64 + d4 * 4] = hv;
        *(float4*)&s_rtm[tl * 64 + d4 * 4] = rv;
        int token = tokbase + tl;
        int bi = token >> 10, si = token & 1023;
        size_t base = ((size_t)((bi * NH + head) * NS + si)) * 64 + d4 * 4;
        *(float4*)&g_h[base] = hv;
        *(float4*)&g_hri[base] = rv;
    }
    __syncthreads();

    {
        int f4 = tid & 15, dg = tid >> 4;
        u64 acc[4][2] = {};
        float cs[4] = {};
#pragma unroll 8
        for (int o = 0; o < 64; ++o) {
            float4 hv = *(const float4*)&s_htm[o * 64 + f4 * 4];
            ulonglong2 rp = *(const ulonglong2*)&s_rtm[o * 64 + dg * 4];
            u64 h0 = dup2(hv.x), h1 = dup2(hv.y), h2 = dup2(hv.z), h3 = dup2(hv.w);
            acc[0][0] = fma2(h0, rp.x, acc[0][0]); acc[0][1] = fma2(h0, rp.y, acc[0][1]);
            acc[1][0] = fma2(h1, rp.x, acc[1][0]); acc[1][1] = fma2(h1, rp.y, acc[1][1]);
            acc[2][0] = fma2(h2, rp.x, acc[2][0]); acc[2][1] = fma2(h2, rp.y, acc[2][1]);
            acc[3][0] = fma2(h3, rp.x, acc[3][0]); acc[3][1] = fma2(h3, rp.y, acc[3][1]);
            if (dg == 0) { cs[0] += hv.x; cs[1] += hv.y; cs[2] += hv.z; cs[3] += hv.w; }
        }
        int bb = tile >> 4;
        int gsplit = tile & 15;
        int bh = bb * NH + head;
        float* gp = g_G1p + ((size_t)(bh * NSG + gsplit)) * 4096;
#pragma unroll
        for (int i = 0; i < 4; i++) {
            ulonglong2 st; st.x = acc[i][0]; st.y = acc[i][1];
            *(ulonglong2*)&gp[(f4 * 4 + i) * 64 + dg * 4] = st;
        }
        if (dg == 0) {
#pragma unroll
            for (int i = 0; i < 4; i++) g_csp[(bh * NSG + gsplit) * 64 + f4 * 4 + i] = cs[i];
        }
    }
}

// ---------------- K4b: iterations 0+1 in closed form ----------------
__global__ void __launch_bounds__(256) alpha01_kernel() {
    __shared__ float sW[4096];
    __shared__ float sG[4096];
    __shared__ float s_c0[64], s_ai0[64], s_c1[64];
    int bh = blockIdx.x, tid = threadIdx.x;

    for (int i = tid; i < 4096; i += 256) sW[i] = g_Wn[i];
    const float* gp = g_G1p + (size_t)bh * NSG * 4096;
    for (int i = tid; i < 4096; i += 256) {
        float s = 0.f;
#pragma unroll
        for (int p = 0; p < NSG; ++p) s += gp[p * 4096 + i];
        sG[i] = s;
    }
    if (tid < 64) {
        float s = 0.f;
#pragma unroll
        for (int p = 0; p < NSG; ++p) s += g_csp[(bh * NSG + p) * 64 + tid];
        s_c0[tid] = s;
    }
    __syncthreads();
    if (tid < 64) {
        int d = tid;
        float r = 0.f;
#pragma unroll 8
        for (int f = 0; f < 64; ++f) r += s_c0[f] * sW[f * 64 + d];
        float ai = 1.f / (r + EPSV);
        s_ai0[d] = ai;
        g_aiA[bh * 64 + d] = ai;
    }
    __syncthreads();
    if (tid < 64) {
        int f = tid;
        float c1 = 0.f;
#pragma unroll 8
        for (int dd = 0; dd < 64; ++dd) {
            int d = (dd + f) & 63;
            c1 += sG[f * 64 + d] * s_ai0[d];
        }
        s_c1[f] = c1;
    }
    __syncthreads();
    if (tid < 64) {
        int d = tid;
        float r = 0.f;
#pragma unroll 8
        for (int f = 0; f < 64; ++f) r += s_c1[f] * sW[f * 64 + d];
        g_aiB[bh * 64 + d] = 1.f / (r + EPSV);
    }
}

// ---------------- K4c: pass2 — single-load 64-token smem, FFMA2 M-accumulation ----------------
__global__ void __launch_bounds__(256) pass2_kernel() {
    __shared__ __align__(16) float s_h[64][68];
    __shared__ __align__(16) float s_r[64][68];
    __shared__ float s_ai0[64], s_ai1[64];
    __shared__ float s_w[64];
    int split = blockIdx.x, bh = blockIdx.y;
    int tid = threadIdx.x;
    if (tid < 64) s_ai0[tid] = g_aiA[bh * 64 + tid];
    else if (tid < 128) s_ai1[tid - 64] = g_aiB[bh * 64 + tid - 64];

    const float* hb = g_h + ((size_t)bh * NS + split * OSPL) * 64;
    const float* rb = g_hri + ((size_t)bh * NS + split * OSPL) * 64;

    // load all 64 tokens (each array = 1024 float4; 4 per thread)
#pragma unroll
    for (int r = 0; r < 4; ++r) {
        int p = tid + r * 256;
        int o = p >> 4, lq = p & 15;
        *(float4*)&s_h[o][lq * 4] = *(const float4*)&hb[o * 64 + lq * 4];
        *(float4*)&s_r[o][lq * 4] = *(const float4*)&rb[o * 64 + lq * 4];
    }
    __syncthreads();

    // w01: token o = tid>>2, 4 lanes each cover 16 d's; reduce within 4-lane group
    {
        int o = tid >> 2, sub = tid & 3;
        float u0 = 0.f, u1 = 0.f;
#pragma unroll
        for (int dq = 0; dq < 4; ++dq) {
            float4 v = *(const float4*)&s_r[o][sub * 16 + dq * 4];
            int base = sub * 16 + dq * 4;
            u0 += v.x * s_ai0[base] + v.y * s_ai0[base + 1] + v.z * s_ai0[base + 2] + v.w * s_ai0[base + 3];
            u1 += v.x * s_ai1[base] + v.y * s_ai1[base + 1] + v.z * s_ai1[base + 2] + v.w * s_ai1[base + 3];
        }
        u0 += __shfl_xor_sync(0xffffffffu, u0, 1);
        u0 += __shfl_xor_sync(0xffffffffu, u0, 2);
        u1 += __shfl_xor_sync(0xffffffffu, u1, 1);
        u1 += __shfl_xor_sync(0xffffffffu, u1, 2);
        if (sub == 0) s_w[o] = u0 * u1;
    }
    __syncthreads();

    // M[f,d] = sum_o (w01_o * h_of) * hri_od  (FFMA2-packed over d-pairs), c2[f] = sum_o w01_o h_of
    {
        int f4 = tid & 15, dg = tid >> 4;
        u64 acc[4][2] = {};
        float cs[4] = {};
#pragma unroll 8
        for (int o = 0; o < 64; ++o) {
            float wo = s_w[o];
            float4 hv = *(const float4*)&s_h[o][f4 * 4];
            ulonglong2 rp = *(const ulonglong2*)&s_r[o][dg * 4];
            float hw0 = hv.x * wo, hw1 = hv.y * wo, hw2 = hv.z * wo, hw3 = hv.w * wo;
            u64 h0 = dup2(hw0), h1 = dup2(hw1), h2 = dup2(hw2), h3 = dup2(hw3);
            acc[0][0] = fma2(h0, rp.x, acc[0][0]); acc[0][1] = fma2(h0, rp.y, acc[0][1]);
            acc[1][0] = fma2(h1, rp.x, acc[1][0]); acc[1][1] = fma2(h1, rp.y, acc[1][1]);
            acc[2][0] = fma2(h2, rp.x, acc[2][0]); acc[2][1] = fma2(h2, rp.y, acc[2][1]);
            acc[3][0] = fma2(h3, rp.x, acc[3][0]); acc[3][1] = fma2(h3, rp.y, acc[3][1]);
            if (dg == 0) { cs[0] += hw0; cs[1] += hw1; cs[2] += hw2; cs[3] += hw3; }
        }
        float* mp = g_Mp + ((size_t)(bh * NSPLIT + split)) * 4096;
#pragma unroll
        for (int i = 0; i < 4; i++) {
            ulonglong2 st; st.x = acc[i][0]; st.y = acc[i][1];
            *(ulonglong2*)&mp[(f4 * 4 + i) * 64 + dg * 4] = st;
        }
        if (dg == 0) {
#pragma unroll
            for (int i = 0; i < 4; i++) g_c2p[(bh * NSPLIT + split) * 64 + f4 * 4 + i] = cs[i];
        }
    }
}

// ---------------- K4d: ai2 + cfin = (sum M)·ai2 ----------------
__global__ void __launch_bounds__(256) alpha2cfin_kernel() {
    __shared__ float sW[4096];
    __shared__ float s_c2[64];
    __shared__ float s_ai2[64];
    __shared__ float s_p[4][64];
    int bh = blockIdx.x, tid = threadIdx.x;
    for (int i = tid; i < 4096; i += 256) sW[i] = g_Wn[i];
    if (tid < 64) {
        float s = 0.f;
#pragma unroll
        for (int p = 0; p < NSPLIT; ++p) s += g_c2p[(bh * NSPLIT + p) * 64 + tid];
        s_c2[tid] = s;
    }
    __syncthreads();
    if (tid < 64) {
        int d = tid;
        float r = 0.f;
#pragma unroll 8
        for (int f = 0; f < 64; ++f) r += s_c2[f] * sW[f * 64 + d];
        s_ai2[d] = 1.f / (r + EPSV);
    }
    __syncthreads();
    {
        int f = tid & 63, g = tid >> 6;
        const float* mp = g_Mp + (size_t)bh * NSPLIT * 4096;
        float partial = 0.f;
#pragma unroll
        for (int dd = 0; dd < 16; ++dd) {
            int d = g * 16 + dd;
            float mv = 0.f;
#pragma unroll
            for (int p = 0; p < NSPLIT; ++p) mv += mp[p * 4096 + f * 64 + d];
            partial += mv * s_ai2[d];
        }
        s_p[g][f] = partial;
    }
    __syncthreads();
    if (tid < 64) {
        int b = bh / NH, head = bh % NH;
        g_cfin[b * NE + head * 64 + tid] = s_p[0][tid] + s_p[1][tid] + s_p[2][tid] + s_p[3][tid];
    }
}

// ---------------- K5: out projection of the 2 unique rows ----------------
__global__ void __launch_bounds__(256) outrow_kernel(const float* __restrict__ out_w,
                                                     const float* __restrict__ out_b) {
    int b = blockIdx.y;
    int warp = threadIdx.x >> 5, lane = threadIdx.x & 31;
    int j = blockIdx.x * 8 + warp;
    const float* c = g_cfin + b * NE;
    const float* wrow = out_w + (size_t)j * NE;
    float acc = 0.f;
    for (int e = lane; e < NE; e += 32) acc += c[e] * wrow[e];
    acc = red32(acc);
    if (lane == 0) g_yrow[b * FIN + j] = acc + out_b[j];
}

// ---------------- K6: broadcast rows to all positions ----------------
__global__ void __launch_bounds__(256) bcast_kernel(float* __restrict__ out) {
    int idx = blockIdx.x * 256 + threadIdx.x;
    const int per_row = FIN / 4;
    int j4 = idx % per_row;
    int bs = idx / per_row;
    int b = bs >> 10;
    float4 v = ((const float4*)(g_yrow + b * FIN))[j4];
    ((float4*)out)[idx] = v;
}

// ---------------- launch ----------------
extern "C" void kernel_launch(void* const* d_in, const int* in_sizes, int n_in,
                              void* d_out, int out_size) {
    const float* x       = (const float*)d_in[0];
    const float* embed_w = (const float*)d_in[1];
    const float* embed_b = (const float*)d_in[2];
    const float* nnmf_w  = (const float*)d_in[3];
    const float* out_w   = (const float*)d_in[4];
    const float* out_b   = (const float*)d_in[5];
    float* out = (float*)d_out;

    static bool attr_set = false;
    if (!attr_set) {
        cudaFuncSetAttribute(nnmf_kernel, cudaFuncAttributeMaxDynamicSharedMemorySize,
                             NN_SMEM_BYTES);
        attr_set = true;
    }

    conv_kernel<<<2113, 256>>>(x, embed_w, nnmf_w);
    embed_mma_kernel<<<dim3(NE / 64, (NB * NS) / 128), 256>>>(embed_b);
    nnmf_kernel<<<dim3((NB * NS) / 64, NH), 256, NN_SMEM_BYTES>>>();
    alpha01_kernel<<<NBH, 256>>>();
    pass2_kernel<<<dim3(NSPLIT, NBH), 256>>>();
    alpha2cfin_kernel<<<NBH, 256>>>();
    outrow_kernel<<<dim3(NE / 8, NB), 256>>>(out_w, out_b);
    bcast_kernel<<<(NB * NS * (FIN / 4)) / 256, 256>>>(out);
}